// round 4
// baseline (speedup 1.0000x reference)
#include <cuda_runtime.h>
#include <cstdint>
#include <math.h>

#define BB    16
#define NQ    256
#define NKV   2304
#define HDIM  768
#define IMGD  1024
#define HEADS 12
#define INTER 3072
#define ATTN_SCALE 0.125f

// ---------------- scratch (static __device__, allocation-free) ----------------
__device__ float g_xn [BB*NKV*IMGD];
__device__ float g_hn [BB*NQ*HDIM];
__device__ float g_q  [BB*NQ*HDIM];
__device__ float g_k  [BB*NKV*HDIM];
__device__ float g_v  [BB*NKV*HDIM];
__device__ float g_ctx[BB*NQ*HDIM];
__device__ float g_o1 [BB*NQ*HDIM];
__device__ float g_hnf[BB*NQ*HDIM];
__device__ float g_ff [BB*NQ*INTER];
// tf32-rounded weights (same [K,N] layout as input)
__device__ float g_wq[HDIM*HDIM];
__device__ float g_wk[IMGD*HDIM];
__device__ float g_wv[IMGD*HDIM];
__device__ float g_wo[HDIM*HDIM];
__device__ float g_w1[HDIM*INTER];
__device__ float g_w2[INTER*HDIM];

// ---------------- helpers ----------------
__device__ __forceinline__ uint32_t smem_u32(const void* p) {
    uint32_t a;
    asm("{ .reg .u64 t; cvta.to.shared.u64 t, %1; cvt.u32.u64 %0, t; }" : "=r"(a) : "l"(p));
    return a;
}
__device__ __forceinline__ float tf32r(float x) {
    uint32_t u; asm("cvt.rna.tf32.f32 %0, %1;" : "=r"(u) : "f"(x));
    return __uint_as_float(u);
}
__device__ __forceinline__ void cpa16(uint32_t dst, const void* src) {
    asm volatile("cp.async.cg.shared.global [%0], [%1], 16;\n" :: "r"(dst), "l"(src));
}
__device__ __forceinline__ void mma_tf32(float* c, const uint32_t* a, const uint32_t* b) {
    asm volatile(
        "mma.sync.aligned.m16n8k8.row.col.f32.tf32.tf32.f32 "
        "{%0,%1,%2,%3}, {%4,%5,%6,%7}, {%8,%9}, {%0,%1,%2,%3};\n"
        : "+f"(c[0]), "+f"(c[1]), "+f"(c[2]), "+f"(c[3])
        : "r"(a[0]), "r"(a[1]), "r"(a[2]), "r"(a[3]), "r"(b[0]), "r"(b[1]));
}
// fast exp via exp2 poly — no MUFU (MUFU is the attention bottleneck otherwise)
__device__ __forceinline__ float fexp(float x) {
    float y = fmaxf(x * 1.44269504f, -120.f);
    float r = y + 12582912.f;          // round-to-nearest int (2^23*1.5 trick)
    float n = r - 12582912.f;
    float f = y - n;
    float p = 0.00133336f;
    p = fmaf(p, f, 0.00961804f);
    p = fmaf(p, f, 0.05550411f);
    p = fmaf(p, f, 0.24022651f);
    p = fmaf(p, f, 0.69314718f);
    p = fmaf(p, f, 1.0f);
    int ni = __float_as_int(r) - 0x4B400000;
    return p * __int_as_float((ni + 127) << 23);
}

// ---------------- weight rounding (rna -> tf32) ----------------
__global__ void __launch_bounds__(256) wround(const float* __restrict__ W,
                                              float* __restrict__ O, int n) {
    int i = blockIdx.x * 1024 + threadIdx.x * 4;
    if (i < n) {
        float4 v = *(const float4*)(W + i);
        v.x = tf32r(v.x); v.y = tf32r(v.y); v.z = tf32r(v.z); v.w = tf32r(v.w);
        *(float4*)(O + i) = v;
    }
}

// ---------------- LayerNorm (tf32-rounded output; feeds GEMM A operands) ------
__device__ __forceinline__ float blk_sum(float v) {
    __shared__ float red[8];
    int lane = threadIdx.x & 31, wid = threadIdx.x >> 5;
#pragma unroll
    for (int m = 16; m; m >>= 1) v += __shfl_xor_sync(0xffffffffu, v, m);
    __syncthreads();
    if (lane == 0) red[wid] = v;
    __syncthreads();
    float s = 0.f;
#pragma unroll
    for (int i = 0; i < 8; i++) s += red[i];
    return s;
}

__global__ void __launch_bounds__(256) ln_kernel(
    const float* __restrict__ in, const float* __restrict__ gam,
    const float* __restrict__ bet, float* __restrict__ out, int D)
{
    long row = blockIdx.x;
    const float* xr = in + row * (long)D;
    float xv[4];
    int n = 0; float s = 0.f;
    for (int i = threadIdx.x; i < D; i += 256) { float t = xr[i]; xv[n++] = t; s += t; }
    s = blk_sum(s);
    float mu = s / (float)D;
    float vr = 0.f;
    for (int c = 0; c < n; c++) { float d = xv[c] - mu; vr += d * d; }
    vr = blk_sum(vr);
    float rstd = rsqrtf(vr / (float)D + 1e-5f);
    float* orow = out + row * (long)D;
    n = 0;
    for (int i = threadIdx.x; i < D; i += 256)
        orow[i] = tf32r((xv[n++] - mu) * rstd * gam[i] + bet[i]);
}

// ---------------- tf32 mma.sync GEMM ----------------
// C[M,N] = A[M,K] @ W[K,N] + bias ; epi: 0=bias, 1=bias+res, 2=bias+gelu->tf32,
// 3=bias->tf32, 4=(bias)*ATTN_SCALE->tf32
#define GAS_F (128*36)
#define GBS_F (32*132)
#define GST_F (GAS_F + GBS_F)
#define GSMEM (3 * GST_F * 4)

__global__ void __launch_bounds__(256, 2) gemm_mma(
    const float* __restrict__ A, const float* __restrict__ Bw,
    const float* __restrict__ bias, const float* __restrict__ res,
    float* __restrict__ C, int M, int N, int K, int epi)
{
    extern __shared__ float smf[];
    int tid = threadIdx.x, lane = tid & 31, wid = tid >> 5;
    int gid = lane >> 2, tig = lane & 3;
    int wm = wid & 1, wn = wid >> 1;
    int m0 = blockIdx.y * 128, n0 = blockIdx.x * 128;

    float acc[4][4][4];
#pragma unroll
    for (int i = 0; i < 4; i++)
#pragma unroll
        for (int j = 0; j < 4; j++)
#pragma unroll
            for (int r = 0; r < 4; r++) acc[i][j][r] = 0.f;

    const int NC = K / 32;

    auto issue = [&](int c, int s) {
        float* as = smf + s * GST_F;
        float* bs = as + GAS_F;
        long kb = (long)c * 32;
#pragma unroll
        for (int i = 0; i < 4; i++) {
            int idx = tid + i * 256;
            int r = idx >> 3, kc = (idx & 7) * 4;
            cpa16(smem_u32(as + r * 36 + kc), A + (long)(m0 + r) * K + kb + kc);
        }
#pragma unroll
        for (int i = 0; i < 4; i++) {
            int idx = tid + i * 256;
            int r = idx >> 5, nc = (idx & 31) * 4;
            cpa16(smem_u32(bs + r * 132 + nc), Bw + (kb + r) * (long)N + n0 + nc);
        }
        asm volatile("cp.async.commit_group;\n" ::: "memory");
    };

    issue(0, 0);
    if (NC > 1) issue(1, 1);

    for (int c = 0; c < NC; c++) {
        int s = c % 3;
        if (c + 1 < NC) asm volatile("cp.async.wait_group 1;\n" ::: "memory");
        else            asm volatile("cp.async.wait_group 0;\n" ::: "memory");
        __syncthreads();

        const float* as = smf + s * GST_F;
        const float* bs = as + GAS_F;
#pragma unroll
        for (int kk = 0; kk < 4; kk++) {
            int k0 = kk * 8;
            uint32_t a[4][4], b[4][2];
#pragma unroll
            for (int mf = 0; mf < 4; mf++) {
                const float* ap = as + (wm * 64 + mf * 16 + gid) * 36 + k0 + tig;
                a[mf][0] = __float_as_uint(ap[0]);
                a[mf][1] = __float_as_uint(ap[8 * 36]);
                a[mf][2] = __float_as_uint(ap[4]);
                a[mf][3] = __float_as_uint(ap[8 * 36 + 4]);
            }
#pragma unroll
            for (int nf = 0; nf < 4; nf++) {
                const float* bp = bs + (k0 + tig) * 132 + wn * 32 + nf * 8 + gid;
                b[nf][0] = __float_as_uint(bp[0]);
                b[nf][1] = __float_as_uint(bp[4 * 132]);
            }
#pragma unroll
            for (int mf = 0; mf < 4; mf++)
#pragma unroll
                for (int nf = 0; nf < 4; nf++)
                    mma_tf32(acc[mf][nf], a[mf], b[nf]);
        }
        __syncthreads();
        if (c + 2 < NC) issue(c + 2, (c + 2) % 3);
    }

    int cbase = n0 + wn * 32 + 2 * tig;
    float2 bl[4];
#pragma unroll
    for (int nf = 0; nf < 4; nf++)
        bl[nf] = *(const float2*)(bias + cbase + nf * 8);

#pragma unroll
    for (int mf = 0; mf < 4; mf++) {
#pragma unroll
        for (int half = 0; half < 2; half++) {
            long r = m0 + wm * 64 + mf * 16 + gid + half * 8;
#pragma unroll
            for (int nf = 0; nf < 4; nf++) {
                int col = cbase + nf * 8;
                float v0 = acc[mf][nf][half * 2 + 0] + bl[nf].x;
                float v1 = acc[mf][nf][half * 2 + 1] + bl[nf].y;
                if (epi == 1) {
                    float2 rv = *(const float2*)(res + r * (long)N + col);
                    v0 += rv.x; v1 += rv.y;
                } else if (epi == 2) {
                    v0 = tf32r(0.5f * v0 * (1.f + erff(v0 * 0.70710678118654752f)));
                    v1 = tf32r(0.5f * v1 * (1.f + erff(v1 * 0.70710678118654752f)));
                } else if (epi == 3) {
                    v0 = tf32r(v0); v1 = tf32r(v1);
                } else if (epi == 4) {
                    v0 = tf32r(v0 * ATTN_SCALE); v1 = tf32r(v1 * ATTN_SCALE);
                }
                *(float2*)(C + r * (long)N + col) = make_float2(v0, v1);
            }
        }
    }
}

// ---------------- tensor-core flash attention (tf32 mma + FMA exp) ------------
// CTA: 128 q-rows of one (b,h). 8 warps x 16 rows (warp-private softmax).
// KV tiles of 64, double-buffered cp.async. Q/K stride 68, V stride 72.
#define AQS   (128*68)
#define AKS   (64*68)
#define AVS   (64*72)
#define ASMEM ((AQS + 2*AKS + 2*AVS) * 4)      // 106496 B
#define ANC   (NKV / 64)

__global__ void __launch_bounds__(256, 2) attn_mma(
    const float* __restrict__ Q, const float* __restrict__ K,
    const float* __restrict__ V, float* __restrict__ O)
{
    extern __shared__ float smf[];
    float* qs = smf;                    // [128][68]
    float* ks = smf + AQS;              // [2][64][68]
    float* vs = ks + 2 * AKS;           // [2][64][72]
    int tid = threadIdx.x, lane = tid & 31, wid = tid >> 5;
    int gid = lane >> 2, tig = lane & 3;
    int qb = blockIdx.x, h = blockIdx.y, b = blockIdx.z;

    const float* Qb = Q + ((long)b * NQ + qb * 128) * HDIM + h * 64;
    const float* Kb = K + (long)b * NKV * HDIM + h * 64;
    const float* Vb = V + (long)b * NKV * HDIM + h * 64;

    auto load_kv = [&](int c, int buf) {
        float* kd = ks + buf * AKS;
        float* vd = vs + buf * AVS;
        long j0 = (long)c * 64;
#pragma unroll
        for (int i = 0; i < 4; i++) {
            int idx = tid + i * 256;
            int r = idx >> 4, ch = (idx & 15) * 4;
            cpa16(smem_u32(kd + r * 68 + ch), Kb + (j0 + r) * HDIM + ch);
            cpa16(smem_u32(vd + r * 72 + ch), Vb + (j0 + r) * HDIM + ch);
        }
        asm volatile("cp.async.commit_group;\n" ::: "memory");
    };

    // Q tile + KV tile 0 as group 0
#pragma unroll
    for (int i = 0; i < 8; i++) {
        int idx = tid + i * 256;
        int r = idx >> 4, ch = (idx & 15) * 4;
        cpa16(smem_u32(qs + r * 68 + ch), Qb + (long)r * HDIM + ch);
    }
    load_kv(0, 0);

    float o[8][4];
#pragma unroll
    for (int nf = 0; nf < 8; nf++)
#pragma unroll
        for (int e = 0; e < 4; e++) o[nf][e] = 0.f;
    float m0 = -1e30f, m1 = -1e30f, l0 = 0.f, l1 = 0.f;

    const float* aq = qs + (wid * 16 + gid) * 68 + tig;
    int src0 = (lane & ~3) | (tig >> 1);
    int src1 = src0 + 2;
    int sel  = tig & 1;

    for (int c = 0; c < ANC; c++) {
        if (c + 1 < ANC) {
            load_kv(c + 1, (c + 1) & 1);
            asm volatile("cp.async.wait_group 1;\n" ::: "memory");
        } else {
            asm volatile("cp.async.wait_group 0;\n" ::: "memory");
        }
        __syncthreads();

        const float* kcur = ks + (c & 1) * AKS;
        const float* vcur = vs + (c & 1) * AVS;

        // ---- S = Q @ K^T (scale pre-folded into Q) ----
        float sc[8][4];
#pragma unroll
        for (int nf = 0; nf < 8; nf++)
#pragma unroll
            for (int e = 0; e < 4; e++) sc[nf][e] = 0.f;
#pragma unroll
        for (int kf = 0; kf < 8; kf++) {
            uint32_t a[4];
            a[0] = __float_as_uint(aq[kf * 8]);
            a[1] = __float_as_uint(aq[kf * 8 + 8 * 68]);
            a[2] = __float_as_uint(aq[kf * 8 + 4]);
            a[3] = __float_as_uint(aq[kf * 8 + 8 * 68 + 4]);
#pragma unroll
            for (int nf = 0; nf < 8; nf++) {
                const float* bp = kcur + (nf * 8 + gid) * 68 + kf * 8 + tig;
                uint32_t bfr[2];
                bfr[0] = __float_as_uint(bp[0]);
                bfr[1] = __float_as_uint(bp[4]);
                mma_tf32(sc[nf], a, bfr);
            }
        }

        // ---- online softmax (warp-private; quad reduce over tig) ----
        float tm0 = -1e30f, tm1 = -1e30f;
#pragma unroll
        for (int nf = 0; nf < 8; nf++) {
            tm0 = fmaxf(tm0, fmaxf(sc[nf][0], sc[nf][1]));
            tm1 = fmaxf(tm1, fmaxf(sc[nf][2], sc[nf][3]));
        }
        tm0 = fmaxf(tm0, __shfl_xor_sync(0xffffffffu, tm0, 1));
        tm0 = fmaxf(tm0, __shfl_xor_sync(0xffffffffu, tm0, 2));
        tm1 = fmaxf(tm1, __shfl_xor_sync(0xffffffffu, tm1, 1));
        tm1 = fmaxf(tm1, __shfl_xor_sync(0xffffffffu, tm1, 2));
        float nm0 = fmaxf(m0, tm0), nm1 = fmaxf(m1, tm1);
        float corr0 = fexp(m0 - nm0), corr1 = fexp(m1 - nm1);
        m0 = nm0; m1 = nm1;
        float ps0 = 0.f, ps1 = 0.f;
#pragma unroll
        for (int nf = 0; nf < 8; nf++) {
            float p0 = tf32r(fexp(sc[nf][0] - nm0));
            float p1 = tf32r(fexp(sc[nf][1] - nm0));
            float p2 = tf32r(fexp(sc[nf][2] - nm1));
            float p3 = tf32r(fexp(sc[nf][3] - nm1));
            sc[nf][0] = p0; sc[nf][1] = p1; sc[nf][2] = p2; sc[nf][3] = p3;
            ps0 += p0 + p1; ps1 += p2 + p3;
        }
        ps0 += __shfl_xor_sync(0xffffffffu, ps0, 1);
        ps0 += __shfl_xor_sync(0xffffffffu, ps0, 2);
        ps1 += __shfl_xor_sync(0xffffffffu, ps1, 1);
        ps1 += __shfl_xor_sync(0xffffffffu, ps1, 2);
        l0 = l0 * corr0 + ps0;
        l1 = l1 * corr1 + ps1;
#pragma unroll
        for (int nf = 0; nf < 8; nf++) {
            o[nf][0] *= corr0; o[nf][1] *= corr0;
            o[nf][2] *= corr1; o[nf][3] *= corr1;
        }

        // ---- O += P @ V  (P C-frag -> A-frag via shfl) ----
#pragma unroll
        for (int kf = 0; kf < 8; kf++) {
            float x0 = sc[kf][0], x1 = sc[kf][1], x2 = sc[kf][2], x3 = sc[kf][3];
            float v00 = __shfl_sync(0xffffffffu, x0, src0);
            float v01 = __shfl_sync(0xffffffffu, x1, src0);
            float v20 = __shfl_sync(0xffffffffu, x2, src0);
            float v21 = __shfl_sync(0xffffffffu, x3, src0);
            float w00 = __shfl_sync(0xffffffffu, x0, src1);
            float w01 = __shfl_sync(0xffffffffu, x1, src1);
            float w20 = __shfl_sync(0xffffffffu, x2, src1);
            float w21 = __shfl_sync(0xffffffffu, x3, src1);
            uint32_t a[4];
            a[0] = __float_as_uint(sel ? v01 : v00);
            a[1] = __float_as_uint(sel ? v21 : v20);
            a[2] = __float_as_uint(sel ? w01 : w00);
            a[3] = __float_as_uint(sel ? w21 : w20);
#pragma unroll
            for (int nf = 0; nf < 8; nf++) {
                const float* bp = vcur + (kf * 8 + tig) * 72 + nf * 8 + gid;
                uint32_t bfr[2];
                bfr[0] = __float_as_uint(bp[0]);
                bfr[1] = __float_as_uint(bp[4 * 72]);
                mma_tf32(o[nf], a, bfr);
            }
        }
        __syncthreads();
    }

    // ---- write out (tf32-rounded; feeds Wo GEMM) ----
    float inv0 = 1.f / l0, inv1 = 1.f / l1;
    long r0 = (long)b * NQ + qb * 128 + wid * 16 + gid;
    long r1 = r0 + 8;
#pragma unroll
    for (int nf = 0; nf < 8; nf++) {
        int col = h * 64 + nf * 8 + 2 * tig;
        *(float2*)(O + r0 * HDIM + col) =
            make_float2(tf32r(o[nf][0] * inv0), tf32r(o[nf][1] * inv0));
        *(float2*)(O + r1 * HDIM + col) =
            make_float2(tf32r(o[nf][2] * inv1), tf32r(o[nf][3] * inv1));
    }
}

// ---------------- launcher ----------------
extern "C" void kernel_launch(void* const* d_in, const int* in_sizes, int n_in,
                              void* d_out, int out_size)
{
    const float* hid = (const float*)d_in[0];
    const float* x   = (const float*)d_in[1];
    const float* Wq  = (const float*)d_in[2];
    const float* bq  = (const float*)d_in[3];
    const float* Wk  = (const float*)d_in[4];
    const float* bk  = (const float*)d_in[5];
    const float* Wv  = (const float*)d_in[6];
    const float* bv  = (const float*)d_in[7];
    const float* Wo  = (const float*)d_in[8];
    const float* bo  = (const float*)d_in[9];
    const float* W1  = (const float*)d_in[10];
    const float* b1  = (const float*)d_in[11];
    const float* W2  = (const float*)d_in[12];
    const float* b2  = (const float*)d_in[13];
    const float* gi  = (const float*)d_in[14];
    const float* bi  = (const float*)d_in[15];
    const float* gh  = (const float*)d_in[16];
    const float* bh  = (const float*)d_in[17];
    const float* gf  = (const float*)d_in[18];
    const float* bf  = (const float*)d_in[19];

    float *xn, *hn, *q, *k, *v, *ctx, *o1, *hnf, *ff;
    float *wq, *wk, *wv, *wo, *w1, *w2;
    cudaGetSymbolAddress((void**)&xn,  g_xn);
    cudaGetSymbolAddress((void**)&hn,  g_hn);
    cudaGetSymbolAddress((void**)&q,   g_q);
    cudaGetSymbolAddress((void**)&k,   g_k);
    cudaGetSymbolAddress((void**)&v,   g_v);
    cudaGetSymbolAddress((void**)&ctx, g_ctx);
    cudaGetSymbolAddress((void**)&o1,  g_o1);
    cudaGetSymbolAddress((void**)&hnf, g_hnf);
    cudaGetSymbolAddress((void**)&ff,  g_ff);
    cudaGetSymbolAddress((void**)&wq,  g_wq);
    cudaGetSymbolAddress((void**)&wk,  g_wk);
    cudaGetSymbolAddress((void**)&wv,  g_wv);
    cudaGetSymbolAddress((void**)&wo,  g_wo);
    cudaGetSymbolAddress((void**)&w1,  g_w1);
    cudaGetSymbolAddress((void**)&w2,  g_w2);

    cudaFuncSetAttribute(attn_mma, cudaFuncAttributeMaxDynamicSharedMemorySize, ASMEM);
    cudaFuncSetAttribute(gemm_mma, cudaFuncAttributeMaxDynamicSharedMemorySize, GSMEM);

    // 0) weight rounding (rna -> tf32)
    wround<<<(HDIM * HDIM  + 1023) / 1024, 256>>>(Wq, wq, HDIM * HDIM);
    wround<<<(IMGD * HDIM  + 1023) / 1024, 256>>>(Wk, wk, IMGD * HDIM);
    wround<<<(IMGD * HDIM  + 1023) / 1024, 256>>>(Wv, wv, IMGD * HDIM);
    wround<<<(HDIM * HDIM  + 1023) / 1024, 256>>>(Wo, wo, HDIM * HDIM);
    wround<<<(HDIM * INTER + 1023) / 1024, 256>>>(W1, w1, HDIM * INTER);
    wround<<<(INTER * HDIM + 1023) / 1024, 256>>>(W2, w2, INTER * HDIM);

    // 1) LayerNorms of inputs (tf32-rounded outputs)
    ln_kernel<<<BB * NKV, 256>>>(x,   gi, bi, xn, IMGD);
    ln_kernel<<<BB * NQ,  256>>>(hid, gh, bh, hn, HDIM);

    // 2) Q/K/V projections (q: scale folded + rounded; k/v: rounded)
    gemm_mma<<<dim3(HDIM / 128, BB * NQ  / 128), 256, GSMEM>>>(hn, wq, bq, nullptr, q, BB * NQ,  HDIM, HDIM, 4);
    gemm_mma<<<dim3(HDIM / 128, BB * NKV / 128), 256, GSMEM>>>(xn, wk, bk, nullptr, k, BB * NKV, HDIM, IMGD, 3);
    gemm_mma<<<dim3(HDIM / 128, BB * NKV / 128), 256, GSMEM>>>(xn, wv, bv, nullptr, v, BB * NKV, HDIM, IMGD, 3);

    // 3) attention (tensor cores)
    attn_mma<<<dim3(NQ / 128, HEADS, BB), 256, ASMEM>>>(q, k, v, ctx);

    // 4) output proj + residual
    gemm_mma<<<dim3(HDIM / 128, BB * NQ / 128), 256, GSMEM>>>(ctx, wo, bo, hid, o1, BB * NQ, HDIM, HDIM, 1);

    // 5) FFN
    ln_kernel<<<BB * NQ, 256>>>(o1, gf, bf, hnf, HDIM);
    gemm_mma<<<dim3(INTER / 128, BB * NQ / 128), 256, GSMEM>>>(hnf, w1, b1, nullptr, ff, BB * NQ, INTER, HDIM, 2);
    gemm_mma<<<dim3(HDIM / 128,  BB * NQ / 128), 256, GSMEM>>>(ff, w2, b2, o1, (float*)d_out, BB * NQ, HDIM, INTER, 1);
}

// round 5
// speedup vs baseline: 2.3376x; 2.3376x over previous
#include <cuda_runtime.h>
#include <cuda_fp16.h>
#include <cstdint>
#include <math.h>

#define BB    16
#define NQ    256
#define NKV   2304
#define HDIM  768
#define IMGD  1024
#define HEADS 12
#define INTER 3072
#define ATTN_SCALE 0.125f

// ---------------- scratch (static __device__, allocation-free) ----------------
__device__ __half g_xn [BB*NKV*IMGD];
__device__ __half g_hn [BB*NQ*HDIM];
__device__ __half g_q  [BB*NQ*HDIM];
__device__ __half g_k  [BB*NKV*HDIM];
__device__ __half g_v  [BB*NKV*HDIM];
__device__ __half g_ctx[BB*NQ*HDIM];
__device__ float  g_o1 [BB*NQ*HDIM];
__device__ __half g_hnf[BB*NQ*HDIM];
__device__ __half g_ff [BB*NQ*INTER];
// transposed fp16 weights [N,K]
__device__ __half g_wq[HDIM*HDIM];
__device__ __half g_wk[HDIM*IMGD];
__device__ __half g_wv[HDIM*IMGD];
__device__ __half g_wo[HDIM*HDIM];
__device__ __half g_w1[INTER*HDIM];
__device__ __half g_w2[HDIM*INTER];

// ---------------- helpers ----------------
__device__ __forceinline__ uint32_t smem_u32(const void* p) {
    uint32_t a;
    asm("{ .reg .u64 t; cvta.to.shared.u64 t, %1; cvt.u32.u64 %0, t; }" : "=r"(a) : "l"(p));
    return a;
}
__device__ __forceinline__ void cpa16(uint32_t dst, const void* src) {
    asm volatile("cp.async.cg.shared.global [%0], [%1], 16;\n" :: "r"(dst), "l"(src));
}
__device__ __forceinline__ void mma_f16(float* c, const uint32_t* a, const uint32_t* b) {
    asm volatile(
        "mma.sync.aligned.m16n8k16.row.col.f32.f16.f16.f32 "
        "{%0,%1,%2,%3}, {%4,%5,%6,%7}, {%8,%9}, {%0,%1,%2,%3};\n"
        : "+f"(c[0]), "+f"(c[1]), "+f"(c[2]), "+f"(c[3])
        : "r"(a[0]), "r"(a[1]), "r"(a[2]), "r"(a[3]), "r"(b[0]), "r"(b[1]));
}
// fast exp2-based exp, no MUFU
__device__ __forceinline__ float fexp(float x) {
    float y = fmaxf(x * 1.44269504f, -120.f);
    float r = y + 12582912.f;
    float n = r - 12582912.f;
    float f = y - n;
    float p = 0.00133336f;
    p = fmaf(p, f, 0.00961804f);
    p = fmaf(p, f, 0.05550411f);
    p = fmaf(p, f, 0.24022651f);
    p = fmaf(p, f, 0.69314718f);
    p = fmaf(p, f, 1.0f);
    int ni = __float_as_int(r) - 0x4B400000;
    return p * __int_as_float((ni + 127) << 23);
}
__device__ __forceinline__ uint32_t h2u(float lo, float hi) {
    __half2 h = __floats2half2_rn(lo, hi);
    return *(uint32_t*)&h;
}

// ---------------- weight prep: transpose [K,N] -> [N,K] fp16 ----------------
__global__ void __launch_bounds__(256) wprep(const float* __restrict__ W,
                                             __half* __restrict__ WT, int K, int N) {
    __shared__ float t[32][33];
    int nb = blockIdx.x * 32, kb = blockIdx.y * 32;
    int tx = threadIdx.x & 31, ty = threadIdx.x >> 5;
#pragma unroll
    for (int i = 0; i < 32; i += 8)
        t[ty + i][tx] = W[(long)(kb + ty + i) * N + nb + tx];
    __syncthreads();
#pragma unroll
    for (int i = 0; i < 32; i += 8)
        WT[(long)(nb + ty + i) * K + kb + tx] = __float2half(t[tx][ty + i]);
}

// ---------------- LayerNorm: fp32 in -> fp16 out ----------------
__device__ __forceinline__ float blk_sum(float v) {
    __shared__ float red[8];
    int lane = threadIdx.x & 31, wid = threadIdx.x >> 5;
#pragma unroll
    for (int m = 16; m; m >>= 1) v += __shfl_xor_sync(0xffffffffu, v, m);
    __syncthreads();
    if (lane == 0) red[wid] = v;
    __syncthreads();
    float s = 0.f;
#pragma unroll
    for (int i = 0; i < 8; i++) s += red[i];
    return s;
}

__global__ void __launch_bounds__(256) ln_kernel(
    const float* __restrict__ in, const float* __restrict__ gam,
    const float* __restrict__ bet, __half* __restrict__ out, int D)
{
    long row = blockIdx.x;
    const float* xr = in + row * (long)D;
    float xv[4];
    int n = 0; float s = 0.f;
    for (int i = threadIdx.x; i < D; i += 256) { float t = xr[i]; xv[n++] = t; s += t; }
    s = blk_sum(s);
    float mu = s / (float)D;
    float vr = 0.f;
    for (int c = 0; c < n; c++) { float d = xv[c] - mu; vr += d * d; }
    vr = blk_sum(vr);
    float rstd = rsqrtf(vr / (float)D + 1e-5f);
    __half* orow = out + row * (long)D;
    n = 0;
    for (int i = threadIdx.x; i < D; i += 256)
        orow[i] = __float2half((xv[n++] - mu) * rstd * gam[i] + bet[i]);
}

// ---------------- fp16 mma.sync GEMM ----------------
// C[M,N] = Ah[M,K] @ WTh[N,K]^T + bias
// epi: 1 = +res -> fp32 out ; 2 = gelu -> fp16 ; 3 = -> fp16 ; 4 = *SCALE -> fp16
// CTA 128x128, BK=32, 256 threads, warps 2(m)x4(n), 3-stage cp.async.
#define HGA   (128*40)            // halves per A stage
#define HGST  (2*HGA)             // A+B halves per stage
#define HGSM  (3*HGST*2)          // bytes = 61440

__global__ void __launch_bounds__(256, 2) gemm_h(
    const __half* __restrict__ A, const __half* __restrict__ Bw,
    const float* __restrict__ bias, const float* __restrict__ res,
    void* __restrict__ Cout, int M, int N, int K, int epi)
{
    extern __shared__ __half smh[];
    int tid = threadIdx.x, lane = tid & 31, wid = tid >> 5;
    int gid = lane >> 2, tig = lane & 3;
    int wm = wid & 1, wn = wid >> 1;
    int m0 = blockIdx.y * 128, n0 = blockIdx.x * 128;

    float acc[4][4][4];
#pragma unroll
    for (int i = 0; i < 4; i++)
#pragma unroll
        for (int j = 0; j < 4; j++)
#pragma unroll
            for (int r = 0; r < 4; r++) acc[i][j][r] = 0.f;

    const int NC = K / 32;

    auto issue = [&](int c, int s) {
        __half* as = smh + s * HGST;
        __half* bs = as + HGA;
        long kb = (long)c * 32;
#pragma unroll
        for (int i = 0; i < 2; i++) {
            int idx = tid + i * 256;
            int r = idx >> 2, c8 = (idx & 3) * 8;
            cpa16(smem_u32(as + r * 40 + c8), A  + (long)(m0 + r) * K + kb + c8);
        }
#pragma unroll
        for (int i = 0; i < 2; i++) {
            int idx = tid + i * 256;
            int r = idx >> 2, c8 = (idx & 3) * 8;
            cpa16(smem_u32(bs + r * 40 + c8), Bw + (long)(n0 + r) * K + kb + c8);
        }
        asm volatile("cp.async.commit_group;\n" ::: "memory");
    };

    issue(0, 0);
    if (NC > 1) issue(1, 1);

    for (int c = 0; c < NC; c++) {
        int s = c % 3;
        if (c + 1 < NC) asm volatile("cp.async.wait_group 1;\n" ::: "memory");
        else            asm volatile("cp.async.wait_group 0;\n" ::: "memory");
        __syncthreads();

        const __half* as = smh + s * HGST;
        const __half* bs = as + HGA;
#pragma unroll
        for (int ks = 0; ks < 2; ks++) {
            int k0 = ks * 16;
            uint32_t a[4][4], b[4][2];
#pragma unroll
            for (int mf = 0; mf < 4; mf++) {
                const __half* ap = as + (wm * 64 + mf * 16 + gid) * 40 + k0 + 2 * tig;
                a[mf][0] = *(const uint32_t*)(ap);
                a[mf][1] = *(const uint32_t*)(ap + 8 * 40);
                a[mf][2] = *(const uint32_t*)(ap + 8);
                a[mf][3] = *(const uint32_t*)(ap + 8 * 40 + 8);
            }
#pragma unroll
            for (int nf = 0; nf < 4; nf++) {
                const __half* bp = bs + (wn * 32 + nf * 8 + gid) * 40 + k0 + 2 * tig;
                b[nf][0] = *(const uint32_t*)(bp);
                b[nf][1] = *(const uint32_t*)(bp + 8);
            }
#pragma unroll
            for (int mf = 0; mf < 4; mf++)
#pragma unroll
                for (int nf = 0; nf < 4; nf++)
                    mma_f16(acc[mf][nf], a[mf], b[nf]);
        }
        __syncthreads();
        if (c + 2 < NC) issue(c + 2, (c + 2) % 3);
    }

    // ---- epilogue ----
    int cbase = n0 + wn * 32 + 2 * tig;
    float2 bl[4];
#pragma unroll
    for (int nf = 0; nf < 4; nf++)
        bl[nf] = *(const float2*)(bias + cbase + nf * 8);

#pragma unroll
    for (int mf = 0; mf < 4; mf++) {
#pragma unroll
        for (int half2i = 0; half2i < 2; half2i++) {
            long r = m0 + wm * 64 + mf * 16 + gid + half2i * 8;
#pragma unroll
            for (int nf = 0; nf < 4; nf++) {
                int col = cbase + nf * 8;
                float v0 = acc[mf][nf][half2i * 2 + 0] + bl[nf].x;
                float v1 = acc[mf][nf][half2i * 2 + 1] + bl[nf].y;
                if (epi == 1) {
                    float2 rv = *(const float2*)(res + r * (long)N + col);
                    *(float2*)((float*)Cout + r * (long)N + col) =
                        make_float2(v0 + rv.x, v1 + rv.y);
                } else {
                    if (epi == 2) {
                        v0 = 0.5f * v0 * (1.f + erff(v0 * 0.70710678118654752f));
                        v1 = 0.5f * v1 * (1.f + erff(v1 * 0.70710678118654752f));
                    } else if (epi == 4) {
                        v0 *= ATTN_SCALE; v1 *= ATTN_SCALE;
                    }
                    *(uint32_t*)((__half*)Cout + r * (long)N + col) = h2u(v0, v1);
                }
            }
        }
    }
}

// ---------------- fp16 tensor-core flash attention ----------------
// CTA: 128 q-rows of one (b,h), 256 thr, 8 warps x 16 rows (warp-private softmax).
// KV tiles 64, double-buffered cp.async. All smem strides 72 halves (conflict-free).
#define AQH   (128*72)
#define AKH   (64*72)
#define ASMEM ((AQH + 4*AKH) * 2)      // 55296 B
#define ANC   (NKV / 64)

__global__ void __launch_bounds__(256) attn_h(
    const __half* __restrict__ Q, const __half* __restrict__ K,
    const __half* __restrict__ V, __half* __restrict__ O)
{
    extern __shared__ __half smh[];
    __half* qs = smh;                  // [128][72]
    __half* ks = smh + AQH;            // [2][64][72]
    __half* vs = ks + 2 * AKH;         // [2][64][72]
    int tid = threadIdx.x, lane = tid & 31, wid = tid >> 5;
    int gid = lane >> 2, tig = lane & 3;
    int qb = blockIdx.x, h = blockIdx.y, b = blockIdx.z;

    const __half* Qb = Q + ((long)b * NQ + qb * 128) * HDIM + h * 64;
    const __half* Kb = K + (long)b * NKV * HDIM + h * 64;
    const __half* Vb = V + (long)b * NKV * HDIM + h * 64;

    auto load_kv = [&](int c, int buf) {
        __half* kd = ks + buf * AKH;
        __half* vd = vs + buf * AKH;
        long j0 = (long)c * 64;
#pragma unroll
        for (int i = 0; i < 2; i++) {
            int idx = tid + i * 256;
            int r = idx >> 3, c8 = (idx & 7) * 8;
            cpa16(smem_u32(kd + r * 72 + c8), Kb + (j0 + r) * HDIM + c8);
            cpa16(smem_u32(vd + r * 72 + c8), Vb + (j0 + r) * HDIM + c8);
        }
        asm volatile("cp.async.commit_group;\n" ::: "memory");
    };

    // Q + KV0 in group 0
#pragma unroll
    for (int i = 0; i < 4; i++) {
        int idx = tid + i * 256;
        int r = idx >> 3, c8 = (idx & 7) * 8;
        cpa16(smem_u32(qs + r * 72 + c8), Qb + (long)r * HDIM + c8);
    }
    load_kv(0, 0);

    float o[8][4];
#pragma unroll
    for (int nf = 0; nf < 8; nf++)
#pragma unroll
        for (int e = 0; e < 4; e++) o[nf][e] = 0.f;
    float m0 = -1e30f, m1 = -1e30f, l0 = 0.f, l1 = 0.f;

    const __half* aq = qs + (wid * 16 + gid) * 72 + 2 * tig;

    for (int c = 0; c < ANC; c++) {
        if (c + 1 < ANC) {
            load_kv(c + 1, (c + 1) & 1);
            asm volatile("cp.async.wait_group 1;\n" ::: "memory");
        } else {
            asm volatile("cp.async.wait_group 0;\n" ::: "memory");
        }
        __syncthreads();

        const __half* kcur = ks + (c & 1) * AKH;
        const __half* vcur = vs + (c & 1) * AKH;

        // ---- S = Q @ K^T  (scale folded into Q) ----
        float sc[8][4];
#pragma unroll
        for (int nf = 0; nf < 8; nf++)
#pragma unroll
            for (int e = 0; e < 4; e++) sc[nf][e] = 0.f;
#pragma unroll
        for (int kf = 0; kf < 4; kf++) {
            int k0 = kf * 16;
            uint32_t a[4];
            a[0] = *(const uint32_t*)(aq + k0);
            a[1] = *(const uint32_t*)(aq + k0 + 8 * 72);
            a[2] = *(const uint32_t*)(aq + k0 + 8);
            a[3] = *(const uint32_t*)(aq + k0 + 8 * 72 + 8);
            uint32_t bfr[8][2];
#pragma unroll
            for (int nf = 0; nf < 8; nf++) {
                const __half* bp = kcur + (nf * 8 + gid) * 72 + k0 + 2 * tig;
                bfr[nf][0] = *(const uint32_t*)(bp);
                bfr[nf][1] = *(const uint32_t*)(bp + 8);
            }
#pragma unroll
            for (int nf = 0; nf < 8; nf++)
                mma_f16(sc[nf], a, bfr[nf]);
        }

        // ---- online softmax (quad reduce over tig) ----
        float tm0 = -1e30f, tm1 = -1e30f;
#pragma unroll
        for (int nf = 0; nf < 8; nf++) {
            tm0 = fmaxf(tm0, fmaxf(sc[nf][0], sc[nf][1]));
            tm1 = fmaxf(tm1, fmaxf(sc[nf][2], sc[nf][3]));
        }
        tm0 = fmaxf(tm0, __shfl_xor_sync(0xffffffffu, tm0, 1));
        tm0 = fmaxf(tm0, __shfl_xor_sync(0xffffffffu, tm0, 2));
        tm1 = fmaxf(tm1, __shfl_xor_sync(0xffffffffu, tm1, 1));
        tm1 = fmaxf(tm1, __shfl_xor_sync(0xffffffffu, tm1, 2));
        float nm0 = fmaxf(m0, tm0), nm1 = fmaxf(m1, tm1);
        float corr0 = fexp(m0 - nm0), corr1 = fexp(m1 - nm1);
        m0 = nm0; m1 = nm1;

        uint32_t ph[4][4];            // packed P A-frags per j-chunk
        float ps0 = 0.f, ps1 = 0.f;
#pragma unroll
        for (int u = 0; u < 4; u++) {
            float p00 = fexp(sc[2*u][0] - nm0),   p01 = fexp(sc[2*u][1] - nm0);
            float p02 = fexp(sc[2*u][2] - nm1),   p03 = fexp(sc[2*u][3] - nm1);
            float p10 = fexp(sc[2*u+1][0] - nm0), p11 = fexp(sc[2*u+1][1] - nm0);
            float p12 = fexp(sc[2*u+1][2] - nm1), p13 = fexp(sc[2*u+1][3] - nm1);
            __half2 h0 = __floats2half2_rn(p00, p01);
            __half2 h1 = __floats2half2_rn(p02, p03);
            __half2 h2 = __floats2half2_rn(p10, p11);
            __half2 h3 = __floats2half2_rn(p12, p13);
            ph[u][0] = *(uint32_t*)&h0; ph[u][1] = *(uint32_t*)&h1;
            ph[u][2] = *(uint32_t*)&h2; ph[u][3] = *(uint32_t*)&h3;
            // sum the rounded values (consistency with the mma)
            float2 f0 = __half22float2(h0), f1 = __half22float2(h1);
            float2 f2 = __half22float2(h2), f3 = __half22float2(h3);
            ps0 += f0.x + f0.y + f2.x + f2.y;
            ps1 += f1.x + f1.y + f3.x + f3.y;
        }
        ps0 += __shfl_xor_sync(0xffffffffu, ps0, 1);
        ps0 += __shfl_xor_sync(0xffffffffu, ps0, 2);
        ps1 += __shfl_xor_sync(0xffffffffu, ps1, 1);
        ps1 += __shfl_xor_sync(0xffffffffu, ps1, 2);
        l0 = l0 * corr0 + ps0;
        l1 = l1 * corr1 + ps1;
#pragma unroll
        for (int nf = 0; nf < 8; nf++) {
            o[nf][0] *= corr0; o[nf][1] *= corr0;
            o[nf][2] *= corr1; o[nf][3] *= corr1;
        }

        // ---- O += P @ V : B-frags via paired ld.shared.u16 ----
#pragma unroll
        for (int u = 0; u < 4; u++) {
            int jb = u * 16 + 2 * tig;
            uint32_t bfr[8][2];
#pragma unroll
            for (int nf = 0; nf < 8; nf++) {
                int d = nf * 8 + gid;
                uint32_t lo0, hi0, lo1, hi1;
                uint32_t a0 = smem_u32(vcur + jb * 72 + d);
                asm volatile("ld.shared.u16 %0, [%1];"     : "=r"(lo0) : "r"(a0));
                asm volatile("ld.shared.u16 %0, [%1+144];" : "=r"(hi0) : "r"(a0));
                asm volatile("ld.shared.u16 %0, [%1+1152];": "=r"(lo1) : "r"(a0));
                asm volatile("ld.shared.u16 %0, [%1+1296];": "=r"(hi1) : "r"(a0));
                bfr[nf][0] = lo0 | (hi0 << 16);
                bfr[nf][1] = lo1 | (hi1 << 16);
            }
#pragma unroll
            for (int nf = 0; nf < 8; nf++)
                mma_f16(o[nf], ph[u], bfr[nf]);
        }
        __syncthreads();
    }

    // ---- write out fp16 ----
    float inv0 = 1.f / l0, inv1 = 1.f / l1;
    long r0 = (long)b * NQ + qb * 128 + wid * 16 + gid;
    long r1 = r0 + 8;
#pragma unroll
    for (int nf = 0; nf < 8; nf++) {
        int col = h * 64 + nf * 8 + 2 * tig;
        *(uint32_t*)(O + r0 * HDIM + col) = h2u(o[nf][0] * inv0, o[nf][1] * inv0);
        *(uint32_t*)(O + r1 * HDIM + col) = h2u(o[nf][2] * inv1, o[nf][3] * inv1);
    }
}

// ---------------- launcher ----------------
extern "C" void kernel_launch(void* const* d_in, const int* in_sizes, int n_in,
                              void* d_out, int out_size)
{
    const float* hid = (const float*)d_in[0];
    const float* x   = (const float*)d_in[1];
    const float* Wq  = (const float*)d_in[2];
    const float* bq  = (const float*)d_in[3];
    const float* Wk  = (const float*)d_in[4];
    const float* bk  = (const float*)d_in[5];
    const float* Wv  = (const float*)d_in[6];
    const float* bv  = (const float*)d_in[7];
    const float* Wo  = (const float*)d_in[8];
    const float* bo  = (const float*)d_in[9];
    const float* W1  = (const float*)d_in[10];
    const float* b1  = (const float*)d_in[11];
    const float* W2  = (const float*)d_in[12];
    const float* b2  = (const float*)d_in[13];
    const float* gi  = (const float*)d_in[14];
    const float* bi  = (const float*)d_in[15];
    const float* gh  = (const float*)d_in[16];
    const float* bh  = (const float*)d_in[17];
    const float* gf  = (const float*)d_in[18];
    const float* bf  = (const float*)d_in[19];

    __half *xn, *hn, *q, *k, *v, *ctx, *hnf, *ff;
    __half *wq, *wk, *wv, *wo, *w1, *w2;
    float *o1;
    cudaGetSymbolAddress((void**)&xn,  g_xn);
    cudaGetSymbolAddress((void**)&hn,  g_hn);
    cudaGetSymbolAddress((void**)&q,   g_q);
    cudaGetSymbolAddress((void**)&k,   g_k);
    cudaGetSymbolAddress((void**)&v,   g_v);
    cudaGetSymbolAddress((void**)&ctx, g_ctx);
    cudaGetSymbolAddress((void**)&o1,  g_o1);
    cudaGetSymbolAddress((void**)&hnf, g_hnf);
    cudaGetSymbolAddress((void**)&ff,  g_ff);
    cudaGetSymbolAddress((void**)&wq,  g_wq);
    cudaGetSymbolAddress((void**)&wk,  g_wk);
    cudaGetSymbolAddress((void**)&wv,  g_wv);
    cudaGetSymbolAddress((void**)&wo,  g_wo);
    cudaGetSymbolAddress((void**)&w1,  g_w1);
    cudaGetSymbolAddress((void**)&w2,  g_w2);

    cudaFuncSetAttribute(attn_h, cudaFuncAttributeMaxDynamicSharedMemorySize, ASMEM);
    cudaFuncSetAttribute(gemm_h, cudaFuncAttributeMaxDynamicSharedMemorySize, HGSM);

    // launches 0-4 (so launch #5 = K-projection GEMM gets profiled by ncu -s 5 -c 1)
    wprep<<<dim3(HDIM / 32,  IMGD / 32), 256>>>(Wk, wk, IMGD, HDIM);      // 0
    wprep<<<dim3(HDIM / 32,  IMGD / 32), 256>>>(Wv, wv, IMGD, HDIM);      // 1
    ln_kernel<<<BB * NKV, 256>>>(x,   gi, bi, xn, IMGD);                  // 2
    ln_kernel<<<BB * NQ,  256>>>(hid, gh, bh, hn, HDIM);                  // 3
    wprep<<<dim3(HDIM / 32,  HDIM / 32), 256>>>(Wq, wq, HDIM, HDIM);      // 4

    // 5: K projection (profiled)
    gemm_h<<<dim3(HDIM / 128, BB * NKV / 128), 256, HGSM>>>(xn, wk, bk, nullptr, k, BB * NKV, HDIM, IMGD, 3);
    // 6: V projection
    gemm_h<<<dim3(HDIM / 128, BB * NKV / 128), 256, HGSM>>>(xn, wv, bv, nullptr, v, BB * NKV, HDIM, IMGD, 3);
    // 7: Q projection (scale folded)
    gemm_h<<<dim3(HDIM / 128, BB * NQ  / 128), 256, HGSM>>>(hn, wq, bq, nullptr, q, BB * NQ,  HDIM, HDIM, 4);

    // remaining weight preps
    wprep<<<dim3(HDIM / 32,  HDIM / 32),  256>>>(Wo, wo, HDIM, HDIM);
    wprep<<<dim3(INTER / 32, HDIM / 32),  256>>>(W1, w1, HDIM, INTER);
    wprep<<<dim3(HDIM / 32,  INTER / 32), 256>>>(W2, w2, INTER, HDIM);

    // attention
    attn_h<<<dim3(NQ / 128, HEADS, BB), 256, ASMEM>>>(q, k, v, ctx);

    // output proj + residual (fp32 out)
    gemm_h<<<dim3(HDIM / 128, BB * NQ / 128), 256, HGSM>>>(ctx, wo, bo, hid, o1, BB * NQ, HDIM, HDIM, 1);

    // FFN
    ln_kernel<<<BB * NQ, 256>>>(o1, gf, bf, hnf, HDIM);
    gemm_h<<<dim3(INTER / 128, BB * NQ / 128), 256, HGSM>>>(hnf, w1, b1, nullptr, ff, BB * NQ, INTER, HDIM, 2);
    gemm_h<<<dim3(HDIM / 128,  BB * NQ / 128), 256, HGSM>>>(ff, w2, b2, o1, d_out, BB * NQ, HDIM, INTER, 1);
}

// round 6
// speedup vs baseline: 2.6112x; 1.1171x over previous
#include <cuda_runtime.h>
#include <cuda_fp16.h>
#include <cstdint>
#include <math.h>

#define BB    16
#define NQ    256
#define NKV   2304
#define HDIM  768
#define IMGD  1024
#define HEADS 12
#define INTER 3072
#define ATTN_SCALE 0.125f

// ---------------- scratch (static __device__, allocation-free) ----------------
__device__ __half g_xn [BB*NKV*IMGD];
__device__ __half g_hn [BB*NQ*HDIM];
__device__ __half g_q  [BB*NQ*HDIM];
__device__ __half g_k  [BB*NKV*HDIM];
__device__ __half g_v  [BB*NKV*HDIM];
__device__ __half g_ctx[BB*NQ*HDIM];
__device__ float  g_o1 [BB*NQ*HDIM];
__device__ __half g_hnf[BB*NQ*HDIM];
__device__ __half g_ff [BB*NQ*INTER];
// transposed fp16 weights [N,K]
__device__ __half g_wq[HDIM*HDIM];
__device__ __half g_wk[HDIM*IMGD];
__device__ __half g_wv[HDIM*IMGD];
__device__ __half g_wo[HDIM*HDIM];
__device__ __half g_w1[INTER*HDIM];
__device__ __half g_w2[HDIM*INTER];

// ---------------- helpers ----------------
__device__ __forceinline__ uint32_t smem_u32(const void* p) {
    uint32_t a;
    asm("{ .reg .u64 t; cvta.to.shared.u64 t, %1; cvt.u32.u64 %0, t; }" : "=r"(a) : "l"(p));
    return a;
}
__device__ __forceinline__ void cpa16(uint32_t dst, const void* src) {
    asm volatile("cp.async.cg.shared.global [%0], [%1], 16;\n" :: "r"(dst), "l"(src));
}
__device__ __forceinline__ void mma_f16(float* c, const uint32_t* a, const uint32_t* b) {
    asm volatile(
        "mma.sync.aligned.m16n8k16.row.col.f32.f16.f16.f32 "
        "{%0,%1,%2,%3}, {%4,%5,%6,%7}, {%8,%9}, {%0,%1,%2,%3};\n"
        : "+f"(c[0]), "+f"(c[1]), "+f"(c[2]), "+f"(c[3])
        : "r"(a[0]), "r"(a[1]), "r"(a[2]), "r"(a[3]), "r"(b[0]), "r"(b[1]));
}
__device__ __forceinline__ void ldm_x4(uint32_t* r, uint32_t addr) {
    asm volatile("ldmatrix.sync.aligned.m8n8.x4.shared.b16 {%0,%1,%2,%3}, [%4];"
        : "=r"(r[0]), "=r"(r[1]), "=r"(r[2]), "=r"(r[3]) : "r"(addr));
}
__device__ __forceinline__ void ldm_x4_t(uint32_t* r, uint32_t addr) {
    asm volatile("ldmatrix.sync.aligned.m8n8.x4.trans.shared.b16 {%0,%1,%2,%3}, [%4];"
        : "=r"(r[0]), "=r"(r[1]), "=r"(r[2]), "=r"(r[3]) : "r"(addr));
}
// fast exp2-based exp, no MUFU
__device__ __forceinline__ float fexp(float x) {
    float y = fmaxf(x * 1.44269504f, -120.f);
    float r = y + 12582912.f;
    float n = r - 12582912.f;
    float f = y - n;
    float p = 0.00133336f;
    p = fmaf(p, f, 0.00961804f);
    p = fmaf(p, f, 0.05550411f);
    p = fmaf(p, f, 0.24022651f);
    p = fmaf(p, f, 0.69314718f);
    p = fmaf(p, f, 1.0f);
    int ni = __float_as_int(r) - 0x4B400000;
    return p * __int_as_float((ni + 127) << 23);
}
__device__ __forceinline__ uint32_t h2u(float lo, float hi) {
    __half2 h = __floats2half2_rn(lo, hi);
    return *(uint32_t*)&h;
}

// ---------------- weight prep: transpose [K,N] -> [N,K] fp16 ----------------
__global__ void __launch_bounds__(256) wprep(const float* __restrict__ W,
                                             __half* __restrict__ WT, int K, int N) {
    __shared__ float t[32][33];
    int nb = blockIdx.x * 32, kb = blockIdx.y * 32;
    int tx = threadIdx.x & 31, ty = threadIdx.x >> 5;
#pragma unroll
    for (int i = 0; i < 32; i += 8)
        t[ty + i][tx] = W[(long)(kb + ty + i) * N + nb + tx];
    __syncthreads();
#pragma unroll
    for (int i = 0; i < 32; i += 8)
        WT[(long)(nb + ty + i) * K + kb + tx] = __float2half(t[tx][ty + i]);
}

// ---------------- LayerNorm: fp32 in -> fp16 out (vectorized, one-pass) -------
__global__ void __launch_bounds__(256) ln_kernel(
    const float* __restrict__ in, const float* __restrict__ gam,
    const float* __restrict__ bet, __half* __restrict__ out, int D)
{
    __shared__ float rs[8], rq[8];
    long row = blockIdx.x;
    int tid = threadIdx.x, lane = tid & 31, wid = tid >> 5;
    int i4 = tid * 4;
    float4 v = make_float4(0.f, 0.f, 0.f, 0.f);
    if (i4 < D) v = *(const float4*)(in + row * (long)D + i4);
    float s  = v.x + v.y + v.z + v.w;
    float s2 = v.x * v.x + v.y * v.y + v.z * v.z + v.w * v.w;
#pragma unroll
    for (int m = 16; m; m >>= 1) {
        s  += __shfl_xor_sync(0xffffffffu, s,  m);
        s2 += __shfl_xor_sync(0xffffffffu, s2, m);
    }
    if (lane == 0) { rs[wid] = s; rq[wid] = s2; }
    __syncthreads();
    s = 0.f; s2 = 0.f;
#pragma unroll
    for (int i = 0; i < 8; i++) { s += rs[i]; s2 += rq[i]; }
    float mu   = s / (float)D;
    float var  = fmaxf(s2 / (float)D - mu * mu, 0.f);
    float rstd = rsqrtf(var + 1e-5f);
    if (i4 < D) {
        float4 g = *(const float4*)(gam + i4);
        float4 b = *(const float4*)(bet + i4);
        __half* orow = out + row * (long)D + i4;
        *(uint32_t*)(orow)     = h2u((v.x - mu) * rstd * g.x + b.x,
                                     (v.y - mu) * rstd * g.y + b.y);
        *(uint32_t*)(orow + 2) = h2u((v.z - mu) * rstd * g.z + b.z,
                                     (v.w - mu) * rstd * g.w + b.w);
    }
}

// ---------------- fp16 mma.sync GEMM (ldmatrix mainloop) ----------------
// C[M,N] = Ah[M,K] @ WTh[N,K]^T + bias
// epi: 1 = +res -> fp32 out ; 2 = gelu -> fp16 ; 3 = -> fp16 ; 4 = *SCALE -> fp16
#define HGA   (128*40)
#define HGST  (2*HGA)
#define HGSM  (3*HGST*2)

__global__ void __launch_bounds__(256, 2) gemm_h(
    const __half* __restrict__ A, const __half* __restrict__ Bw,
    const float* __restrict__ bias, const float* __restrict__ res,
    void* __restrict__ Cout, int M, int N, int K, int epi)
{
    extern __shared__ __half smh[];
    int tid = threadIdx.x, lane = tid & 31, wid = tid >> 5;
    int gid = lane >> 2, tig = lane & 3;
    int wm = wid & 1, wn = wid >> 1;
    int m0 = blockIdx.y * 128, n0 = blockIdx.x * 128;

    // ldmatrix per-lane row/col (half offsets)
    int l8    = lane & 7;
    int amrow = wm * 64 + ((lane >> 3) & 1) * 8 + l8;   // + mf*16
    int akcol = (lane >> 4) * 8;                        // + ks*16
    int bnrow = wn * 32 + (lane >> 4) * 8 + l8;         // + np*16
    int bkcol = ((lane >> 3) & 1) * 8;                  // + ks*16

    float acc[4][4][4];
#pragma unroll
    for (int i = 0; i < 4; i++)
#pragma unroll
        for (int j = 0; j < 4; j++)
#pragma unroll
            for (int r = 0; r < 4; r++) acc[i][j][r] = 0.f;

    const int NC = K / 32;

    auto issue = [&](int c, int s) {
        __half* as = smh + s * HGST;
        __half* bs = as + HGA;
        long kb = (long)c * 32;
#pragma unroll
        for (int i = 0; i < 2; i++) {
            int idx = tid + i * 256;
            int r = idx >> 2, c8 = (idx & 3) * 8;
            cpa16(smem_u32(as + r * 40 + c8), A  + (long)(m0 + r) * K + kb + c8);
        }
#pragma unroll
        for (int i = 0; i < 2; i++) {
            int idx = tid + i * 256;
            int r = idx >> 2, c8 = (idx & 3) * 8;
            cpa16(smem_u32(bs + r * 40 + c8), Bw + (long)(n0 + r) * K + kb + c8);
        }
        asm volatile("cp.async.commit_group;\n" ::: "memory");
    };

    issue(0, 0);
    if (NC > 1) issue(1, 1);

    for (int c = 0; c < NC; c++) {
        int s = c % 3;
        if (c + 1 < NC) asm volatile("cp.async.wait_group 1;\n" ::: "memory");
        else            asm volatile("cp.async.wait_group 0;\n" ::: "memory");
        __syncthreads();
        if (c + 2 < NC) issue(c + 2, (c + 2) % 3);   // stage consumed at iter c-1

        const __half* as = smh + s * HGST;
        const __half* bs = as + HGA;
#pragma unroll
        for (int ks = 0; ks < 2; ks++) {
            uint32_t a[4][4], b[2][4];
#pragma unroll
            for (int mf = 0; mf < 4; mf++)
                ldm_x4(a[mf], smem_u32(as + (amrow + mf * 16) * 40 + ks * 16 + akcol));
#pragma unroll
            for (int np = 0; np < 2; np++)
                ldm_x4(b[np], smem_u32(bs + (bnrow + np * 16) * 40 + ks * 16 + bkcol));
#pragma unroll
            for (int mf = 0; mf < 4; mf++)
#pragma unroll
                for (int nf = 0; nf < 4; nf++)
                    mma_f16(acc[mf][nf], a[mf], &b[nf >> 1][(nf & 1) * 2]);
        }
    }

    // ---- epilogue ----
    int cbase = n0 + wn * 32 + 2 * tig;
    float2 bl[4];
#pragma unroll
    for (int nf = 0; nf < 4; nf++)
        bl[nf] = *(const float2*)(bias + cbase + nf * 8);

#pragma unroll
    for (int mf = 0; mf < 4; mf++) {
#pragma unroll
        for (int hh = 0; hh < 2; hh++) {
            long r = m0 + wm * 64 + mf * 16 + gid + hh * 8;
#pragma unroll
            for (int nf = 0; nf < 4; nf++) {
                int col = cbase + nf * 8;
                float v0 = acc[mf][nf][hh * 2 + 0] + bl[nf].x;
                float v1 = acc[mf][nf][hh * 2 + 1] + bl[nf].y;
                if (epi == 1) {
                    float2 rv = *(const float2*)(res + r * (long)N + col);
                    *(float2*)((float*)Cout + r * (long)N + col) =
                        make_float2(v0 + rv.x, v1 + rv.y);
                } else {
                    if (epi == 2) {
                        v0 = 0.5f * v0 * (1.f + erff(v0 * 0.70710678118654752f));
                        v1 = 0.5f * v1 * (1.f + erff(v1 * 0.70710678118654752f));
                    } else if (epi == 4) {
                        v0 *= ATTN_SCALE; v1 *= ATTN_SCALE;
                    }
                    *(uint32_t*)((__half*)Cout + r * (long)N + col) = h2u(v0, v1);
                }
            }
        }
    }
}

// ---------------- fp16 tensor-core flash attention (ldmatrix) ----------------
#define AQH   (128*72)
#define AKH   (64*72)
#define ASMEM ((AQH + 4*AKH) * 2)      // 55296 B
#define ANC   (NKV / 64)

__global__ void __launch_bounds__(256, 2) attn_h(
    const __half* __restrict__ Q, const __half* __restrict__ K,
    const __half* __restrict__ V, __half* __restrict__ O)
{
    extern __shared__ __half smh[];
    __half* qs = smh;                  // [128][72]
    __half* ks = smh + AQH;            // [2][64][72]
    __half* vs = ks + 2 * AKH;         // [2][64][72]
    int tid = threadIdx.x, lane = tid & 31, wid = tid >> 5;
    int gid = lane >> 2, tig = lane & 3;
    int qb = blockIdx.x, h = blockIdx.y, b = blockIdx.z;

    const __half* Qb = Q + ((long)b * NQ + qb * 128) * HDIM + h * 64;
    const __half* Kb = K + (long)b * NKV * HDIM + h * 64;
    const __half* Vb = V + (long)b * NKV * HDIM + h * 64;

    // ldmatrix per-lane offsets
    int l8    = lane & 7;
    int qrow  = wid * 16 + ((lane >> 3) & 1) * 8 + l8;  // A-frag rows
    int qcol  = (lane >> 4) * 8;                        // + kf*16
    int krow  = (lane >> 4) * 8 + l8;                   // + np*16 (B-frag rows)
    int kcol  = ((lane >> 3) & 1) * 8;                  // + kf*16
    int vrow  = ((lane >> 3) & 1) * 8 + l8;             // + u*16 (trans: k rows)
    int vcol  = (lane >> 4) * 8;                        // + np*16 (trans: n cols)

    auto load_kv = [&](int c, int buf) {
        __half* kd = ks + buf * AKH;
        __half* vd = vs + buf * AKH;
        long j0 = (long)c * 64;
#pragma unroll
        for (int i = 0; i < 2; i++) {
            int idx = tid + i * 256;
            int r = idx >> 3, c8 = (idx & 7) * 8;
            cpa16(smem_u32(kd + r * 72 + c8), Kb + (j0 + r) * HDIM + c8);
            cpa16(smem_u32(vd + r * 72 + c8), Vb + (j0 + r) * HDIM + c8);
        }
        asm volatile("cp.async.commit_group;\n" ::: "memory");
    };

    // Q + KV0 in group 0
#pragma unroll
    for (int i = 0; i < 4; i++) {
        int idx = tid + i * 256;
        int r = idx >> 3, c8 = (idx & 7) * 8;
        cpa16(smem_u32(qs + r * 72 + c8), Qb + (long)r * HDIM + c8);
    }
    load_kv(0, 0);

    float o[8][4];
#pragma unroll
    for (int nf = 0; nf < 8; nf++)
#pragma unroll
        for (int e = 0; e < 4; e++) o[nf][e] = 0.f;
    float m0 = -1e30f, m1 = -1e30f, l0 = 0.f, l1 = 0.f;

    uint32_t qa[4][4];                 // hoisted Q A-frags (loop-invariant)

    for (int c = 0; c < ANC; c++) {
        if (c + 1 < ANC) {
            load_kv(c + 1, (c + 1) & 1);
            asm volatile("cp.async.wait_group 1;\n" ::: "memory");
        } else {
            asm volatile("cp.async.wait_group 0;\n" ::: "memory");
        }
        __syncthreads();

        if (c == 0) {
#pragma unroll
            for (int kf = 0; kf < 4; kf++)
                ldm_x4(qa[kf], smem_u32(qs + qrow * 72 + kf * 16 + qcol));
        }

        const __half* kcur = ks + (c & 1) * AKH;
        const __half* vcur = vs + (c & 1) * AKH;

        // ---- S = Q @ K^T (scale folded into Q) ----
        float sc[8][4];
#pragma unroll
        for (int nf = 0; nf < 8; nf++)
#pragma unroll
            for (int e = 0; e < 4; e++) sc[nf][e] = 0.f;
#pragma unroll
        for (int kf = 0; kf < 4; kf++) {
            uint32_t kb4[4][4];
#pragma unroll
            for (int np = 0; np < 4; np++)
                ldm_x4(kb4[np], smem_u32(kcur + (krow + np * 16) * 72 + kf * 16 + kcol));
#pragma unroll
            for (int np = 0; np < 4; np++) {
                mma_f16(sc[2 * np],     qa[kf], &kb4[np][0]);
                mma_f16(sc[2 * np + 1], qa[kf], &kb4[np][2]);
            }
        }

        // ---- online softmax (quad reduce over tig) ----
        float tm0 = -1e30f, tm1 = -1e30f;
#pragma unroll
        for (int nf = 0; nf < 8; nf++) {
            tm0 = fmaxf(tm0, fmaxf(sc[nf][0], sc[nf][1]));
            tm1 = fmaxf(tm1, fmaxf(sc[nf][2], sc[nf][3]));
        }
        tm0 = fmaxf(tm0, __shfl_xor_sync(0xffffffffu, tm0, 1));
        tm0 = fmaxf(tm0, __shfl_xor_sync(0xffffffffu, tm0, 2));
        tm1 = fmaxf(tm1, __shfl_xor_sync(0xffffffffu, tm1, 1));
        tm1 = fmaxf(tm1, __shfl_xor_sync(0xffffffffu, tm1, 2));
        float nm0 = fmaxf(m0, tm0), nm1 = fmaxf(m1, tm1);
        float corr0 = fexp(m0 - nm0), corr1 = fexp(m1 - nm1);
        m0 = nm0; m1 = nm1;

        uint32_t ph[4][4];
        float ps0 = 0.f, ps1 = 0.f;
#pragma unroll
        for (int u = 0; u < 4; u++) {
            float p00 = fexp(sc[2*u][0] - nm0),   p01 = fexp(sc[2*u][1] - nm0);
            float p02 = fexp(sc[2*u][2] - nm1),   p03 = fexp(sc[2*u][3] - nm1);
            float p10 = fexp(sc[2*u+1][0] - nm0), p11 = fexp(sc[2*u+1][1] - nm0);
            float p12 = fexp(sc[2*u+1][2] - nm1), p13 = fexp(sc[2*u+1][3] - nm1);
            __half2 h0 = __floats2half2_rn(p00, p01);
            __half2 h1 = __floats2half2_rn(p02, p03);
            __half2 h2 = __floats2half2_rn(p10, p11);
            __half2 h3 = __floats2half2_rn(p12, p13);
            ph[u][0] = *(uint32_t*)&h0; ph[u][1] = *(uint32_t*)&h1;
            ph[u][2] = *(uint32_t*)&h2; ph[u][3] = *(uint32_t*)&h3;
            float2 f0 = __half22float2(h0), f1 = __half22float2(h1);
            float2 f2 = __half22float2(h2), f3 = __half22float2(h3);
            ps0 += f0.x + f0.y + f2.x + f2.y;
            ps1 += f1.x + f1.y + f3.x + f3.y;
        }
        ps0 += __shfl_xor_sync(0xffffffffu, ps0, 1);
        ps0 += __shfl_xor_sync(0xffffffffu, ps0, 2);
        ps1 += __shfl_xor_sync(0xffffffffu, ps1, 1);
        ps1 += __shfl_xor_sync(0xffffffffu, ps1, 2);
        l0 = l0 * corr0 + ps0;
        l1 = l1 * corr1 + ps1;
#pragma unroll
        for (int nf = 0; nf < 8; nf++) {
            o[nf][0] *= corr0; o[nf][1] *= corr0;
            o[nf][2] *= corr1; o[nf][3] *= corr1;
        }

        // ---- O += P @ V  (V B-frags via ldmatrix.trans) ----
#pragma unroll
        for (int u = 0; u < 4; u++) {
#pragma unroll
            for (int np = 0; np < 4; np++) {
                uint32_t vb[4];
                ldm_x4_t(vb, smem_u32(vcur + (u * 16 + vrow) * 72 + np * 16 + vcol));
                mma_f16(o[2 * np],     ph[u], &vb[0]);
                mma_f16(o[2 * np + 1], ph[u], &vb[2]);
            }
        }
        __syncthreads();
    }

    // ---- write out fp16 ----
    float inv0 = 1.f / l0, inv1 = 1.f / l1;
    long r0 = (long)b * NQ + qb * 128 + wid * 16 + gid;
    long r1 = r0 + 8;
#pragma unroll
    for (int nf = 0; nf < 8; nf++) {
        int col = h * 64 + nf * 8 + 2 * tig;
        *(uint32_t*)(O + r0 * HDIM + col) = h2u(o[nf][0] * inv0, o[nf][1] * inv0);
        *(uint32_t*)(O + r1 * HDIM + col) = h2u(o[nf][2] * inv1, o[nf][3] * inv1);
    }
}

// ---------------- launcher ----------------
extern "C" void kernel_launch(void* const* d_in, const int* in_sizes, int n_in,
                              void* d_out, int out_size)
{
    const float* hid = (const float*)d_in[0];
    const float* x   = (const float*)d_in[1];
    const float* Wq  = (const float*)d_in[2];
    const float* bq  = (const float*)d_in[3];
    const float* Wk  = (const float*)d_in[4];
    const float* bk  = (const float*)d_in[5];
    const float* Wv  = (const float*)d_in[6];
    const float* bv  = (const float*)d_in[7];
    const float* Wo  = (const float*)d_in[8];
    const float* bo  = (const float*)d_in[9];
    const float* W1  = (const float*)d_in[10];
    const float* b1  = (const float*)d_in[11];
    const float* W2  = (const float*)d_in[12];
    const float* b2  = (const float*)d_in[13];
    const float* gi  = (const float*)d_in[14];
    const float* bi  = (const float*)d_in[15];
    const float* gh  = (const float*)d_in[16];
    const float* bh  = (const float*)d_in[17];
    const float* gf  = (const float*)d_in[18];
    const float* bf  = (const float*)d_in[19];

    __half *xn, *hn, *q, *k, *v, *ctx, *hnf, *ff;
    __half *wq, *wk, *wv, *wo, *w1, *w2;
    float *o1;
    cudaGetSymbolAddress((void**)&xn,  g_xn);
    cudaGetSymbolAddress((void**)&hn,  g_hn);
    cudaGetSymbolAddress((void**)&q,   g_q);
    cudaGetSymbolAddress((void**)&k,   g_k);
    cudaGetSymbolAddress((void**)&v,   g_v);
    cudaGetSymbolAddress((void**)&ctx, g_ctx);
    cudaGetSymbolAddress((void**)&o1,  g_o1);
    cudaGetSymbolAddress((void**)&hnf, g_hnf);
    cudaGetSymbolAddress((void**)&ff,  g_ff);
    cudaGetSymbolAddress((void**)&wq,  g_wq);
    cudaGetSymbolAddress((void**)&wk,  g_wk);
    cudaGetSymbolAddress((void**)&wv,  g_wv);
    cudaGetSymbolAddress((void**)&wo,  g_wo);
    cudaGetSymbolAddress((void**)&w1,  g_w1);
    cudaGetSymbolAddress((void**)&w2,  g_w2);

    cudaFuncSetAttribute(attn_h, cudaFuncAttributeMaxDynamicSharedMemorySize, ASMEM);
    cudaFuncSetAttribute(gemm_h, cudaFuncAttributeMaxDynamicSharedMemorySize, HGSM);

    // order chosen so launches #3 and #5 are the big K/V-projection GEMMs
    wprep<<<dim3(HDIM / 32, IMGD / 32), 256>>>(Wk, wk, IMGD, HDIM);                      // 0
    wprep<<<dim3(HDIM / 32, IMGD / 32), 256>>>(Wv, wv, IMGD, HDIM);                      // 1
    ln_kernel<<<BB * NKV, 256>>>(x, gi, bi, xn, IMGD);                                   // 2
    gemm_h<<<dim3(HDIM / 128, BB * NKV / 128), 256, HGSM>>>(xn, wk, bk, nullptr, k,      // 3
                                                            BB * NKV, HDIM, IMGD, 3);
    ln_kernel<<<BB * NQ, 256>>>(hid, gh, bh, hn, HDIM);                                  // 4
    gemm_h<<<dim3(HDIM / 128, BB * NKV / 128), 256, HGSM>>>(xn, wv, bv, nullptr, v,      // 5
                                                            BB * NKV, HDIM, IMGD, 3);
    wprep<<<dim3(HDIM / 32, HDIM / 32), 256>>>(Wq, wq, HDIM, HDIM);                      // 6
    gemm_h<<<dim3(HDIM / 128, BB * NQ / 128), 256, HGSM>>>(hn, wq, bq, nullptr, q,       // 7
                                                           BB * NQ, HDIM, HDIM, 4);
    wprep<<<dim3(HDIM / 32,  HDIM / 32),  256>>>(Wo, wo, HDIM, HDIM);
    wprep<<<dim3(INTER / 32, HDIM / 32),  256>>>(W1, w1, HDIM, INTER);
    wprep<<<dim3(HDIM / 32,  INTER / 32), 256>>>(W2, w2, INTER, HDIM);

    attn_h<<<dim3(NQ / 128, HEADS, BB), 256, ASMEM>>>(q, k, v, ctx);

    gemm_h<<<dim3(HDIM / 128, BB * NQ / 128), 256, HGSM>>>(ctx, wo, bo, hid, o1,
                                                           BB * NQ, HDIM, HDIM, 1);

    ln_kernel<<<BB * NQ, 256>>>(o1, gf, bf, hnf, HDIM);
    gemm_h<<<dim3(INTER / 128, BB * NQ / 128), 256, HGSM>>>(hnf, w1, b1, nullptr, ff,
                                                            BB * NQ, INTER, HDIM, 2);
    gemm_h<<<dim3(HDIM / 128,  BB * NQ / 128), 256, HGSM>>>(ff, w2, b2, o1, d_out,
                                                            BB * NQ, HDIM, INTER, 1);
}

// round 11
// speedup vs baseline: 2.9546x; 1.1315x over previous
#include <cuda_runtime.h>
#include <cuda_fp16.h>
#include <cstdint>
#include <math.h>

#define BB    16
#define NQ    256
#define NKV   2304
#define HDIM  768
#define IMGD  1024
#define HEADS 12
#define INTER 3072
#define KVS   1536            // fused K|V row stride
#define ATTN_SCALE 0.125f

// ---------------- scratch (static __device__, allocation-free) ----------------
__device__ __half g_xn [BB*NKV*IMGD];
__device__ __half g_hn [BB*NQ*HDIM];
__device__ __half g_q  [BB*NQ*HDIM];
__device__ __half g_kv [BB*NKV*KVS];          // fused K|V
__device__ __half g_ctx[BB*NQ*HDIM];
__device__ float  g_o1 [BB*NQ*HDIM];
__device__ __half g_hnf[BB*NQ*HDIM];
__device__ __half g_ff [BB*NQ*INTER];
// transposed fp16 weights [N,K]
__device__ __half g_wq [HDIM*HDIM];
__device__ __half g_wkv[KVS*IMGD];            // rows 0..767 = Wk^T, 768..1535 = Wv^T
__device__ __half g_wo [HDIM*HDIM];
__device__ __half g_w1 [INTER*HDIM];
__device__ __half g_w2 [HDIM*INTER];
__device__ float  g_bkv[KVS];

// ---------------- helpers ----------------
__device__ __forceinline__ uint32_t smem_u32(const void* p) {
    uint32_t a;
    asm("{ .reg .u64 t; cvta.to.shared.u64 t, %1; cvt.u32.u64 %0, t; }" : "=r"(a) : "l"(p));
    return a;
}
__device__ __forceinline__ void cpa16(uint32_t dst, const void* src) {
    asm volatile("cp.async.cg.shared.global [%0], [%1], 16;\n" :: "r"(dst), "l"(src));
}
__device__ __forceinline__ void mma_f16(float* c, const uint32_t* a, const uint32_t* b) {
    asm volatile(
        "mma.sync.aligned.m16n8k16.row.col.f32.f16.f16.f32 "
        "{%0,%1,%2,%3}, {%4,%5,%6,%7}, {%8,%9}, {%0,%1,%2,%3};\n"
        : "+f"(c[0]), "+f"(c[1]), "+f"(c[2]), "+f"(c[3])
        : "r"(a[0]), "r"(a[1]), "r"(a[2]), "r"(a[3]), "r"(b[0]), "r"(b[1]));
}
__device__ __forceinline__ void ldm_x4(uint32_t* r, uint32_t addr) {
    asm volatile("ldmatrix.sync.aligned.m8n8.x4.shared.b16 {%0,%1,%2,%3}, [%4];"
        : "=r"(r[0]), "=r"(r[1]), "=r"(r[2]), "=r"(r[3]) : "r"(addr));
}
__device__ __forceinline__ void ldm_x4_t(uint32_t* r, uint32_t addr) {
    asm volatile("ldmatrix.sync.aligned.m8n8.x4.trans.shared.b16 {%0,%1,%2,%3}, [%4];"
        : "=r"(r[0]), "=r"(r[1]), "=r"(r[2]), "=r"(r[3]) : "r"(addr));
}
__device__ __forceinline__ float fexp(float x) {
    float y = fmaxf(x * 1.44269504f, -120.f);
    float r = y + 12582912.f;
    float n = r - 12582912.f;
    float f = y - n;
    float p = 0.00133336f;
    p = fmaf(p, f, 0.00961804f);
    p = fmaf(p, f, 0.05550411f);
    p = fmaf(p, f, 0.24022651f);
    p = fmaf(p, f, 0.69314718f);
    p = fmaf(p, f, 1.0f);
    int ni = __float_as_int(r) - 0x4B400000;
    return p * __int_as_float((ni + 127) << 23);
}
__device__ __forceinline__ uint32_t h2u(float lo, float hi) {
    __half2 h = __floats2half2_rn(lo, hi);
    return *(uint32_t*)&h;
}

// ---------------- weight prep: transpose [K,N] -> [N,K] fp16 ----------------
__global__ void __launch_bounds__(256) wprep(const float* __restrict__ W,
                                             __half* __restrict__ WT, int K, int N) {
    __shared__ float t[32][33];
    int nb = blockIdx.x * 32, kb = blockIdx.y * 32;
    int tx = threadIdx.x & 31, ty = threadIdx.x >> 5;
#pragma unroll
    for (int i = 0; i < 32; i += 8)
        t[ty + i][tx] = W[(long)(kb + ty + i) * N + nb + tx];
    __syncthreads();
#pragma unroll
    for (int i = 0; i < 32; i += 8)
        WT[(long)(nb + ty + i) * K + kb + tx] = __float2half(t[tx][ty + i]);
}

__global__ void __launch_bounds__(256) bcat2(const float* __restrict__ a,
                                             const float* __restrict__ b,
                                             float* __restrict__ o) {
    int i = blockIdx.x * 256 + threadIdx.x;
    if (i < HDIM)          o[i] = a[i];
    else if (i < 2 * HDIM) o[i] = b[i - HDIM];
}

// ---------------- LayerNorm: fp32 in -> fp16 out (vectorized, one-pass) -------
__global__ void __launch_bounds__(256) ln_kernel(
    const float* __restrict__ in, const float* __restrict__ gam,
    const float* __restrict__ bet, __half* __restrict__ out, int D)
{
    __shared__ float rs[8], rq[8];
    long row = blockIdx.x;
    int tid = threadIdx.x, lane = tid & 31, wid = tid >> 5;
    int i4 = tid * 4;
    float4 v = make_float4(0.f, 0.f, 0.f, 0.f);
    if (i4 < D) v = *(const float4*)(in + row * (long)D + i4);
    float s  = v.x + v.y + v.z + v.w;
    float s2 = v.x * v.x + v.y * v.y + v.z * v.z + v.w * v.w;
#pragma unroll
    for (int m = 16; m; m >>= 1) {
        s  += __shfl_xor_sync(0xffffffffu, s,  m);
        s2 += __shfl_xor_sync(0xffffffffu, s2, m);
    }
    if (lane == 0) { rs[wid] = s; rq[wid] = s2; }
    __syncthreads();
    s = 0.f; s2 = 0.f;
#pragma unroll
    for (int i = 0; i < 8; i++) { s += rs[i]; s2 += rq[i]; }
    float mu   = s / (float)D;
    float var  = fmaxf(s2 / (float)D - mu * mu, 0.f);
    float rstd = rsqrtf(var + 1e-5f);
    if (i4 < D) {
        float4 g = *(const float4*)(gam + i4);
        float4 b = *(const float4*)(bet + i4);
        __half* orow = out + row * (long)D + i4;
        *(uint32_t*)(orow)     = h2u((v.x - mu) * rstd * g.x + b.x,
                                     (v.y - mu) * rstd * g.y + b.y);
        *(uint32_t*)(orow + 2) = h2u((v.z - mu) * rstd * g.z + b.z,
                                     (v.w - mu) * rstd * g.w + b.w);
    }
}

// ---------------- fp16 mma.sync GEMM (BK=64, hoisted addresses) ----------------
// C[M,N] = Ah[M,K] @ WTh[N,K]^T + bias
// epi: 1 = +res -> fp32 out ; 2 = gelu -> fp16 ; 3 = -> fp16 ; 4 = *SCALE -> fp16
#define GROW  72                      // halves per smem row
#define GA_H  (128*GROW)              // 9216 halves per A (or B) block
#define GST_H (2*GA_H)                // 18432 halves per stage
#define GSM   (3*GST_H*2)             // 110592 bytes

__global__ void __launch_bounds__(256, 2) gemm_h(
    const __half* __restrict__ A, const __half* __restrict__ Bw,
    const float* __restrict__ bias, const float* __restrict__ res,
    void* __restrict__ Cout, int M, int N, int K, int epi)
{
    extern __shared__ __half smh[];
    uint32_t usm = smem_u32(smh);
    int tid = threadIdx.x, lane = tid & 31, wid = tid >> 5;
    int gid = lane >> 2, tig = lane & 3;
    int wm = wid & 1, wn = wid >> 1;
    int m0 = blockIdx.y * 128, n0 = blockIdx.x * 128;

    // cp.async: 4 chunks each of A and B per thread per stage
    long     asrc[4], bsrc[4];
    uint32_t adst[4], bdst[4];
#pragma unroll
    for (int i = 0; i < 4; i++) {
        int idx = tid + i * 256;
        int r = idx >> 3, ch = idx & 7;
        asrc[i] = (long)(m0 + r) * K + ch * 8;
        bsrc[i] = (long)(n0 + r) * K + ch * 8;
        adst[i] = (r * GROW + ch * 8) * 2;
        bdst[i] = (GA_H + r * GROW + ch * 8) * 2;
    }
    // ldmatrix base addresses (stage 0)
    int l8    = lane & 7;
    int amrow = wm * 64 + ((lane >> 3) & 1) * 8 + l8;
    int akcol = (lane >> 4) * 8;
    int bnrow = wn * 32 + (lane >> 4) * 8 + l8;
    int bkcol = ((lane >> 3) & 1) * 8;
    uint32_t aB[4], bB[2];
#pragma unroll
    for (int mf = 0; mf < 4; mf++)
        aB[mf] = usm + ((amrow + mf * 16) * GROW + akcol) * 2;
#pragma unroll
    for (int np = 0; np < 2; np++)
        bB[np] = usm + ((GA_H + (bnrow + np * 16) * GROW + bkcol)) * 2;

    float acc[4][4][4];
#pragma unroll
    for (int i = 0; i < 4; i++)
#pragma unroll
        for (int j = 0; j < 4; j++)
#pragma unroll
            for (int r = 0; r < 4; r++) acc[i][j][r] = 0.f;

    const int NC = K / 64;

    auto issue = [&](int c, int s) {
        long kb = (long)c * 64;
        uint32_t so = usm + s * (GST_H * 2);
#pragma unroll
        for (int i = 0; i < 4; i++) cpa16(so + adst[i], A  + asrc[i] + kb);
#pragma unroll
        for (int i = 0; i < 4; i++) cpa16(so + bdst[i], Bw + bsrc[i] + kb);
        asm volatile("cp.async.commit_group;\n" ::: "memory");
    };

    issue(0, 0);
    if (NC > 1) issue(1, 1);

    for (int c = 0; c < NC; c++) {
        int s = c % 3;
        if (c + 1 < NC) asm volatile("cp.async.wait_group 1;\n" ::: "memory");
        else            asm volatile("cp.async.wait_group 0;\n" ::: "memory");
        __syncthreads();
        if (c + 2 < NC) issue(c + 2, (c + 2) % 3);   // stage consumed at iter c-1

        uint32_t so = s * (GST_H * 2);
#pragma unroll
        for (int ks = 0; ks < 4; ks++) {
            uint32_t a[4][4], b[2][4];
#pragma unroll
            for (int mf = 0; mf < 4; mf++) ldm_x4(a[mf], aB[mf] + so + ks * 32);
#pragma unroll
            for (int np = 0; np < 2; np++) ldm_x4(b[np], bB[np] + so + ks * 32);
#pragma unroll
            for (int mf = 0; mf < 4; mf++)
#pragma unroll
                for (int nf = 0; nf < 4; nf++)
                    mma_f16(acc[mf][nf], a[mf], &b[nf >> 1][(nf & 1) * 2]);
        }
    }

    // ---- epilogue ----
    int cbase = n0 + wn * 32 + 2 * tig;
    float2 bl[4];
#pragma unroll
    for (int nf = 0; nf < 4; nf++)
        bl[nf] = *(const float2*)(bias + cbase + nf * 8);

#pragma unroll
    for (int mf = 0; mf < 4; mf++) {
#pragma unroll
        for (int hh = 0; hh < 2; hh++) {
            long r = m0 + wm * 64 + mf * 16 + gid + hh * 8;
#pragma unroll
            for (int nf = 0; nf < 4; nf++) {
                int col = cbase + nf * 8;
                float v0 = acc[mf][nf][hh * 2 + 0] + bl[nf].x;
                float v1 = acc[mf][nf][hh * 2 + 1] + bl[nf].y;
                if (epi == 1) {
                    float2 rv = *(const float2*)(res + r * (long)N + col);
                    *(float2*)((float*)Cout + r * (long)N + col) =
                        make_float2(v0 + rv.x, v1 + rv.y);
                } else {
                    if (epi == 2) {
                        v0 = 0.5f * v0 * (1.f + erff(v0 * 0.70710678118654752f));
                        v1 = 0.5f * v1 * (1.f + erff(v1 * 0.70710678118654752f));
                    } else if (epi == 4) {
                        v0 *= ATTN_SCALE; v1 *= ATTN_SCALE;
                    }
                    *(uint32_t*)((__half*)Cout + r * (long)N + col) = h2u(v0, v1);
                }
            }
        }
    }
}

// ---------------- fp16 tensor-core flash attention (ldmatrix) ----------------
#define AQH   (128*72)
#define AKH   (64*72)
#define ASMEM ((AQH + 4*AKH) * 2)      // 55296 B
#define ANC   (NKV / 64)

__global__ void __launch_bounds__(256, 2) attn_h(
    const __half* __restrict__ Q, const __half* __restrict__ KV,
    __half* __restrict__ O)
{
    extern __shared__ __half smh[];
    __half* qs = smh;                  // [128][72]
    __half* ks = smh + AQH;            // [2][64][72]
    __half* vs = ks + 2 * AKH;         // [2][64][72]
    int tid = threadIdx.x, lane = tid & 31, wid = tid >> 5;
    int gid = lane >> 2, tig = lane & 3;
    int qb = blockIdx.x, h = blockIdx.y, b = blockIdx.z;

    const __half* Qb = Q  + ((long)b * NQ + qb * 128) * HDIM + h * 64;
    const __half* Kb = KV + (long)b * NKV * KVS + h * 64;
    const __half* Vb = Kb + HDIM;

    int l8    = lane & 7;
    int qrow  = wid * 16 + ((lane >> 3) & 1) * 8 + l8;
    int qcol  = (lane >> 4) * 8;
    int krow  = (lane >> 4) * 8 + l8;
    int kcol  = ((lane >> 3) & 1) * 8;
    int vrow  = ((lane >> 3) & 1) * 8 + l8;
    int vcol  = (lane >> 4) * 8;

    auto load_kv = [&](int c, int buf) {
        __half* kd = ks + buf * AKH;
        __half* vd = vs + buf * AKH;
        long j0 = (long)c * 64;
#pragma unroll
        for (int i = 0; i < 2; i++) {
            int idx = tid + i * 256;
            int r = idx >> 3, c8 = (idx & 7) * 8;
            cpa16(smem_u32(kd + r * 72 + c8), Kb + (j0 + r) * KVS + c8);
            cpa16(smem_u32(vd + r * 72 + c8), Vb + (j0 + r) * KVS + c8);
        }
        asm volatile("cp.async.commit_group;\n" ::: "memory");
    };

#pragma unroll
    for (int i = 0; i < 4; i++) {
        int idx = tid + i * 256;
        int r = idx >> 3, c8 = (idx & 7) * 8;
        cpa16(smem_u32(qs + r * 72 + c8), Qb + (long)r * HDIM + c8);
    }
    load_kv(0, 0);

    float o[8][4];
#pragma unroll
    for (int nf = 0; nf < 8; nf++)
#pragma unroll
        for (int e = 0; e < 4; e++) o[nf][e] = 0.f;
    float m0 = -1e30f, m1 = -1e30f, l0 = 0.f, l1 = 0.f;

    uint32_t qa[4][4];

    for (int c = 0; c < ANC; c++) {
        if (c + 1 < ANC) {
            load_kv(c + 1, (c + 1) & 1);
            asm volatile("cp.async.wait_group 1;\n" ::: "memory");
        } else {
            asm volatile("cp.async.wait_group 0;\n" ::: "memory");
        }
        __syncthreads();

        if (c == 0) {
#pragma unroll
            for (int kf = 0; kf < 4; kf++)
                ldm_x4(qa[kf], smem_u32(qs + qrow * 72 + kf * 16 + qcol));
        }

        const __half* kcur = ks + (c & 1) * AKH;
        const __half* vcur = vs + (c & 1) * AKH;

        float sc[8][4];
#pragma unroll
        for (int nf = 0; nf < 8; nf++)
#pragma unroll
            for (int e = 0; e < 4; e++) sc[nf][e] = 0.f;
#pragma unroll
        for (int kf = 0; kf < 4; kf++) {
            uint32_t kb4[4][4];
#pragma unroll
            for (int np = 0; np < 4; np++)
                ldm_x4(kb4[np], smem_u32(kcur + (krow + np * 16) * 72 + kf * 16 + kcol));
#pragma unroll
            for (int np = 0; np < 4; np++) {
                mma_f16(sc[2 * np],     qa[kf], &kb4[np][0]);
                mma_f16(sc[2 * np + 1], qa[kf], &kb4[np][2]);
            }
        }

        float tm0 = -1e30f, tm1 = -1e30f;
#pragma unroll
        for (int nf = 0; nf < 8; nf++) {
            tm0 = fmaxf(tm0, fmaxf(sc[nf][0], sc[nf][1]));
            tm1 = fmaxf(tm1, fmaxf(sc[nf][2], sc[nf][3]));
        }
        tm0 = fmaxf(tm0, __shfl_xor_sync(0xffffffffu, tm0, 1));
        tm0 = fmaxf(tm0, __shfl_xor_sync(0xffffffffu, tm0, 2));
        tm1 = fmaxf(tm1, __shfl_xor_sync(0xffffffffu, tm1, 1));
        tm1 = fmaxf(tm1, __shfl_xor_sync(0xffffffffu, tm1, 2));
        float nm0 = fmaxf(m0, tm0), nm1 = fmaxf(m1, tm1);
        float corr0 = fexp(m0 - nm0), corr1 = fexp(m1 - nm1);
        m0 = nm0; m1 = nm1;

        uint32_t ph[4][4];
        float ps0 = 0.f, ps1 = 0.f;
#pragma unroll
        for (int u = 0; u < 4; u++) {
            float p00 = fexp(sc[2*u][0] - nm0),   p01 = fexp(sc[2*u][1] - nm0);
            float p02 = fexp(sc[2*u][2] - nm1),   p03 = fexp(sc[2*u][3] - nm1);
            float p10 = fexp(sc[2*u+1][0] - nm0), p11 = fexp(sc[2*u+1][1] - nm0);
            float p12 = fexp(sc[2*u+1][2] - nm1), p13 = fexp(sc[2*u+1][3] - nm1);
            __half2 h0 = __floats2half2_rn(p00, p01);
            __half2 h1 = __floats2half2_rn(p02, p03);
            __half2 h2 = __floats2half2_rn(p10, p11);
            __half2 h3 = __floats2half2_rn(p12, p13);
            ph[u][0] = *(uint32_t*)&h0; ph[u][1] = *(uint32_t*)&h1;
            ph[u][2] = *(uint32_t*)&h2; ph[u][3] = *(uint32_t*)&h3;
            float2 f0 = __half22float2(h0), f1 = __half22float2(h1);
            float2 f2 = __half22float2(h2), f3 = __half22float2(h3);
            ps0 += f0.x + f0.y + f2.x + f2.y;
            ps1 += f1.x + f1.y + f3.x + f3.y;
        }
        ps0 += __shfl_xor_sync(0xffffffffu, ps0, 1);
        ps0 += __shfl_xor_sync(0xffffffffu, ps0, 2);
        ps1 += __shfl_xor_sync(0xffffffffu, ps1, 1);
        ps1 += __shfl_xor_sync(0xffffffffu, ps1, 2);
        l0 = l0 * corr0 + ps0;
        l1 = l1 * corr1 + ps1;
#pragma unroll
        for (int nf = 0; nf < 8; nf++) {
            o[nf][0] *= corr0; o[nf][1] *= corr0;
            o[nf][2] *= corr1; o[nf][3] *= corr1;
        }

#pragma unroll
        for (int u = 0; u < 4; u++) {
#pragma unroll
            for (int np = 0; np < 4; np++) {
                uint32_t vb[4];
                ldm_x4_t(vb, smem_u32(vcur + (u * 16 + vrow) * 72 + np * 16 + vcol));
                mma_f16(o[2 * np],     ph[u], &vb[0]);
                mma_f16(o[2 * np + 1], ph[u], &vb[2]);
            }
        }
        __syncthreads();
    }

    float inv0 = 1.f / l0, inv1 = 1.f / l1;
    long r0 = (long)b * NQ + qb * 128 + wid * 16 + gid;
    long r1 = r0 + 8;
#pragma unroll
    for (int nf = 0; nf < 8; nf++) {
        int col = h * 64 + nf * 8 + 2 * tig;
        *(uint32_t*)(O + r0 * HDIM + col) = h2u(o[nf][0] * inv0, o[nf][1] * inv0);
        *(uint32_t*)(O + r1 * HDIM + col) = h2u(o[nf][2] * inv1, o[nf][3] * inv1);
    }
}

// ---------------- launcher ----------------
extern "C" void kernel_launch(void* const* d_in, const int* in_sizes, int n_in,
                              void* d_out, int out_size)
{
    const float* hid = (const float*)d_in[0];
    const float* x   = (const float*)d_in[1];
    const float* Wq  = (const float*)d_in[2];
    const float* bq  = (const float*)d_in[3];
    const float* Wk  = (const float*)d_in[4];
    const float* bk  = (const float*)d_in[5];
    const float* Wv  = (const float*)d_in[6];
    const float* bv  = (const float*)d_in[7];
    const float* Wo  = (const float*)d_in[8];
    const float* bo  = (const float*)d_in[9];
    const float* W1  = (const float*)d_in[10];
    const float* b1  = (const float*)d_in[11];
    const float* W2  = (const float*)d_in[12];
    const float* b2  = (const float*)d_in[13];
    const float* gi  = (const float*)d_in[14];
    const float* bi  = (const float*)d_in[15];
    const float* gh  = (const float*)d_in[16];
    const float* bh  = (const float*)d_in[17];
    const float* gf  = (const float*)d_in[18];
    const float* bf  = (const float*)d_in[19];

    __half *xn, *hn, *q, *kv, *ctx, *hnf, *ff;
    __half *wq, *wkv, *wo, *w1, *w2;
    float *o1, *bkv;
    cudaGetSymbolAddress((void**)&xn,  g_xn);
    cudaGetSymbolAddress((void**)&hn,  g_hn);
    cudaGetSymbolAddress((void**)&q,   g_q);
    cudaGetSymbolAddress((void**)&kv,  g_kv);
    cudaGetSymbolAddress((void**)&ctx, g_ctx);
    cudaGetSymbolAddress((void**)&o1,  g_o1);
    cudaGetSymbolAddress((void**)&hnf, g_hnf);
    cudaGetSymbolAddress((void**)&ff,  g_ff);
    cudaGetSymbolAddress((void**)&wq,  g_wq);
    cudaGetSymbolAddress((void**)&wkv, g_wkv);
    cudaGetSymbolAddress((void**)&wo,  g_wo);
    cudaGetSymbolAddress((void**)&w1,  g_w1);
    cudaGetSymbolAddress((void**)&w2,  g_w2);
    cudaGetSymbolAddress((void**)&bkv, g_bkv);

    cudaFuncSetAttribute(attn_h, cudaFuncAttributeMaxDynamicSharedMemorySize, ASMEM);
    cudaFuncSetAttribute(gemm_h, cudaFuncAttributeMaxDynamicSharedMemorySize, GSM);

    // order: launch #5 = fused KV-projection GEMM (profiled by ncu -s 5 -c 1)
    wprep<<<dim3(HDIM / 32, IMGD / 32), 256>>>(Wk, wkv, IMGD, HDIM);                 // 0
    wprep<<<dim3(HDIM / 32, IMGD / 32), 256>>>(Wv, wkv + (long)HDIM * IMGD,          // 1
                                               IMGD, HDIM);
    bcat2<<<KVS / 256, 256>>>(bk, bv, bkv);                                          // 2
    ln_kernel<<<BB * NKV, 256>>>(x, gi, bi, xn, IMGD);                               // 3
    wprep<<<dim3(HDIM / 32, HDIM / 32), 256>>>(Wq, wq, HDIM, HDIM);                  // 4
    gemm_h<<<dim3(KVS / 128, BB * NKV / 128), 256, GSM>>>(xn, wkv, bkv, nullptr,     // 5
                                                          kv, BB * NKV, KVS, IMGD, 3);
    ln_kernel<<<BB * NQ, 256>>>(hid, gh, bh, hn, HDIM);                              // 6
    gemm_h<<<dim3(HDIM / 128, BB * NQ / 128), 256, GSM>>>(hn, wq, bq, nullptr, q,    // 7
                                                          BB * NQ, HDIM, HDIM, 4);
    wprep<<<dim3(HDIM / 32,  HDIM / 32),  256>>>(Wo, wo, HDIM, HDIM);
    wprep<<<dim3(INTER / 32, HDIM / 32),  256>>>(W1, w1, HDIM, INTER);
    wprep<<<dim3(HDIM / 32,  INTER / 32), 256>>>(W2, w2, INTER, HDIM);

    attn_h<<<dim3(NQ / 128, HEADS, BB), 256, ASMEM>>>(q, kv, ctx);

    gemm_h<<<dim3(HDIM / 128, BB * NQ / 128), 256, GSM>>>(ctx, wo, bo, hid, o1,
                                                          BB * NQ, HDIM, HDIM, 1);

    ln_kernel<<<BB * NQ, 256>>>(o1, gf, bf, hnf, HDIM);
    gemm_h<<<dim3(INTER / 128, BB * NQ / 128), 256, GSM>>>(hnf, w1, b1, nullptr, ff,
                                                           BB * NQ, INTER, HDIM, 2);
    gemm_h<<<dim3(HDIM / 128,  BB * NQ / 128), 256, GSM>>>(ff, w2, b2, o1, d_out,
                                                           BB * NQ, HDIM, INTER, 1);
}

// round 12
// speedup vs baseline: 3.1330x; 1.0604x over previous
#include <cuda_runtime.h>
#include <cuda_fp16.h>
#include <cstdint>
#include <math.h>

#define BB    16
#define NQ    256
#define NKV   2304
#define HDIM  768
#define IMGD  1024
#define HEADS 12
#define INTER 3072
#define KVS   1536            // fused K|V row stride
#define ATTN_SCALE 0.125f

// ---------------- scratch (static __device__, allocation-free) ----------------
__device__ __half g_xn [BB*NKV*IMGD];
__device__ __half g_hn [BB*NQ*HDIM];
__device__ __half g_q  [BB*NQ*HDIM];
__device__ __half g_kv [BB*NKV*KVS];          // fused K|V
__device__ __half g_ctx[BB*NQ*HDIM];
__device__ float  g_o1 [BB*NQ*HDIM];
__device__ __half g_hnf[BB*NQ*HDIM];
__device__ __half g_ff [BB*NQ*INTER];
// transposed fp16 weights [N,K]
__device__ __half g_wq [HDIM*HDIM];
__device__ __half g_wkv[KVS*IMGD];
__device__ __half g_wo [HDIM*HDIM];
__device__ __half g_w1 [INTER*HDIM];
__device__ __half g_w2 [HDIM*INTER];
__device__ float  g_bkv[KVS];

// ---------------- helpers ----------------
__device__ __forceinline__ uint32_t smem_u32(const void* p) {
    uint32_t a;
    asm("{ .reg .u64 t; cvta.to.shared.u64 t, %1; cvt.u32.u64 %0, t; }" : "=r"(a) : "l"(p));
    return a;
}
__device__ __forceinline__ void cpa16(uint32_t dst, const void* src) {
    asm volatile("cp.async.cg.shared.global [%0], [%1], 16;\n" :: "r"(dst), "l"(src));
}
__device__ __forceinline__ void mma_f16(float* c, const uint32_t* a, const uint32_t* b) {
    asm volatile(
        "mma.sync.aligned.m16n8k16.row.col.f32.f16.f16.f32 "
        "{%0,%1,%2,%3}, {%4,%5,%6,%7}, {%8,%9}, {%0,%1,%2,%3};\n"
        : "+f"(c[0]), "+f"(c[1]), "+f"(c[2]), "+f"(c[3])
        : "r"(a[0]), "r"(a[1]), "r"(a[2]), "r"(a[3]), "r"(b[0]), "r"(b[1]));
}
__device__ __forceinline__ void ldm_x4(uint32_t* r, uint32_t addr) {
    asm volatile("ldmatrix.sync.aligned.m8n8.x4.shared.b16 {%0,%1,%2,%3}, [%4];"
        : "=r"(r[0]), "=r"(r[1]), "=r"(r[2]), "=r"(r[3]) : "r"(addr));
}
__device__ __forceinline__ void ldm_x4_t(uint32_t* r, uint32_t addr) {
    asm volatile("ldmatrix.sync.aligned.m8n8.x4.trans.shared.b16 {%0,%1,%2,%3}, [%4];"
        : "=r"(r[0]), "=r"(r[1]), "=r"(r[2]), "=r"(r[3]) : "r"(addr));
}
__device__ __forceinline__ float fexp(float x) {
    float y = fmaxf(x * 1.44269504f, -120.f);
    float r = y + 12582912.f;
    float n = r - 12582912.f;
    float f = y - n;
    float p = 0.00133336f;
    p = fmaf(p, f, 0.00961804f);
    p = fmaf(p, f, 0.05550411f);
    p = fmaf(p, f, 0.24022651f);
    p = fmaf(p, f, 0.69314718f);
    p = fmaf(p, f, 1.0f);
    int ni = __float_as_int(r) - 0x4B400000;
    return p * __int_as_float((ni + 127) << 23);
}
__device__ __forceinline__ uint32_t h2u(float lo, float hi) {
    __half2 h = __floats2half2_rn(lo, hi);
    return *(uint32_t*)&h;
}

// common epilogue math
__device__ __forceinline__ void epi_store(float v0, float v1, int epi,
                                          const float* res, void* Cout,
                                          long r, long N, int col) {
    if (epi == 1) {
        float2 rv = *(const float2*)(res + r * N + col);
        *(float2*)((float*)Cout + r * N + col) = make_float2(v0 + rv.x, v1 + rv.y);
    } else {
        if (epi == 2) {
            v0 = 0.5f * v0 * (1.f + erff(v0 * 0.70710678118654752f));
            v1 = 0.5f * v1 * (1.f + erff(v1 * 0.70710678118654752f));
        } else if (epi == 4) {
            v0 *= ATTN_SCALE; v1 *= ATTN_SCALE;
        }
        *(uint32_t*)((__half*)Cout + r * N + col) = h2u(v0, v1);
    }
}

// ---------------- weight prep: transpose [K,N] -> [N,K] fp16 ----------------
__global__ void __launch_bounds__(256) wprep(const float* __restrict__ W,
                                             __half* __restrict__ WT, int K, int N) {
    __shared__ float t[32][33];
    int nb = blockIdx.x * 32, kb = blockIdx.y * 32;
    int tx = threadIdx.x & 31, ty = threadIdx.x >> 5;
#pragma unroll
    for (int i = 0; i < 32; i += 8)
        t[ty + i][tx] = W[(long)(kb + ty + i) * N + nb + tx];
    __syncthreads();
#pragma unroll
    for (int i = 0; i < 32; i += 8)
        WT[(long)(nb + ty + i) * K + kb + tx] = __float2half(t[tx][ty + i]);
}

__global__ void __launch_bounds__(256) bcat2(const float* __restrict__ a,
                                             const float* __restrict__ b,
                                             float* __restrict__ o) {
    int i = blockIdx.x * 256 + threadIdx.x;
    if (i < HDIM)          o[i] = a[i];
    else if (i < 2 * HDIM) o[i] = b[i - HDIM];
}

// ---------------- LayerNorm: 128 thr/row, 8 elems/thread -------------------
__global__ void __launch_bounds__(128) ln_kernel(
    const float* __restrict__ in, const float* __restrict__ gam,
    const float* __restrict__ bet, __half* __restrict__ out, int D)
{
    __shared__ float rs[4], rq[4];
    long row = blockIdx.x;
    int tid = threadIdx.x, lane = tid & 31, wid = tid >> 5;
    int i8 = tid * 8;
    float4 v0 = make_float4(0.f, 0.f, 0.f, 0.f);
    float4 v1 = make_float4(0.f, 0.f, 0.f, 0.f);
    if (i8 < D) {
        v0 = *(const float4*)(in + row * (long)D + i8);
        v1 = *(const float4*)(in + row * (long)D + i8 + 4);
    }
    float s  = v0.x + v0.y + v0.z + v0.w + v1.x + v1.y + v1.z + v1.w;
    float s2 = v0.x*v0.x + v0.y*v0.y + v0.z*v0.z + v0.w*v0.w
             + v1.x*v1.x + v1.y*v1.y + v1.z*v1.z + v1.w*v1.w;
#pragma unroll
    for (int m = 16; m; m >>= 1) {
        s  += __shfl_xor_sync(0xffffffffu, s,  m);
        s2 += __shfl_xor_sync(0xffffffffu, s2, m);
    }
    if (lane == 0) { rs[wid] = s; rq[wid] = s2; }
    __syncthreads();
    s  = rs[0] + rs[1] + rs[2] + rs[3];
    s2 = rq[0] + rq[1] + rq[2] + rq[3];
    float mu   = s / (float)D;
    float var  = fmaxf(s2 / (float)D - mu * mu, 0.f);
    float rstd = rsqrtf(var + 1e-5f);
    if (i8 < D) {
        float4 g0 = *(const float4*)(gam + i8);
        float4 g1 = *(const float4*)(gam + i8 + 4);
        float4 b0 = *(const float4*)(bet + i8);
        float4 b1 = *(const float4*)(bet + i8 + 4);
        __half* orow = out + row * (long)D + i8;
        *(uint32_t*)(orow)     = h2u((v0.x - mu) * rstd * g0.x + b0.x,
                                     (v0.y - mu) * rstd * g0.y + b0.y);
        *(uint32_t*)(orow + 2) = h2u((v0.z - mu) * rstd * g0.z + b0.z,
                                     (v0.w - mu) * rstd * g0.w + b0.w);
        *(uint32_t*)(orow + 4) = h2u((v1.x - mu) * rstd * g1.x + b1.x,
                                     (v1.y - mu) * rstd * g1.y + b1.y);
        *(uint32_t*)(orow + 6) = h2u((v1.z - mu) * rstd * g1.z + b1.z,
                                     (v1.w - mu) * rstd * g1.w + b1.w);
    }
}

// ---------------- fp16 mma.sync GEMM 128x128 (BK=64) ----------------
#define GROW  72
#define GA_H  (128*GROW)
#define GST_H (2*GA_H)
#define GSM   (3*GST_H*2)

__global__ void __launch_bounds__(256, 2) gemm_h(
    const __half* __restrict__ A, const __half* __restrict__ Bw,
    const float* __restrict__ bias, const float* __restrict__ res,
    void* __restrict__ Cout, int M, int N, int K, int epi)
{
    extern __shared__ __half smh[];
    uint32_t usm = smem_u32(smh);
    int tid = threadIdx.x, lane = tid & 31, wid = tid >> 5;
    int gid = lane >> 2, tig = lane & 3;
    int wm = wid & 1, wn = wid >> 1;
    int m0 = blockIdx.y * 128, n0 = blockIdx.x * 128;

    long     asrc[4], bsrc[4];
    uint32_t adst[4], bdst[4];
#pragma unroll
    for (int i = 0; i < 4; i++) {
        int idx = tid + i * 256;
        int r = idx >> 3, ch = idx & 7;
        asrc[i] = (long)(m0 + r) * K + ch * 8;
        bsrc[i] = (long)(n0 + r) * K + ch * 8;
        adst[i] = (r * GROW + ch * 8) * 2;
        bdst[i] = (GA_H + r * GROW + ch * 8) * 2;
    }
    int l8    = lane & 7;
    int amrow = wm * 64 + ((lane >> 3) & 1) * 8 + l8;
    int akcol = (lane >> 4) * 8;
    int bnrow = wn * 32 + (lane >> 4) * 8 + l8;
    int bkcol = ((lane >> 3) & 1) * 8;
    uint32_t aB[4], bB[2];
#pragma unroll
    for (int mf = 0; mf < 4; mf++)
        aB[mf] = usm + ((amrow + mf * 16) * GROW + akcol) * 2;
#pragma unroll
    for (int np = 0; np < 2; np++)
        bB[np] = usm + ((GA_H + (bnrow + np * 16) * GROW + bkcol)) * 2;

    float acc[4][4][4];
#pragma unroll
    for (int i = 0; i < 4; i++)
#pragma unroll
        for (int j = 0; j < 4; j++)
#pragma unroll
            for (int r = 0; r < 4; r++) acc[i][j][r] = 0.f;

    const int NC = K / 64;

    auto issue = [&](int c, int s) {
        long kb = (long)c * 64;
        uint32_t so = usm + s * (GST_H * 2);
#pragma unroll
        for (int i = 0; i < 4; i++) cpa16(so + adst[i], A  + asrc[i] + kb);
#pragma unroll
        for (int i = 0; i < 4; i++) cpa16(so + bdst[i], Bw + bsrc[i] + kb);
        asm volatile("cp.async.commit_group;\n" ::: "memory");
    };

    issue(0, 0);
    if (NC > 1) issue(1, 1);

    for (int c = 0; c < NC; c++) {
        int s = c % 3;
        if (c + 1 < NC) asm volatile("cp.async.wait_group 1;\n" ::: "memory");
        else            asm volatile("cp.async.wait_group 0;\n" ::: "memory");
        __syncthreads();
        if (c + 2 < NC) issue(c + 2, (c + 2) % 3);

        uint32_t so = s * (GST_H * 2);
#pragma unroll
        for (int ks = 0; ks < 4; ks++) {
            uint32_t a[4][4], b[2][4];
#pragma unroll
            for (int mf = 0; mf < 4; mf++) ldm_x4(a[mf], aB[mf] + so + ks * 32);
#pragma unroll
            for (int np = 0; np < 2; np++) ldm_x4(b[np], bB[np] + so + ks * 32);
#pragma unroll
            for (int mf = 0; mf < 4; mf++)
#pragma unroll
                for (int nf = 0; nf < 4; nf++)
                    mma_f16(acc[mf][nf], a[mf], &b[nf >> 1][(nf & 1) * 2]);
        }
    }

    int cbase = n0 + wn * 32 + 2 * tig;
    float2 bl[4];
#pragma unroll
    for (int nf = 0; nf < 4; nf++)
        bl[nf] = *(const float2*)(bias + cbase + nf * 8);

#pragma unroll
    for (int mf = 0; mf < 4; mf++)
#pragma unroll
        for (int hh = 0; hh < 2; hh++) {
            long r = m0 + wm * 64 + mf * 16 + gid + hh * 8;
#pragma unroll
            for (int nf = 0; nf < 4; nf++)
                epi_store(acc[mf][nf][hh * 2] + bl[nf].x,
                          acc[mf][nf][hh * 2 + 1] + bl[nf].y,
                          epi, res, Cout, r, N, cbase + nf * 8);
        }
}

// ---------------- fp16 mma.sync GEMM 64x128 (occ 4 — wave-balanced) ---------
#define W6ROW  72
#define W6A_H  (64*W6ROW)                 // 4608 halves
#define W6ST_H (W6A_H + 128*W6ROW)        // 13824 halves
#define W6SM   (2*W6ST_H*2)               // 55296 B

__global__ void __launch_bounds__(128, 4) gemm64(
    const __half* __restrict__ A, const __half* __restrict__ Bw,
    const float* __restrict__ bias, const float* __restrict__ res,
    void* __restrict__ Cout, int M, int N, int K, int epi)
{
    extern __shared__ __half smh[];
    uint32_t usm = smem_u32(smh);
    int tid = threadIdx.x, lane = tid & 31, wn = tid >> 5;
    int gid = lane >> 2, tig = lane & 3;
    int m0 = blockIdx.y * 64, n0 = blockIdx.x * 128;

    // base chunks; siblings derived by +i*16 rows
    int r0 = tid >> 3, ch = tid & 7;
    long     asrc0 = (long)(m0 + r0) * K + ch * 8;
    long     bsrc0 = (long)(n0 + r0) * K + ch * 8;
    uint32_t adst0 = (r0 * W6ROW + ch * 8) * 2;
    uint32_t bdst0 = (W6A_H + r0 * W6ROW + ch * 8) * 2;
    long kstep16 = (long)16 * K;

    int l8    = lane & 7;
    int amrow = ((lane >> 3) & 1) * 8 + l8;
    int akcol = (lane >> 4) * 8;
    int bnrow = wn * 32 + (lane >> 4) * 8 + l8;
    int bkcol = ((lane >> 3) & 1) * 8;
    uint32_t aB[4], bB[2];
#pragma unroll
    for (int mf = 0; mf < 4; mf++)
        aB[mf] = usm + ((amrow + mf * 16) * W6ROW + akcol) * 2;
#pragma unroll
    for (int np = 0; np < 2; np++)
        bB[np] = usm + ((W6A_H + (bnrow + np * 16) * W6ROW + bkcol)) * 2;

    float acc[4][4][4];
#pragma unroll
    for (int i = 0; i < 4; i++)
#pragma unroll
        for (int j = 0; j < 4; j++)
#pragma unroll
            for (int r = 0; r < 4; r++) acc[i][j][r] = 0.f;

    const int NC = K / 64;

    auto issue = [&](int c, int s) {
        long kb = (long)c * 64;
        uint32_t so = usm + s * W6ST_H * 2;
#pragma unroll
        for (int i = 0; i < 4; i++)
            cpa16(so + adst0 + i * (16 * W6ROW * 2), A + asrc0 + i * kstep16 + kb);
#pragma unroll
        for (int i = 0; i < 8; i++)
            cpa16(so + bdst0 + i * (16 * W6ROW * 2), Bw + bsrc0 + i * kstep16 + kb);
        asm volatile("cp.async.commit_group;\n" ::: "memory");
    };

    issue(0, 0);

    for (int c = 0; c < NC; c++) {
        if (c + 1 < NC) {
            issue(c + 1, (c + 1) & 1);
            asm volatile("cp.async.wait_group 1;\n" ::: "memory");
        } else {
            asm volatile("cp.async.wait_group 0;\n" ::: "memory");
        }
        __syncthreads();

        uint32_t so = (c & 1) * (W6ST_H * 2);
#pragma unroll
        for (int ks = 0; ks < 4; ks++) {
            uint32_t a[4][4], b[2][4];
#pragma unroll
            for (int mf = 0; mf < 4; mf++) ldm_x4(a[mf], aB[mf] + so + ks * 32);
#pragma unroll
            for (int np = 0; np < 2; np++) ldm_x4(b[np], bB[np] + so + ks * 32);
#pragma unroll
            for (int mf = 0; mf < 4; mf++)
#pragma unroll
                for (int nf = 0; nf < 4; nf++)
                    mma_f16(acc[mf][nf], a[mf], &b[nf >> 1][(nf & 1) * 2]);
        }
        __syncthreads();          // stage reusable before next issue
    }

    int cbase = n0 + wn * 32 + 2 * tig;
    float2 bl[4];
#pragma unroll
    for (int nf = 0; nf < 4; nf++)
        bl[nf] = *(const float2*)(bias + cbase + nf * 8);

#pragma unroll
    for (int mf = 0; mf < 4; mf++)
#pragma unroll
        for (int hh = 0; hh < 2; hh++) {
            long r = m0 + mf * 16 + gid + hh * 8;
#pragma unroll
            for (int nf = 0; nf < 4; nf++)
                epi_store(acc[mf][nf][hh * 2] + bl[nf].x,
                          acc[mf][nf][hh * 2 + 1] + bl[nf].y,
                          epi, res, Cout, r, N, cbase + nf * 8);
        }
}

// ---------------- fp16 tensor-core flash attention (ldmatrix) ----------------
#define AQH   (128*72)
#define AKH   (64*72)
#define ASMEM ((AQH + 4*AKH) * 2)
#define ANC   (NKV / 64)

__global__ void __launch_bounds__(256, 2) attn_h(
    const __half* __restrict__ Q, const __half* __restrict__ KV,
    __half* __restrict__ O)
{
    extern __shared__ __half smh[];
    __half* qs = smh;
    __half* ks = smh + AQH;
    __half* vs = ks + 2 * AKH;
    int tid = threadIdx.x, lane = tid & 31, wid = tid >> 5;
    int gid = lane >> 2, tig = lane & 3;
    int qb = blockIdx.x, h = blockIdx.y, b = blockIdx.z;

    const __half* Qb = Q  + ((long)b * NQ + qb * 128) * HDIM + h * 64;
    const __half* Kb = KV + (long)b * NKV * KVS + h * 64;
    const __half* Vb = Kb + HDIM;

    int l8    = lane & 7;
    int qrow  = wid * 16 + ((lane >> 3) & 1) * 8 + l8;
    int qcol  = (lane >> 4) * 8;
    int krow  = (lane >> 4) * 8 + l8;
    int kcol  = ((lane >> 3) & 1) * 8;
    int vrow  = ((lane >> 3) & 1) * 8 + l8;
    int vcol  = (lane >> 4) * 8;

    auto load_kv = [&](int c, int buf) {
        __half* kd = ks + buf * AKH;
        __half* vd = vs + buf * AKH;
        long j0 = (long)c * 64;
#pragma unroll
        for (int i = 0; i < 2; i++) {
            int idx = tid + i * 256;
            int r = idx >> 3, c8 = (idx & 7) * 8;
            cpa16(smem_u32(kd + r * 72 + c8), Kb + (j0 + r) * KVS + c8);
            cpa16(smem_u32(vd + r * 72 + c8), Vb + (j0 + r) * KVS + c8);
        }
        asm volatile("cp.async.commit_group;\n" ::: "memory");
    };

#pragma unroll
    for (int i = 0; i < 4; i++) {
        int idx = tid + i * 256;
        int r = idx >> 3, c8 = (idx & 7) * 8;
        cpa16(smem_u32(qs + r * 72 + c8), Qb + (long)r * HDIM + c8);
    }
    load_kv(0, 0);

    float o[8][4];
#pragma unroll
    for (int nf = 0; nf < 8; nf++)
#pragma unroll
        for (int e = 0; e < 4; e++) o[nf][e] = 0.f;
    float m0 = -1e30f, m1 = -1e30f, l0 = 0.f, l1 = 0.f;

    uint32_t qa[4][4];

    for (int c = 0; c < ANC; c++) {
        if (c + 1 < ANC) {
            load_kv(c + 1, (c + 1) & 1);
            asm volatile("cp.async.wait_group 1;\n" ::: "memory");
        } else {
            asm volatile("cp.async.wait_group 0;\n" ::: "memory");
        }
        __syncthreads();

        if (c == 0) {
#pragma unroll
            for (int kf = 0; kf < 4; kf++)
                ldm_x4(qa[kf], smem_u32(qs + qrow * 72 + kf * 16 + qcol));
        }

        const __half* kcur = ks + (c & 1) * AKH;
        const __half* vcur = vs + (c & 1) * AKH;

        float sc[8][4];
#pragma unroll
        for (int nf = 0; nf < 8; nf++)
#pragma unroll
            for (int e = 0; e < 4; e++) sc[nf][e] = 0.f;
#pragma unroll
        for (int kf = 0; kf < 4; kf++) {
            uint32_t kb4[4][4];
#pragma unroll
            for (int np = 0; np < 4; np++)
                ldm_x4(kb4[np], smem_u32(kcur + (krow + np * 16) * 72 + kf * 16 + kcol));
#pragma unroll
            for (int np = 0; np < 4; np++) {
                mma_f16(sc[2 * np],     qa[kf], &kb4[np][0]);
                mma_f16(sc[2 * np + 1], qa[kf], &kb4[np][2]);
            }
        }

        float tm0 = -1e30f, tm1 = -1e30f;
#pragma unroll
        for (int nf = 0; nf < 8; nf++) {
            tm0 = fmaxf(tm0, fmaxf(sc[nf][0], sc[nf][1]));
            tm1 = fmaxf(tm1, fmaxf(sc[nf][2], sc[nf][3]));
        }
        tm0 = fmaxf(tm0, __shfl_xor_sync(0xffffffffu, tm0, 1));
        tm0 = fmaxf(tm0, __shfl_xor_sync(0xffffffffu, tm0, 2));
        tm1 = fmaxf(tm1, __shfl_xor_sync(0xffffffffu, tm1, 1));
        tm1 = fmaxf(tm1, __shfl_xor_sync(0xffffffffu, tm1, 2));
        float nm0 = fmaxf(m0, tm0), nm1 = fmaxf(m1, tm1);
        float corr0 = fexp(m0 - nm0), corr1 = fexp(m1 - nm1);
        m0 = nm0; m1 = nm1;

        uint32_t ph[4][4];
        float ps0 = 0.f, ps1 = 0.f;
#pragma unroll
        for (int u = 0; u < 4; u++) {
            float p00 = fexp(sc[2*u][0] - nm0),   p01 = fexp(sc[2*u][1] - nm0);
            float p02 = fexp(sc[2*u][2] - nm1),   p03 = fexp(sc[2*u][3] - nm1);
            float p10 = fexp(sc[2*u+1][0] - nm0), p11 = fexp(sc[2*u+1][1] - nm0);
            float p12 = fexp(sc[2*u+1][2] - nm1), p13 = fexp(sc[2*u+1][3] - nm1);
            __half2 h0 = __floats2half2_rn(p00, p01);
            __half2 h1 = __floats2half2_rn(p02, p03);
            __half2 h2 = __floats2half2_rn(p10, p11);
            __half2 h3 = __floats2half2_rn(p12, p13);
            ph[u][0] = *(uint32_t*)&h0; ph[u][1] = *(uint32_t*)&h1;
            ph[u][2] = *(uint32_t*)&h2; ph[u][3] = *(uint32_t*)&h3;
            float2 f0 = __half22float2(h0), f1 = __half22float2(h1);
            float2 f2 = __half22float2(h2), f3 = __half22float2(h3);
            ps0 += f0.x + f0.y + f2.x + f2.y;
            ps1 += f1.x + f1.y + f3.x + f3.y;
        }
        ps0 += __shfl_xor_sync(0xffffffffu, ps0, 1);
        ps0 += __shfl_xor_sync(0xffffffffu, ps0, 2);
        ps1 += __shfl_xor_sync(0xffffffffu, ps1, 1);
        ps1 += __shfl_xor_sync(0xffffffffu, ps1, 2);
        l0 = l0 * corr0 + ps0;
        l1 = l1 * corr1 + ps1;
#pragma unroll
        for (int nf = 0; nf < 8; nf++) {
            o[nf][0] *= corr0; o[nf][1] *= corr0;
            o[nf][2] *= corr1; o[nf][3] *= corr1;
        }

#pragma unroll
        for (int u = 0; u < 4; u++) {
#pragma unroll
            for (int np = 0; np < 4; np++) {
                uint32_t vb[4];
                ldm_x4_t(vb, smem_u32(vcur + (u * 16 + vrow) * 72 + np * 16 + vcol));
                mma_f16(o[2 * np],     ph[u], &vb[0]);
                mma_f16(o[2 * np + 1], ph[u], &vb[2]);
            }
        }
        __syncthreads();
    }

    float inv0 = 1.f / l0, inv1 = 1.f / l1;
    long r0 = (long)b * NQ + qb * 128 + wid * 16 + gid;
    long r1 = r0 + 8;
#pragma unroll
    for (int nf = 0; nf < 8; nf++) {
        int col = h * 64 + nf * 8 + 2 * tig;
        *(uint32_t*)(O + r0 * HDIM + col) = h2u(o[nf][0] * inv0, o[nf][1] * inv0);
        *(uint32_t*)(O + r1 * HDIM + col) = h2u(o[nf][2] * inv1, o[nf][3] * inv1);
    }
}

// ---------------- launcher ----------------
extern "C" void kernel_launch(void* const* d_in, const int* in_sizes, int n_in,
                              void* d_out, int out_size)
{
    const float* hid = (const float*)d_in[0];
    const float* x   = (const float*)d_in[1];
    const float* Wq  = (const float*)d_in[2];
    const float* bq  = (const float*)d_in[3];
    const float* Wk  = (const float*)d_in[4];
    const float* bk  = (const float*)d_in[5];
    const float* Wv  = (const float*)d_in[6];
    const float* bv  = (const float*)d_in[7];
    const float* Wo  = (const float*)d_in[8];
    const float* bo  = (const float*)d_in[9];
    const float* W1  = (const float*)d_in[10];
    const float* b1  = (const float*)d_in[11];
    const float* W2  = (const float*)d_in[12];
    const float* b2  = (const float*)d_in[13];
    const float* gi  = (const float*)d_in[14];
    const float* bi  = (const float*)d_in[15];
    const float* gh  = (const float*)d_in[16];
    const float* bh  = (const float*)d_in[17];
    const float* gf  = (const float*)d_in[18];
    const float* bf  = (const float*)d_in[19];

    __half *xn, *hn, *q, *kv, *ctx, *hnf, *ff;
    __half *wq, *wkv, *wo, *w1, *w2;
    float *o1, *bkv;
    cudaGetSymbolAddress((void**)&xn,  g_xn);
    cudaGetSymbolAddress((void**)&hn,  g_hn);
    cudaGetSymbolAddress((void**)&q,   g_q);
    cudaGetSymbolAddress((void**)&kv,  g_kv);
    cudaGetSymbolAddress((void**)&ctx, g_ctx);
    cudaGetSymbolAddress((void**)&o1,  g_o1);
    cudaGetSymbolAddress((void**)&hnf, g_hnf);
    cudaGetSymbolAddress((void**)&ff,  g_ff);
    cudaGetSymbolAddress((void**)&wq,  g_wq);
    cudaGetSymbolAddress((void**)&wkv, g_wkv);
    cudaGetSymbolAddress((void**)&wo,  g_wo);
    cudaGetSymbolAddress((void**)&w1,  g_w1);
    cudaGetSymbolAddress((void**)&w2,  g_w2);
    cudaGetSymbolAddress((void**)&bkv, g_bkv);

    cudaFuncSetAttribute(attn_h, cudaFuncAttributeMaxDynamicSharedMemorySize, ASMEM);
    cudaFuncSetAttribute(gemm_h, cudaFuncAttributeMaxDynamicSharedMemorySize, GSM);
    cudaFuncSetAttribute(gemm64, cudaFuncAttributeMaxDynamicSharedMemorySize, W6SM);

    wprep<<<dim3(HDIM / 32, IMGD / 32), 256>>>(Wk, wkv, IMGD, HDIM);                 // 0
    wprep<<<dim3(HDIM / 32, IMGD / 32), 256>>>(Wv, wkv + (long)HDIM * IMGD,          // 1
                                               IMGD, HDIM);
    bcat2<<<KVS / 256, 256>>>(bk, bv, bkv);                                          // 2
    ln_kernel<<<BB * NKV, 128>>>(x, gi, bi, xn, IMGD);                               // 3
    wprep<<<dim3(HDIM / 32, HDIM / 32), 256>>>(Wq, wq, HDIM, HDIM);                  // 4
    gemm_h<<<dim3(KVS / 128, BB * NKV / 128), 256, GSM>>>(xn, wkv, bkv, nullptr,     // 5
                                                          kv, BB * NKV, KVS, IMGD, 3);
    ln_kernel<<<BB * NQ, 128>>>(hid, gh, bh, hn, HDIM);                              // 6
    gemm64<<<dim3(HDIM / 128, BB * NQ / 64), 128, W6SM>>>(hn, wq, bq, nullptr, q,    // 7
                                                          BB * NQ, HDIM, HDIM, 4);
    wprep<<<dim3(HDIM / 32,  HDIM / 32),  256>>>(Wo, wo, HDIM, HDIM);
    wprep<<<dim3(INTER / 32, HDIM / 32),  256>>>(W1, w1, HDIM, INTER);
    wprep<<<dim3(HDIM / 32,  INTER / 32), 256>>>(W2, w2, INTER, HDIM);

    attn_h<<<dim3(NQ / 128, HEADS, BB), 256, ASMEM>>>(q, kv, ctx);

    gemm64<<<dim3(HDIM / 128, BB * NQ / 64), 128, W6SM>>>(ctx, wo, bo, hid, o1,
                                                          BB * NQ, HDIM, HDIM, 1);

    ln_kernel<<<BB * NQ, 128>>>(o1, gf, bf, hnf, HDIM);
    gemm_h<<<dim3(INTER / 128, BB * NQ / 128), 256, GSM>>>(hnf, w1, b1, nullptr, ff,
                                                           BB * NQ, INTER, HDIM, 2);
    gemm64<<<dim3(HDIM / 128,  BB * NQ / 64), 128, W6SM>>>(ff, w2, b2, o1, d_out,
                                                           BB * NQ, HDIM, INTER, 1);
}

// round 14
// speedup vs baseline: 3.1442x; 1.0036x over previous
#include <cuda_runtime.h>
#include <cuda_fp16.h>
#include <cstdint>
#include <math.h>

#define BB    16
#define NQ    256
#define NKV   2304
#define HDIM  768
#define IMGD  1024
#define HEADS 12
#define INTER 3072
#define KVS   1536
#define NSPL  3               // attention KV splits
#define ATTN_SCALE 0.125f

// ---------------- scratch (static __device__, allocation-free) ----------------
__device__ __half g_xn [BB*NKV*IMGD];
__device__ __half g_hn [BB*NQ*HDIM];
__device__ __half g_q  [BB*NQ*HDIM];
__device__ __half g_kv [BB*NKV*KVS];
__device__ __half g_ctx[BB*NQ*HDIM];
__device__ float  g_o1 [BB*NQ*HDIM];
__device__ __half g_hnf[BB*NQ*HDIM];
__device__ __half g_ff [BB*NQ*INTER];
__device__ float  g_po [(long)NSPL*BB*HEADS*NQ*64];   // split partial O
__device__ float  g_pml[(long)NSPL*BB*HEADS*NQ*2];    // split m,l
// transposed fp16 weights [N,K]
__device__ __half g_wq [HDIM*HDIM];
__device__ __half g_wkv[KVS*IMGD];
__device__ __half g_wo [HDIM*HDIM];
__device__ __half g_w1 [INTER*HDIM];
__device__ __half g_w2 [HDIM*INTER];
__device__ float  g_bkv[KVS];

// ---------------- helpers ----------------
__device__ __forceinline__ uint32_t smem_u32(const void* p) {
    uint32_t a;
    asm("{ .reg .u64 t; cvta.to.shared.u64 t, %1; cvt.u32.u64 %0, t; }" : "=r"(a) : "l"(p));
    return a;
}
__device__ __forceinline__ void cpa16(uint32_t dst, const void* src) {
    asm volatile("cp.async.cg.shared.global [%0], [%1], 16;\n" :: "r"(dst), "l"(src));
}
__device__ __forceinline__ void mma_f16(float* c, const uint32_t* a, const uint32_t* b) {
    asm volatile(
        "mma.sync.aligned.m16n8k16.row.col.f32.f16.f16.f32 "
        "{%0,%1,%2,%3}, {%4,%5,%6,%7}, {%8,%9}, {%0,%1,%2,%3};\n"
        : "+f"(c[0]), "+f"(c[1]), "+f"(c[2]), "+f"(c[3])
        : "r"(a[0]), "r"(a[1]), "r"(a[2]), "r"(a[3]), "r"(b[0]), "r"(b[1]));
}
__device__ __forceinline__ void ldm_x4(uint32_t* r, uint32_t addr) {
    asm volatile("ldmatrix.sync.aligned.m8n8.x4.shared.b16 {%0,%1,%2,%3}, [%4];"
        : "=r"(r[0]), "=r"(r[1]), "=r"(r[2]), "=r"(r[3]) : "r"(addr));
}
__device__ __forceinline__ void ldm_x4_t(uint32_t* r, uint32_t addr) {
    asm volatile("ldmatrix.sync.aligned.m8n8.x4.trans.shared.b16 {%0,%1,%2,%3}, [%4];"
        : "=r"(r[0]), "=r"(r[1]), "=r"(r[2]), "=r"(r[3]) : "r"(addr));
}
__device__ __forceinline__ float fexp(float x) {
    float y = fmaxf(x * 1.44269504f, -120.f);
    float r = y + 12582912.f;
    float n = r - 12582912.f;
    float f = y - n;
    float p = 0.00133336f;
    p = fmaf(p, f, 0.00961804f);
    p = fmaf(p, f, 0.05550411f);
    p = fmaf(p, f, 0.24022651f);
    p = fmaf(p, f, 0.69314718f);
    p = fmaf(p, f, 1.0f);
    int ni = __float_as_int(r) - 0x4B400000;
    return p * __int_as_float((ni + 127) << 23);
}
__device__ __forceinline__ uint32_t h2u(float lo, float hi) {
    __half2 h = __floats2half2_rn(lo, hi);
    return *(uint32_t*)&h;
}

__device__ __forceinline__ void epi_store(float v0, float v1, int epi,
                                          const float* res, void* Cout,
                                          long r, long N, int col) {
    if (epi == 1) {
        float2 rv = *(const float2*)(res + r * N + col);
        *(float2*)((float*)Cout + r * N + col) = make_float2(v0 + rv.x, v1 + rv.y);
    } else {
        if (epi == 2) {
            v0 = 0.5f * v0 * (1.f + erff(v0 * 0.70710678118654752f));
            v1 = 0.5f * v1 * (1.f + erff(v1 * 0.70710678118654752f));
        } else if (epi == 4) {
            v0 *= ATTN_SCALE; v1 *= ATTN_SCALE;
        }
        *(uint32_t*)((__half*)Cout + r * N + col) = h2u(v0, v1);
    }
}

// ---------------- weight prep ----------------
__global__ void __launch_bounds__(256) wprep(const float* __restrict__ W,
                                             __half* __restrict__ WT, int K, int N) {
    __shared__ float t[32][33];
    int nb = blockIdx.x * 32, kb = blockIdx.y * 32;
    int tx = threadIdx.x & 31, ty = threadIdx.x >> 5;
#pragma unroll
    for (int i = 0; i < 32; i += 8)
        t[ty + i][tx] = W[(long)(kb + ty + i) * N + nb + tx];
    __syncthreads();
#pragma unroll
    for (int i = 0; i < 32; i += 8)
        WT[(long)(nb + ty + i) * K + kb + tx] = __float2half(t[tx][ty + i]);
}

__global__ void __launch_bounds__(256) bcat2(const float* __restrict__ a,
                                             const float* __restrict__ b,
                                             float* __restrict__ o) {
    int i = blockIdx.x * 256 + threadIdx.x;
    if (i < HDIM)          o[i] = a[i];
    else if (i < 2 * HDIM) o[i] = b[i - HDIM];
}

// ---------------- LayerNorm: warp-per-row, 8 rows/block -------------------
__global__ void __launch_bounds__(256) ln_kernel(
    const float* __restrict__ in, const float* __restrict__ gam,
    const float* __restrict__ bet, __half* __restrict__ out, int D)
{
    int lane = threadIdx.x & 31, wid = threadIdx.x >> 5;
    long row = (long)blockIdx.x * 8 + wid;
    const float* xr = in + row * (long)D;
    int nv = D >> 7;                      // float4 chunks per lane (6 or 8)
    float4 v[8];
    float s = 0.f, s2 = 0.f;
#pragma unroll 8
    for (int i = 0; i < nv; i++) {
        v[i] = *(const float4*)(xr + (i * 32 + lane) * 4);
        s  += v[i].x + v[i].y + v[i].z + v[i].w;
        s2 += v[i].x*v[i].x + v[i].y*v[i].y + v[i].z*v[i].z + v[i].w*v[i].w;
    }
#pragma unroll
    for (int m = 16; m; m >>= 1) {
        s  += __shfl_xor_sync(0xffffffffu, s,  m);
        s2 += __shfl_xor_sync(0xffffffffu, s2, m);
    }
    float mu   = s / (float)D;
    float var  = fmaxf(s2 / (float)D - mu * mu, 0.f);
    float rstd = rsqrtf(var + 1e-5f);
    __half* orow = out + row * (long)D;
#pragma unroll 8
    for (int i = 0; i < nv; i++) {
        int c = (i * 32 + lane) * 4;
        float4 g = *(const float4*)(gam + c);
        float4 b = *(const float4*)(bet + c);
        *(uint32_t*)(orow + c)     = h2u((v[i].x - mu) * rstd * g.x + b.x,
                                         (v[i].y - mu) * rstd * g.y + b.y);
        *(uint32_t*)(orow + c + 2) = h2u((v[i].z - mu) * rstd * g.z + b.z,
                                         (v[i].w - mu) * rstd * g.w + b.w);
    }
}

// ---------------- fp16 mma.sync GEMM 128x128 (BK=64) ----------------
#define GROW  72
#define GA_H  (128*GROW)
#define GST_H (2*GA_H)
#define GSM   (3*GST_H*2)

__global__ void __launch_bounds__(256, 2) gemm_h(
    const __half* __restrict__ A, const __half* __restrict__ Bw,
    const float* __restrict__ bias, const float* __restrict__ res,
    void* __restrict__ Cout, int M, int N, int K, int epi)
{
    extern __shared__ __half smh[];
    uint32_t usm = smem_u32(smh);
    int tid = threadIdx.x, lane = tid & 31, wid = tid >> 5;
    int gid = lane >> 2, tig = lane & 3;
    int wm = wid & 1, wn = wid >> 1;
    int m0 = blockIdx.y * 128, n0 = blockIdx.x * 128;

    long     asrc[4], bsrc[4];
    uint32_t adst[4], bdst[4];
#pragma unroll
    for (int i = 0; i < 4; i++) {
        int idx = tid + i * 256;
        int r = idx >> 3, ch = idx & 7;
        asrc[i] = (long)(m0 + r) * K + ch * 8;
        bsrc[i] = (long)(n0 + r) * K + ch * 8;
        adst[i] = (r * GROW + ch * 8) * 2;
        bdst[i] = (GA_H + r * GROW + ch * 8) * 2;
    }
    int l8    = lane & 7;
    int amrow = wm * 64 + ((lane >> 3) & 1) * 8 + l8;
    int akcol = (lane >> 4) * 8;
    int bnrow = wn * 32 + (lane >> 4) * 8 + l8;
    int bkcol = ((lane >> 3) & 1) * 8;
    uint32_t aB[4], bB[2];
#pragma unroll
    for (int mf = 0; mf < 4; mf++)
        aB[mf] = usm + ((amrow + mf * 16) * GROW + akcol) * 2;
#pragma unroll
    for (int np = 0; np < 2; np++)
        bB[np] = usm + ((GA_H + (bnrow + np * 16) * GROW + bkcol)) * 2;

    float acc[4][4][4];
#pragma unroll
    for (int i = 0; i < 4; i++)
#pragma unroll
        for (int j = 0; j < 4; j++)
#pragma unroll
            for (int r = 0; r < 4; r++) acc[i][j][r] = 0.f;

    const int NC = K / 64;

    auto issue = [&](int c, int s) {
        long kb = (long)c * 64;
        uint32_t so = usm + s * (GST_H * 2);
#pragma unroll
        for (int i = 0; i < 4; i++) cpa16(so + adst[i], A  + asrc[i] + kb);
#pragma unroll
        for (int i = 0; i < 4; i++) cpa16(so + bdst[i], Bw + bsrc[i] + kb);
        asm volatile("cp.async.commit_group;\n" ::: "memory");
    };

    issue(0, 0);
    if (NC > 1) issue(1, 1);

    for (int c = 0; c < NC; c++) {
        int s = c % 3;
        if (c + 1 < NC) asm volatile("cp.async.wait_group 1;\n" ::: "memory");
        else            asm volatile("cp.async.wait_group 0;\n" ::: "memory");
        __syncthreads();
        if (c + 2 < NC) issue(c + 2, (c + 2) % 3);

        uint32_t so = s * (GST_H * 2);
#pragma unroll
        for (int ks = 0; ks < 4; ks++) {
            uint32_t a[4][4], b[2][4];
#pragma unroll
            for (int mf = 0; mf < 4; mf++) ldm_x4(a[mf], aB[mf] + so + ks * 32);
#pragma unroll
            for (int np = 0; np < 2; np++) ldm_x4(b[np], bB[np] + so + ks * 32);
#pragma unroll
            for (int mf = 0; mf < 4; mf++)
#pragma unroll
                for (int nf = 0; nf < 4; nf++)
                    mma_f16(acc[mf][nf], a[mf], &b[nf >> 1][(nf & 1) * 2]);
        }
    }

    int cbase = n0 + wn * 32 + 2 * tig;
    float2 bl[4];
#pragma unroll
    for (int nf = 0; nf < 4; nf++)
        bl[nf] = *(const float2*)(bias + cbase + nf * 8);

#pragma unroll
    for (int mf = 0; mf < 4; mf++)
#pragma unroll
        for (int hh = 0; hh < 2; hh++) {
            long r = m0 + wm * 64 + mf * 16 + gid + hh * 8;
#pragma unroll
            for (int nf = 0; nf < 4; nf++)
                epi_store(acc[mf][nf][hh * 2] + bl[nf].x,
                          acc[mf][nf][hh * 2 + 1] + bl[nf].y,
                          epi, res, Cout, r, N, cbase + nf * 8);
        }
}

// ---------------- fp16 mma.sync GEMM 64x128 (occ 4) ----------------
#define W6ROW  72
#define W6A_H  (64*W6ROW)
#define W6ST_H (W6A_H + 128*W6ROW)
#define W6SM   (2*W6ST_H*2)

__global__ void __launch_bounds__(128, 4) gemm64(
    const __half* __restrict__ A, const __half* __restrict__ Bw,
    const float* __restrict__ bias, const float* __restrict__ res,
    void* __restrict__ Cout, int M, int N, int K, int epi)
{
    extern __shared__ __half smh[];
    uint32_t usm = smem_u32(smh);
    int tid = threadIdx.x, lane = tid & 31, wn = tid >> 5;
    int gid = lane >> 2, tig = lane & 3;
    int m0 = blockIdx.y * 64, n0 = blockIdx.x * 128;

    int r0 = tid >> 3, ch = tid & 7;
    long     asrc0 = (long)(m0 + r0) * K + ch * 8;
    long     bsrc0 = (long)(n0 + r0) * K + ch * 8;
    uint32_t adst0 = (r0 * W6ROW + ch * 8) * 2;
    uint32_t bdst0 = (W6A_H + r0 * W6ROW + ch * 8) * 2;
    long kstep16 = (long)16 * K;

    int l8    = lane & 7;
    int amrow = ((lane >> 3) & 1) * 8 + l8;
    int akcol = (lane >> 4) * 8;
    int bnrow = wn * 32 + (lane >> 4) * 8 + l8;
    int bkcol = ((lane >> 3) & 1) * 8;
    uint32_t aB[4], bB[2];
#pragma unroll
    for (int mf = 0; mf < 4; mf++)
        aB[mf] = usm + ((amrow + mf * 16) * W6ROW + akcol) * 2;
#pragma unroll
    for (int np = 0; np < 2; np++)
        bB[np] = usm + ((W6A_H + (bnrow + np * 16) * W6ROW + bkcol)) * 2;

    float acc[4][4][4];
#pragma unroll
    for (int i = 0; i < 4; i++)
#pragma unroll
        for (int j = 0; j < 4; j++)
#pragma unroll
            for (int r = 0; r < 4; r++) acc[i][j][r] = 0.f;

    const int NC = K / 64;

    auto issue = [&](int c, int s) {
        long kb = (long)c * 64;
        uint32_t so = usm + s * W6ST_H * 2;
#pragma unroll
        for (int i = 0; i < 4; i++)
            cpa16(so + adst0 + i * (16 * W6ROW * 2), A + asrc0 + i * kstep16 + kb);
#pragma unroll
        for (int i = 0; i < 8; i++)
            cpa16(so + bdst0 + i * (16 * W6ROW * 2), Bw + bsrc0 + i * kstep16 + kb);
        asm volatile("cp.async.commit_group;\n" ::: "memory");
    };

    issue(0, 0);

    for (int c = 0; c < NC; c++) {
        if (c + 1 < NC) {
            issue(c + 1, (c + 1) & 1);
            asm volatile("cp.async.wait_group 1;\n" ::: "memory");
        } else {
            asm volatile("cp.async.wait_group 0;\n" ::: "memory");
        }
        __syncthreads();

        uint32_t so = (c & 1) * (W6ST_H * 2);
#pragma unroll
        for (int ks = 0; ks < 4; ks++) {
            uint32_t a[4][4], b[2][4];
#pragma unroll
            for (int mf = 0; mf < 4; mf++) ldm_x4(a[mf], aB[mf] + so + ks * 32);
#pragma unroll
            for (int np = 0; np < 2; np++) ldm_x4(b[np], bB[np] + so + ks * 32);
#pragma unroll
            for (int mf = 0; mf < 4; mf++)
#pragma unroll
                for (int nf = 0; nf < 4; nf++)
                    mma_f16(acc[mf][nf], a[mf], &b[nf >> 1][(nf & 1) * 2]);
        }
        __syncthreads();
    }

    int cbase = n0 + wn * 32 + 2 * tig;
    float2 bl[4];
#pragma unroll
    for (int nf = 0; nf < 4; nf++)
        bl[nf] = *(const float2*)(bias + cbase + nf * 8);

#pragma unroll
    for (int mf = 0; mf < 4; mf++)
#pragma unroll
        for (int hh = 0; hh < 2; hh++) {
            long r = m0 + mf * 16 + gid + hh * 8;
#pragma unroll
            for (int nf = 0; nf < 4; nf++)
                epi_store(acc[mf][nf][hh * 2] + bl[nf].x,
                          acc[mf][nf][hh * 2 + 1] + bl[nf].y,
                          epi, res, Cout, r, N, cbase + nf * 8);
        }
}

// ---------------- fp16 flash attention, split-KV x3 ----------------
#define AQH   (128*72)
#define AKH   (64*72)
#define ASMEM ((AQH + 4*AKH) * 2)
#define ANCT  (NKV / 64)                 // 36 total tiles
#define ANCS  (ANCT / NSPL)              // 12 per split

__global__ void __launch_bounds__(256, 2) attn_h(
    const __half* __restrict__ Q, const __half* __restrict__ KV,
    float* __restrict__ po, float* __restrict__ pml)
{
    extern __shared__ __half smh[];
    __half* qs = smh;
    __half* ks = smh + AQH;
    __half* vs = ks + 2 * AKH;
    int tid = threadIdx.x, lane = tid & 31, wid = tid >> 5;
    int gid = lane >> 2, tig = lane & 3;
    int qb = blockIdx.x & 1, sp = blockIdx.x >> 1;
    int h = blockIdx.y, b = blockIdx.z;
    int c0 = sp * ANCS;

    const __half* Qb = Q  + ((long)b * NQ + qb * 128) * HDIM + h * 64;
    const __half* Kb = KV + (long)b * NKV * KVS + h * 64;
    const __half* Vb = Kb + HDIM;

    int l8    = lane & 7;
    int qrow  = wid * 16 + ((lane >> 3) & 1) * 8 + l8;
    int qcol  = (lane >> 4) * 8;
    int krow  = (lane >> 4) * 8 + l8;
    int kcol  = ((lane >> 3) & 1) * 8;
    int vrow  = ((lane >> 3) & 1) * 8 + l8;
    int vcol  = (lane >> 4) * 8;

    auto load_kv = [&](int ct, int buf) {
        __half* kd = ks + buf * AKH;
        __half* vd = vs + buf * AKH;
        long j0 = (long)ct * 64;
#pragma unroll
        for (int i = 0; i < 2; i++) {
            int idx = tid + i * 256;
            int r = idx >> 3, c8 = (idx & 7) * 8;
            cpa16(smem_u32(kd + r * 72 + c8), Kb + (j0 + r) * KVS + c8);
            cpa16(smem_u32(vd + r * 72 + c8), Vb + (j0 + r) * KVS + c8);
        }
        asm volatile("cp.async.commit_group;\n" ::: "memory");
    };

#pragma unroll
    for (int i = 0; i < 4; i++) {
        int idx = tid + i * 256;
        int r = idx >> 3, c8 = (idx & 7) * 8;
        cpa16(smem_u32(qs + r * 72 + c8), Qb + (long)r * HDIM + c8);
    }
    load_kv(c0, 0);

    float o[8][4];
#pragma unroll
    for (int nf = 0; nf < 8; nf++)
#pragma unroll
        for (int e = 0; e < 4; e++) o[nf][e] = 0.f;
    float m0 = -1e30f, m1 = -1e30f, l0 = 0.f, l1 = 0.f;

    uint32_t qa[4][4];

    for (int c = 0; c < ANCS; c++) {
        if (c + 1 < ANCS) {
            load_kv(c0 + c + 1, (c + 1) & 1);
            asm volatile("cp.async.wait_group 1;\n" ::: "memory");
        } else {
            asm volatile("cp.async.wait_group 0;\n" ::: "memory");
        }
        __syncthreads();

        if (c == 0) {
#pragma unroll
            for (int kf = 0; kf < 4; kf++)
                ldm_x4(qa[kf], smem_u32(qs + qrow * 72 + kf * 16 + qcol));
        }

        const __half* kcur = ks + (c & 1) * AKH;
        const __half* vcur = vs + (c & 1) * AKH;

        float sc[8][4];
#pragma unroll
        for (int nf = 0; nf < 8; nf++)
#pragma unroll
            for (int e = 0; e < 4; e++) sc[nf][e] = 0.f;
#pragma unroll
        for (int kf = 0; kf < 4; kf++) {
            uint32_t kb4[4][4];
#pragma unroll
            for (int np = 0; np < 4; np++)
                ldm_x4(kb4[np], smem_u32(kcur + (krow + np * 16) * 72 + kf * 16 + kcol));
#pragma unroll
            for (int np = 0; np < 4; np++) {
                mma_f16(sc[2 * np],     qa[kf], &kb4[np][0]);
                mma_f16(sc[2 * np + 1], qa[kf], &kb4[np][2]);
            }
        }

        float tm0 = -1e30f, tm1 = -1e30f;
#pragma unroll
        for (int nf = 0; nf < 8; nf++) {
            tm0 = fmaxf(tm0, fmaxf(sc[nf][0], sc[nf][1]));
            tm1 = fmaxf(tm1, fmaxf(sc[nf][2], sc[nf][3]));
        }
        tm0 = fmaxf(tm0, __shfl_xor_sync(0xffffffffu, tm0, 1));
        tm0 = fmaxf(tm0, __shfl_xor_sync(0xffffffffu, tm0, 2));
        tm1 = fmaxf(tm1, __shfl_xor_sync(0xffffffffu, tm1, 1));
        tm1 = fmaxf(tm1, __shfl_xor_sync(0xffffffffu, tm1, 2));
        float nm0 = fmaxf(m0, tm0), nm1 = fmaxf(m1, tm1);
        float corr0 = fexp(m0 - nm0), corr1 = fexp(m1 - nm1);
        m0 = nm0; m1 = nm1;

        uint32_t ph[4][4];
        float ps0 = 0.f, ps1 = 0.f;
#pragma unroll
        for (int u = 0; u < 4; u++) {
            float p00 = fexp(sc[2*u][0] - nm0),   p01 = fexp(sc[2*u][1] - nm0);
            float p02 = fexp(sc[2*u][2] - nm1),   p03 = fexp(sc[2*u][3] - nm1);
            float p10 = fexp(sc[2*u+1][0] - nm0), p11 = fexp(sc[2*u+1][1] - nm0);
            float p12 = fexp(sc[2*u+1][2] - nm1), p13 = fexp(sc[2*u+1][3] - nm1);
            __half2 h0 = __floats2half2_rn(p00, p01);
            __half2 h1 = __floats2half2_rn(p02, p03);
            __half2 h2 = __floats2half2_rn(p10, p11);
            __half2 h3 = __floats2half2_rn(p12, p13);
            ph[u][0] = *(uint32_t*)&h0; ph[u][1] = *(uint32_t*)&h1;
            ph[u][2] = *(uint32_t*)&h2; ph[u][3] = *(uint32_t*)&h3;
            float2 f0 = __half22float2(h0), f1 = __half22float2(h1);
            float2 f2 = __half22float2(h2), f3 = __half22float2(h3);
            ps0 += f0.x + f0.y + f2.x + f2.y;
            ps1 += f1.x + f1.y + f3.x + f3.y;
        }
        ps0 += __shfl_xor_sync(0xffffffffu, ps0, 1);
        ps0 += __shfl_xor_sync(0xffffffffu, ps0, 2);
        ps1 += __shfl_xor_sync(0xffffffffu, ps1, 1);
        ps1 += __shfl_xor_sync(0xffffffffu, ps1, 2);
        l0 = l0 * corr0 + ps0;
        l1 = l1 * corr1 + ps1;
#pragma unroll
        for (int nf = 0; nf < 8; nf++) {
            o[nf][0] *= corr0; o[nf][1] *= corr0;
            o[nf][2] *= corr1; o[nf][3] *= corr1;
        }

#pragma unroll
        for (int u = 0; u < 4; u++) {
#pragma unroll
            for (int np = 0; np < 4; np++) {
                uint32_t vb[4];
                ldm_x4_t(vb, smem_u32(vcur + (u * 16 + vrow) * 72 + np * 16 + vcol));
                mma_f16(o[2 * np],     ph[u], &vb[0]);
                mma_f16(o[2 * np + 1], ph[u], &vb[2]);
            }
        }
        __syncthreads();
    }

    // ---- write unnormalized partials + (m,l) ----
    long prow = (((long)sp * BB + b) * HEADS + h) * NQ + qb * 128 + wid * 16 + gid;
    float* poB = po + prow * 64;
#pragma unroll
    for (int nf = 0; nf < 8; nf++) {
        int col = nf * 8 + 2 * tig;
        *(float2*)(poB + col)          = make_float2(o[nf][0], o[nf][1]);
        *(float2*)(poB + 8 * 64 + col) = make_float2(o[nf][2], o[nf][3]);
    }
    if (tig == 0) {
        *(float2*)(pml + prow * 2)       = make_float2(m0, l0);
        *(float2*)(pml + (prow + 8) * 2) = make_float2(m1, l1);
    }
}

// ---------------- combine split partials -> ctx fp16 ----------------
__global__ void __launch_bounds__(256) attn_comb(
    const float* __restrict__ po, const float* __restrict__ pml,
    __half* __restrict__ ctx)
{
    const long S = (long)BB * HEADS * NQ;
    long idx = (long)blockIdx.x * 256 + threadIdx.x;   // (rbh, colpair)
    int cp   = (int)(idx & 31);
    long rbh = idx >> 5;
    float2 ml0 = *(const float2*)(pml + rbh * 2);
    float2 ml1 = *(const float2*)(pml + (S + rbh) * 2);
    float2 ml2 = *(const float2*)(pml + (2 * S + rbh) * 2);
    float M  = fmaxf(ml0.x, fmaxf(ml1.x, ml2.x));
    float w0 = fexp(ml0.x - M), w1 = fexp(ml1.x - M), w2 = fexp(ml2.x - M);
    float inv = 1.f / (ml0.y * w0 + ml1.y * w1 + ml2.y * w2);
    float2 a0 = *(const float2*)(po + rbh * 64 + cp * 2);
    float2 a1 = *(const float2*)(po + (S + rbh) * 64 + cp * 2);
    float2 a2 = *(const float2*)(po + (2 * S + rbh) * 64 + cp * 2);
    float ox = (a0.x * w0 + a1.x * w1 + a2.x * w2) * inv;
    float oy = (a0.y * w0 + a1.y * w1 + a2.y * w2) * inv;
    int row = (int)(rbh % NQ);
    long bh = rbh / NQ;
    int h = (int)(bh % HEADS), b = (int)(bh / HEADS);
    *(uint32_t*)(ctx + ((long)b * NQ + row) * HDIM + h * 64 + cp * 2) = h2u(ox, oy);
}

// ---------------- launcher ----------------
extern "C" void kernel_launch(void* const* d_in, const int* in_sizes, int n_in,
                              void* d_out, int out_size)
{
    const float* hid = (const float*)d_in[0];
    const float* x   = (const float*)d_in[1];
    const float* Wq  = (const float*)d_in[2];
    const float* bq  = (const float*)d_in[3];
    const float* Wk  = (const float*)d_in[4];
    const float* bk  = (const float*)d_in[5];
    const float* Wv  = (const float*)d_in[6];
    const float* bv  = (const float*)d_in[7];
    const float* Wo  = (const float*)d_in[8];
    const float* bo  = (const float*)d_in[9];
    const float* W1  = (const float*)d_in[10];
    const float* b1  = (const float*)d_in[11];
    const float* W2  = (const float*)d_in[12];
    const float* b2  = (const float*)d_in[13];
    const float* gi  = (const float*)d_in[14];
    const float* bi  = (const float*)d_in[15];
    const float* gh  = (const float*)d_in[16];
    const float* bh  = (const float*)d_in[17];
    const float* gf  = (const float*)d_in[18];
    const float* bf  = (const float*)d_in[19];

    __half *xn, *hn, *q, *kv, *ctx, *hnf, *ff;
    __half *wq, *wkv, *wo, *w1, *w2;
    float *o1, *bkv, *po, *pml;
    cudaGetSymbolAddress((void**)&xn,  g_xn);
    cudaGetSymbolAddress((void**)&hn,  g_hn);
    cudaGetSymbolAddress((void**)&q,   g_q);
    cudaGetSymbolAddress((void**)&kv,  g_kv);
    cudaGetSymbolAddress((void**)&ctx, g_ctx);
    cudaGetSymbolAddress((void**)&o1,  g_o1);
    cudaGetSymbolAddress((void**)&hnf, g_hnf);
    cudaGetSymbolAddress((void**)&ff,  g_ff);
    cudaGetSymbolAddress((void**)&wq,  g_wq);
    cudaGetSymbolAddress((void**)&wkv, g_wkv);
    cudaGetSymbolAddress((void**)&wo,  g_wo);
    cudaGetSymbolAddress((void**)&w1,  g_w1);
    cudaGetSymbolAddress((void**)&w2,  g_w2);
    cudaGetSymbolAddress((void**)&bkv, g_bkv);
    cudaGetSymbolAddress((void**)&po,  g_po);
    cudaGetSymbolAddress((void**)&pml, g_pml);

    cudaFuncSetAttribute(attn_h, cudaFuncAttributeMaxDynamicSharedMemorySize, ASMEM);
    cudaFuncSetAttribute(gemm_h, cudaFuncAttributeMaxDynamicSharedMemorySize, GSM);
    cudaFuncSetAttribute(gemm64, cudaFuncAttributeMaxDynamicSharedMemorySize, W6SM);

    wprep<<<dim3(HDIM / 32, IMGD / 32), 256>>>(Wk, wkv, IMGD, HDIM);                 // 0
    wprep<<<dim3(HDIM / 32, IMGD / 32), 256>>>(Wv, wkv + (long)HDIM * IMGD,          // 1
                                               IMGD, HDIM);
    bcat2<<<KVS / 256, 256>>>(bk, bv, bkv);                                          // 2
    ln_kernel<<<BB * NKV / 8, 256>>>(x, gi, bi, xn, IMGD);                           // 3
    wprep<<<dim3(HDIM / 32, HDIM / 32), 256>>>(Wq, wq, HDIM, HDIM);                  // 4
    gemm_h<<<dim3(KVS / 128, BB * NKV / 128), 256, GSM>>>(xn, wkv, bkv, nullptr,     // 5
                                                          kv, BB * NKV, KVS, IMGD, 3);
    ln_kernel<<<BB * NQ / 8, 256>>>(hid, gh, bh, hn, HDIM);                          // 6
    gemm64<<<dim3(HDIM / 128, BB * NQ / 64), 128, W6SM>>>(hn, wq, bq, nullptr, q,    // 7
                                                          BB * NQ, HDIM, HDIM, 4);
    wprep<<<dim3(HDIM / 32,  HDIM / 32),  256>>>(Wo, wo, HDIM, HDIM);
    wprep<<<dim3(INTER / 32, HDIM / 32),  256>>>(W1, w1, HDIM, INTER);
    wprep<<<dim3(HDIM / 32,  INTER / 32), 256>>>(W2, w2, INTER, HDIM);

    attn_h<<<dim3(2 * NSPL, HEADS, BB), 256, ASMEM>>>(q, kv, po, pml);
    attn_comb<<<(int)(((long)BB * HEADS * NQ * 32) / 256), 256>>>(po, pml, ctx);

    gemm64<<<dim3(HDIM / 128, BB * NQ / 64), 128, W6SM>>>(ctx, wo, bo, hid, o1,
                                                          BB * NQ, HDIM, HDIM, 1);

    ln_kernel<<<BB * NQ / 8, 256>>>(o1, gf, bf, hnf, HDIM);
    gemm_h<<<dim3(INTER / 128, BB * NQ / 128), 256, GSM>>>(hnf, w1, b1, nullptr, ff,
                                                           BB * NQ, INTER, HDIM, 2);
    gemm64<<<dim3(HDIM / 128,  BB * NQ / 64), 128, W6SM>>>(ff, w2, b2, o1, d_out,
                                                           BB * NQ, HDIM, INTER, 1);
}

// round 15
// speedup vs baseline: 3.2395x; 1.0303x over previous
#include <cuda_runtime.h>
#include <cuda_fp16.h>
#include <cstdint>
#include <math.h>

#define BB    16
#define NQ    256
#define NKV   2304
#define HDIM  768
#define IMGD  1024
#define HEADS 12
#define INTER 3072
#define KVS   1536
#define NSPL  3
#define ATTN_SCALE 0.125f

// ---------------- scratch (static __device__, allocation-free) ----------------
__device__ __half g_xn [BB*NKV*IMGD];
__device__ __half g_hn [BB*NQ*HDIM];
__device__ __half g_q  [BB*NQ*HDIM];
__device__ __half g_kv [BB*NKV*KVS];
__device__ __half g_ctx[BB*NQ*HDIM];
__device__ float  g_o1 [BB*NQ*HDIM];
__device__ __half g_hnf[BB*NQ*HDIM];
__device__ __half g_ff [BB*NQ*INTER];
__device__ float  g_po [(long)NSPL*BB*HEADS*NQ*64];
__device__ float  g_pml[(long)NSPL*BB*HEADS*NQ*2];
__device__ __half g_wq [HDIM*HDIM];
__device__ __half g_wkv[KVS*IMGD];
__device__ __half g_wo [HDIM*HDIM];
__device__ __half g_w1 [INTER*HDIM];
__device__ __half g_w2 [HDIM*INTER];
__device__ float  g_bkv[KVS];

// ---------------- helpers ----------------
__device__ __forceinline__ uint32_t smem_u32(const void* p) {
    uint32_t a;
    asm("{ .reg .u64 t; cvta.to.shared.u64 t, %1; cvt.u32.u64 %0, t; }" : "=r"(a) : "l"(p));
    return a;
}
__device__ __forceinline__ void cpa16(uint32_t dst, const void* src) {
    asm volatile("cp.async.cg.shared.global [%0], [%1], 16;\n" :: "r"(dst), "l"(src));
}
__device__ __forceinline__ void mma_f16(float* c, const uint32_t* a, const uint32_t* b) {
    asm volatile(
        "mma.sync.aligned.m16n8k16.row.col.f32.f16.f16.f32 "
        "{%0,%1,%2,%3}, {%4,%5,%6,%7}, {%8,%9}, {%0,%1,%2,%3};\n"
        : "+f"(c[0]), "+f"(c[1]), "+f"(c[2]), "+f"(c[3])
        : "r"(a[0]), "r"(a[1]), "r"(a[2]), "r"(a[3]), "r"(b[0]), "r"(b[1]));
}
__device__ __forceinline__ void ldm_x4(uint32_t* r, uint32_t addr) {
    asm volatile("ldmatrix.sync.aligned.m8n8.x4.shared.b16 {%0,%1,%2,%3}, [%4];"
        : "=r"(r[0]), "=r"(r[1]), "=r"(r[2]), "=r"(r[3]) : "r"(addr));
}
__device__ __forceinline__ void ldm_x4_t(uint32_t* r, uint32_t addr) {
    asm volatile("ldmatrix.sync.aligned.m8n8.x4.trans.shared.b16 {%0,%1,%2,%3}, [%4];"
        : "=r"(r[0]), "=r"(r[1]), "=r"(r[2]), "=r"(r[3]) : "r"(addr));
}
__device__ __forceinline__ float fexp(float x) {
    float y = fmaxf(x * 1.44269504f, -120.f);
    float r = y + 12582912.f;
    float n = r - 12582912.f;
    float f = y - n;
    float p = 0.00133336f;
    p = fmaf(p, f, 0.00961804f);
    p = fmaf(p, f, 0.05550411f);
    p = fmaf(p, f, 0.24022651f);
    p = fmaf(p, f, 0.69314718f);
    p = fmaf(p, f, 1.0f);
    int ni = __float_as_int(r) - 0x4B400000;
    return p * __int_as_float((ni + 127) << 23);
}
__device__ __forceinline__ uint32_t h2u(float lo, float hi) {
    __half2 h = __floats2half2_rn(lo, hi);
    return *(uint32_t*)&h;
}

__device__ __forceinline__ void epi_store(float v0, float v1, int epi,
                                          const float* res, void* Cout,
                                          long r, long N, int col) {
    if (epi == 1) {
        float2 rv = *(const float2*)(res + r * N + col);
        *(float2*)((float*)Cout + r * N + col) = make_float2(v0 + rv.x, v1 + rv.y);
    } else {
        if (epi == 2) {
            v0 = 0.5f * v0 * (1.f + erff(v0 * 0.70710678118654752f));
            v1 = 0.5f * v1 * (1.f + erff(v1 * 0.70710678118654752f));
        } else if (epi == 4) {
            v0 *= ATTN_SCALE; v1 *= ATTN_SCALE;
        }
        *(uint32_t*)((__half*)Cout + r * N + col) = h2u(v0, v1);
    }
}

// ---------------- fused weight prep: all 6 transposes + bias concat -----------
// segments: 0:Wq(768,768) 1:Wk(1024,768) 2:Wv(1024,768) 3:Wo(768,768)
//           4:W1(768,3072) 5:W2(3072,768) 6:bcat (6 blocks)
#define WPB0 576
#define WPB1 (WPB0+768)
#define WPB2 (WPB1+768)
#define WPB3 (WPB2+576)
#define WPB4 (WPB3+2304)
#define WPB5 (WPB4+2304)
#define WPBT (WPB5+6)

__global__ void __launch_bounds__(256) wprep_all(
    const float* __restrict__ Wq, const float* __restrict__ Wk,
    const float* __restrict__ Wv, const float* __restrict__ Wo,
    const float* __restrict__ W1, const float* __restrict__ W2,
    const float* __restrict__ bk, const float* __restrict__ bv,
    __half* __restrict__ wq, __half* __restrict__ wkv,
    __half* __restrict__ wo, __half* __restrict__ w1,
    __half* __restrict__ w2, float* __restrict__ bkv)
{
    int bx = blockIdx.x;
    if (bx >= WPB5) {                      // bias concat
        int i = (bx - WPB5) * 256 + threadIdx.x;
        if (i < HDIM)          bkv[i] = bk[i];
        else if (i < 2 * HDIM) bkv[i] = bv[i - HDIM];
        return;
    }
    const float* W; __half* WT; int K, N, lb;
    if (bx < WPB0)      { W = Wq; WT = wq;  K = HDIM;  N = HDIM;  lb = bx; }
    else if (bx < WPB1) { W = Wk; WT = wkv; K = IMGD;  N = HDIM;  lb = bx - WPB0; }
    else if (bx < WPB2) { W = Wv; WT = wkv + (long)HDIM * IMGD;
                          K = IMGD;  N = HDIM;  lb = bx - WPB1; }
    else if (bx < WPB3) { W = Wo; WT = wo;  K = HDIM;  N = HDIM;  lb = bx - WPB2; }
    else if (bx < WPB4) { W = W1; WT = w1;  K = HDIM;  N = INTER; lb = bx - WPB3; }
    else                { W = W2; WT = w2;  K = INTER; N = HDIM;  lb = bx - WPB4; }
    int nbn = N / 32;
    int nb = (lb % nbn) * 32, kb = (lb / nbn) * 32;

    __shared__ float t[32][33];
    int tx = threadIdx.x & 31, ty = threadIdx.x >> 5;
#pragma unroll
    for (int i = 0; i < 32; i += 8)
        t[ty + i][tx] = W[(long)(kb + ty + i) * N + nb + tx];
    __syncthreads();
#pragma unroll
    for (int i = 0; i < 32; i += 8)
        WT[(long)(nb + ty + i) * K + kb + tx] = __float2half(t[tx][ty + i]);
}

// ---------------- LayerNorm: warp-per-row, two-pass streaming ----------------
__global__ void __launch_bounds__(256) ln_kernel(
    const float* __restrict__ in, const float* __restrict__ gam,
    const float* __restrict__ bet, __half* __restrict__ out, int D)
{
    int lane = threadIdx.x & 31, wid = threadIdx.x >> 5;
    long row = (long)blockIdx.x * 8 + wid;
    const float* xr = in + row * (long)D;
    int nv = D >> 7;
    float s = 0.f, s2 = 0.f;
#pragma unroll 8
    for (int i = 0; i < nv; i++) {
        float4 v = __ldg((const float4*)(xr + (i * 32 + lane) * 4));
        s  += v.x + v.y + v.z + v.w;
        s2 += v.x*v.x + v.y*v.y + v.z*v.z + v.w*v.w;
    }
#pragma unroll
    for (int m = 16; m; m >>= 1) {
        s  += __shfl_xor_sync(0xffffffffu, s,  m);
        s2 += __shfl_xor_sync(0xffffffffu, s2, m);
    }
    float mu   = s / (float)D;
    float var  = fmaxf(s2 / (float)D - mu * mu, 0.f);
    float rstd = rsqrtf(var + 1e-5f);
    __half* orow = out + row * (long)D;
#pragma unroll 8
    for (int i = 0; i < nv; i++) {
        int c = (i * 32 + lane) * 4;
        float4 v = __ldg((const float4*)(xr + c));       // L1/L2 hit (just read)
        float4 g = __ldg((const float4*)(gam + c));
        float4 b = __ldg((const float4*)(bet + c));
        *(uint32_t*)(orow + c)     = h2u((v.x - mu) * rstd * g.x + b.x,
                                         (v.y - mu) * rstd * g.y + b.y);
        *(uint32_t*)(orow + c + 2) = h2u((v.z - mu) * rstd * g.z + b.z,
                                         (v.w - mu) * rstd * g.w + b.w);
    }
}

// ---------------- fp16 mma.sync GEMM 128x128 (BK=64) ----------------
#define GROW  72
#define GA_H  (128*GROW)
#define GST_H (2*GA_H)
#define GSM   (3*GST_H*2)

__global__ void __launch_bounds__(256, 2) gemm_h(
    const __half* __restrict__ A, const __half* __restrict__ Bw,
    const float* __restrict__ bias, const float* __restrict__ res,
    void* __restrict__ Cout, int M, int N, int K, int epi)
{
    extern __shared__ __half smh[];
    uint32_t usm = smem_u32(smh);
    int tid = threadIdx.x, lane = tid & 31, wid = tid >> 5;
    int gid = lane >> 2, tig = lane & 3;
    int wm = wid & 1, wn = wid >> 1;
    int m0 = blockIdx.y * 128, n0 = blockIdx.x * 128;

    long     asrc[4], bsrc[4];
    uint32_t adst[4], bdst[4];
#pragma unroll
    for (int i = 0; i < 4; i++) {
        int idx = tid + i * 256;
        int r = idx >> 3, ch = idx & 7;
        asrc[i] = (long)(m0 + r) * K + ch * 8;
        bsrc[i] = (long)(n0 + r) * K + ch * 8;
        adst[i] = (r * GROW + ch * 8) * 2;
        bdst[i] = (GA_H + r * GROW + ch * 8) * 2;
    }
    int l8    = lane & 7;
    int amrow = wm * 64 + ((lane >> 3) & 1) * 8 + l8;
    int akcol = (lane >> 4) * 8;
    int bnrow = wn * 32 + (lane >> 4) * 8 + l8;
    int bkcol = ((lane >> 3) & 1) * 8;
    uint32_t aB[4], bB[2];
#pragma unroll
    for (int mf = 0; mf < 4; mf++)
        aB[mf] = usm + ((amrow + mf * 16) * GROW + akcol) * 2;
#pragma unroll
    for (int np = 0; np < 2; np++)
        bB[np] = usm + ((GA_H + (bnrow + np * 16) * GROW + bkcol)) * 2;

    float acc[4][4][4];
#pragma unroll
    for (int i = 0; i < 4; i++)
#pragma unroll
        for (int j = 0; j < 4; j++)
#pragma unroll
            for (int r = 0; r < 4; r++) acc[i][j][r] = 0.f;

    const int NC = K / 64;

    auto issue = [&](int c, int s) {
        long kb = (long)c * 64;
        uint32_t so = usm + s * (GST_H * 2);
#pragma unroll
        for (int i = 0; i < 4; i++) cpa16(so + adst[i], A  + asrc[i] + kb);
#pragma unroll
        for (int i = 0; i < 4; i++) cpa16(so + bdst[i], Bw + bsrc[i] + kb);
        asm volatile("cp.async.commit_group;\n" ::: "memory");
    };

    issue(0, 0);
    if (NC > 1) issue(1, 1);

    for (int c = 0; c < NC; c++) {
        int s = c % 3;
        if (c + 1 < NC) asm volatile("cp.async.wait_group 1;\n" ::: "memory");
        else            asm volatile("cp.async.wait_group 0;\n" ::: "memory");
        __syncthreads();
        if (c + 2 < NC) issue(c + 2, (c + 2) % 3);

        uint32_t so = s * (GST_H * 2);
#pragma unroll
        for (int ks = 0; ks < 4; ks++) {
            uint32_t a[4][4], b[2][4];
#pragma unroll
            for (int mf = 0; mf < 4; mf++) ldm_x4(a[mf], aB[mf] + so + ks * 32);
#pragma unroll
            for (int np = 0; np < 2; np++) ldm_x4(b[np], bB[np] + so + ks * 32);
#pragma unroll
            for (int mf = 0; mf < 4; mf++)
#pragma unroll
                for (int nf = 0; nf < 4; nf++)
                    mma_f16(acc[mf][nf], a[mf], &b[nf >> 1][(nf & 1) * 2]);
        }
    }

    int cbase = n0 + wn * 32 + 2 * tig;
    float2 bl[4];
#pragma unroll
    for (int nf = 0; nf < 4; nf++)
        bl[nf] = *(const float2*)(bias + cbase + nf * 8);

#pragma unroll
    for (int mf = 0; mf < 4; mf++)
#pragma unroll
        for (int hh = 0; hh < 2; hh++) {
            long r = m0 + wm * 64 + mf * 16 + gid + hh * 8;
#pragma unroll
            for (int nf = 0; nf < 4; nf++)
                epi_store(acc[mf][nf][hh * 2] + bl[nf].x,
                          acc[mf][nf][hh * 2 + 1] + bl[nf].y,
                          epi, res, Cout, r, N, cbase + nf * 8);
        }
}

// ---------------- fp16 mma.sync GEMM 64x128 (occ 4) ----------------
#define W6ROW  72
#define W6A_H  (64*W6ROW)
#define W6ST_H (W6A_H + 128*W6ROW)
#define W6SM   (2*W6ST_H*2)

__global__ void __launch_bounds__(128, 4) gemm64(
    const __half* __restrict__ A, const __half* __restrict__ Bw,
    const float* __restrict__ bias, const float* __restrict__ res,
    void* __restrict__ Cout, int M, int N, int K, int epi)
{
    extern __shared__ __half smh[];
    uint32_t usm = smem_u32(smh);
    int tid = threadIdx.x, lane = tid & 31, wn = tid >> 5;
    int gid = lane >> 2, tig = lane & 3;
    int m0 = blockIdx.y * 64, n0 = blockIdx.x * 128;

    int r0 = tid >> 3, ch = tid & 7;
    long     asrc0 = (long)(m0 + r0) * K + ch * 8;
    long     bsrc0 = (long)(n0 + r0) * K + ch * 8;
    uint32_t adst0 = (r0 * W6ROW + ch * 8) * 2;
    uint32_t bdst0 = (W6A_H + r0 * W6ROW + ch * 8) * 2;
    long kstep16 = (long)16 * K;

    int l8    = lane & 7;
    int amrow = ((lane >> 3) & 1) * 8 + l8;
    int akcol = (lane >> 4) * 8;
    int bnrow = wn * 32 + (lane >> 4) * 8 + l8;
    int bkcol = ((lane >> 3) & 1) * 8;
    uint32_t aB[4], bB[2];
#pragma unroll
    for (int mf = 0; mf < 4; mf++)
        aB[mf] = usm + ((amrow + mf * 16) * W6ROW + akcol) * 2;
#pragma unroll
    for (int np = 0; np < 2; np++)
        bB[np] = usm + ((W6A_H + (bnrow + np * 16) * W6ROW + bkcol)) * 2;

    float acc[4][4][4];
#pragma unroll
    for (int i = 0; i < 4; i++)
#pragma unroll
        for (int j = 0; j < 4; j++)
#pragma unroll
            for (int r = 0; r < 4; r++) acc[i][j][r] = 0.f;

    const int NC = K / 64;

    auto issue = [&](int c, int s) {
        long kb = (long)c * 64;
        uint32_t so = usm + s * W6ST_H * 2;
#pragma unroll
        for (int i = 0; i < 4; i++)
            cpa16(so + adst0 + i * (16 * W6ROW * 2), A + asrc0 + i * kstep16 + kb);
#pragma unroll
        for (int i = 0; i < 8; i++)
            cpa16(so + bdst0 + i * (16 * W6ROW * 2), Bw + bsrc0 + i * kstep16 + kb);
        asm volatile("cp.async.commit_group;\n" ::: "memory");
    };

    issue(0, 0);

    for (int c = 0; c < NC; c++) {
        if (c + 1 < NC) {
            issue(c + 1, (c + 1) & 1);
            asm volatile("cp.async.wait_group 1;\n" ::: "memory");
        } else {
            asm volatile("cp.async.wait_group 0;\n" ::: "memory");
        }
        __syncthreads();

        uint32_t so = (c & 1) * (W6ST_H * 2);
#pragma unroll
        for (int ks = 0; ks < 4; ks++) {
            uint32_t a[4][4], b[2][4];
#pragma unroll
            for (int mf = 0; mf < 4; mf++) ldm_x4(a[mf], aB[mf] + so + ks * 32);
#pragma unroll
            for (int np = 0; np < 2; np++) ldm_x4(b[np], bB[np] + so + ks * 32);
#pragma unroll
            for (int mf = 0; mf < 4; mf++)
#pragma unroll
                for (int nf = 0; nf < 4; nf++)
                    mma_f16(acc[mf][nf], a[mf], &b[nf >> 1][(nf & 1) * 2]);
        }
        __syncthreads();
    }

    int cbase = n0 + wn * 32 + 2 * tig;
    float2 bl[4];
#pragma unroll
    for (int nf = 0; nf < 4; nf++)
        bl[nf] = *(const float2*)(bias + cbase + nf * 8);

#pragma unroll
    for (int mf = 0; mf < 4; mf++)
#pragma unroll
        for (int hh = 0; hh < 2; hh++) {
            long r = m0 + mf * 16 + gid + hh * 8;
#pragma unroll
            for (int nf = 0; nf < 4; nf++)
                epi_store(acc[mf][nf][hh * 2] + bl[nf].x,
                          acc[mf][nf][hh * 2 + 1] + bl[nf].y,
                          epi, res, Cout, r, N, cbase + nf * 8);
        }
}

// ---------------- fp16 flash attention, split-KV x3 ----------------
#define AQH   (128*72)
#define AKH   (64*72)
#define ASMEM ((AQH + 4*AKH) * 2)
#define ANCT  (NKV / 64)
#define ANCS  (ANCT / NSPL)

__global__ void __launch_bounds__(256, 2) attn_h(
    const __half* __restrict__ Q, const __half* __restrict__ KV,
    float* __restrict__ po, float* __restrict__ pml)
{
    extern __shared__ __half smh[];
    __half* qs = smh;
    __half* ks = smh + AQH;
    __half* vs = ks + 2 * AKH;
    int tid = threadIdx.x, lane = tid & 31, wid = tid >> 5;
    int gid = lane >> 2, tig = lane & 3;
    int qb = blockIdx.x & 1, sp = blockIdx.x >> 1;
    int h = blockIdx.y, b = blockIdx.z;
    int c0 = sp * ANCS;

    const __half* Qb = Q  + ((long)b * NQ + qb * 128) * HDIM + h * 64;
    const __half* Kb = KV + (long)b * NKV * KVS + h * 64;
    const __half* Vb = Kb + HDIM;

    int l8    = lane & 7;
    int qrow  = wid * 16 + ((lane >> 3) & 1) * 8 + l8;
    int qcol  = (lane >> 4) * 8;
    int krow  = (lane >> 4) * 8 + l8;
    int kcol  = ((lane >> 3) & 1) * 8;
    int vrow  = ((lane >> 3) & 1) * 8 + l8;
    int vcol  = (lane >> 4) * 8;

    auto load_kv = [&](int ct, int buf) {
        __half* kd = ks + buf * AKH;
        __half* vd = vs + buf * AKH;
        long j0 = (long)ct * 64;
#pragma unroll
        for (int i = 0; i < 2; i++) {
            int idx = tid + i * 256;
            int r = idx >> 3, c8 = (idx & 7) * 8;
            cpa16(smem_u32(kd + r * 72 + c8), Kb + (j0 + r) * KVS + c8);
            cpa16(smem_u32(vd + r * 72 + c8), Vb + (j0 + r) * KVS + c8);
        }
        asm volatile("cp.async.commit_group;\n" ::: "memory");
    };

#pragma unroll
    for (int i = 0; i < 4; i++) {
        int idx = tid + i * 256;
        int r = idx >> 3, c8 = (idx & 7) * 8;
        cpa16(smem_u32(qs + r * 72 + c8), Qb + (long)r * HDIM + c8);
    }
    load_kv(c0, 0);

    float o[8][4];
#pragma unroll
    for (int nf = 0; nf < 8; nf++)
#pragma unroll
        for (int e = 0; e < 4; e++) o[nf][e] = 0.f;
    float m0 = -1e30f, m1 = -1e30f, l0 = 0.f, l1 = 0.f;

    uint32_t qa[4][4];

    for (int c = 0; c < ANCS; c++) {
        if (c + 1 < ANCS) {
            load_kv(c0 + c + 1, (c + 1) & 1);
            asm volatile("cp.async.wait_group 1;\n" ::: "memory");
        } else {
            asm volatile("cp.async.wait_group 0;\n" ::: "memory");
        }
        __syncthreads();

        if (c == 0) {
#pragma unroll
            for (int kf = 0; kf < 4; kf++)
                ldm_x4(qa[kf], smem_u32(qs + qrow * 72 + kf * 16 + qcol));
        }

        const __half* kcur = ks + (c & 1) * AKH;
        const __half* vcur = vs + (c & 1) * AKH;

        float sc[8][4];
#pragma unroll
        for (int nf = 0; nf < 8; nf++)
#pragma unroll
            for (int e = 0; e < 4; e++) sc[nf][e] = 0.f;
#pragma unroll
        for (int kf = 0; kf < 4; kf++) {
            uint32_t kb4[4][4];
#pragma unroll
            for (int np = 0; np < 4; np++)
                ldm_x4(kb4[np], smem_u32(kcur + (krow + np * 16) * 72 + kf * 16 + kcol));
#pragma unroll
            for (int np = 0; np < 4; np++) {
                mma_f16(sc[2 * np],     qa[kf], &kb4[np][0]);
                mma_f16(sc[2 * np + 1], qa[kf], &kb4[np][2]);
            }
        }

        float tm0 = -1e30f, tm1 = -1e30f;
#pragma unroll
        for (int nf = 0; nf < 8; nf++) {
            tm0 = fmaxf(tm0, fmaxf(sc[nf][0], sc[nf][1]));
            tm1 = fmaxf(tm1, fmaxf(sc[nf][2], sc[nf][3]));
        }
        tm0 = fmaxf(tm0, __shfl_xor_sync(0xffffffffu, tm0, 1));
        tm0 = fmaxf(tm0, __shfl_xor_sync(0xffffffffu, tm0, 2));
        tm1 = fmaxf(tm1, __shfl_xor_sync(0xffffffffu, tm1, 1));
        tm1 = fmaxf(tm1, __shfl_xor_sync(0xffffffffu, tm1, 2));
        float nm0 = fmaxf(m0, tm0), nm1 = fmaxf(m1, tm1);
        float corr0 = fexp(m0 - nm0), corr1 = fexp(m1 - nm1);
        m0 = nm0; m1 = nm1;

        uint32_t ph[4][4];
        float ps0 = 0.f, ps1 = 0.f;
#pragma unroll
        for (int u = 0; u < 4; u++) {
            float p00 = fexp(sc[2*u][0] - nm0),   p01 = fexp(sc[2*u][1] - nm0);
            float p02 = fexp(sc[2*u][2] - nm1),   p03 = fexp(sc[2*u][3] - nm1);
            float p10 = fexp(sc[2*u+1][0] - nm0), p11 = fexp(sc[2*u+1][1] - nm0);
            float p12 = fexp(sc[2*u+1][2] - nm1), p13 = fexp(sc[2*u+1][3] - nm1);
            __half2 h0 = __floats2half2_rn(p00, p01);
            __half2 h1 = __floats2half2_rn(p02, p03);
            __half2 h2 = __floats2half2_rn(p10, p11);
            __half2 h3 = __floats2half2_rn(p12, p13);
            ph[u][0] = *(uint32_t*)&h0; ph[u][1] = *(uint32_t*)&h1;
            ph[u][2] = *(uint32_t*)&h2; ph[u][3] = *(uint32_t*)&h3;
            float2 f0 = __half22float2(h0), f1 = __half22float2(h1);
            float2 f2 = __half22float2(h2), f3 = __half22float2(h3);
            ps0 += f0.x + f0.y + f2.x + f2.y;
            ps1 += f1.x + f1.y + f3.x + f3.y;
        }
        ps0 += __shfl_xor_sync(0xffffffffu, ps0, 1);
        ps0 += __shfl_xor_sync(0xffffffffu, ps0, 2);
        ps1 += __shfl_xor_sync(0xffffffffu, ps1, 1);
        ps1 += __shfl_xor_sync(0xffffffffu, ps1, 2);
        l0 = l0 * corr0 + ps0;
        l1 = l1 * corr1 + ps1;
#pragma unroll
        for (int nf = 0; nf < 8; nf++) {
            o[nf][0] *= corr0; o[nf][1] *= corr0;
            o[nf][2] *= corr1; o[nf][3] *= corr1;
        }

#pragma unroll
        for (int u = 0; u < 4; u++) {
#pragma unroll
            for (int np = 0; np < 4; np++) {
                uint32_t vb[4];
                ldm_x4_t(vb, smem_u32(vcur + (u * 16 + vrow) * 72 + np * 16 + vcol));
                mma_f16(o[2 * np],     ph[u], &vb[0]);
                mma_f16(o[2 * np + 1], ph[u], &vb[2]);
            }
        }
        __syncthreads();
    }

    long prow = (((long)sp * BB + b) * HEADS + h) * NQ + qb * 128 + wid * 16 + gid;
    float* poB = po + prow * 64;
#pragma unroll
    for (int nf = 0; nf < 8; nf++) {
        int col = nf * 8 + 2 * tig;
        *(float2*)(poB + col)          = make_float2(o[nf][0], o[nf][1]);
        *(float2*)(poB + 8 * 64 + col) = make_float2(o[nf][2], o[nf][3]);
    }
    if (tig == 0) {
        *(float2*)(pml + prow * 2)       = make_float2(m0, l0);
        *(float2*)(pml + (prow + 8) * 2) = make_float2(m1, l1);
    }
}

// ---------------- combine split partials -> ctx fp16 ----------------
__global__ void __launch_bounds__(256) attn_comb(
    const float* __restrict__ po, const float* __restrict__ pml,
    __half* __restrict__ ctx)
{
    const long S = (long)BB * HEADS * NQ;
    long idx = (long)blockIdx.x * 256 + threadIdx.x;
    int cp   = (int)(idx & 31);
    long rbh = idx >> 5;
    float2 ml0 = *(const float2*)(pml + rbh * 2);
    float2 ml1 = *(const float2*)(pml + (S + rbh) * 2);
    float2 ml2 = *(const float2*)(pml + (2 * S + rbh) * 2);
    float M  = fmaxf(ml0.x, fmaxf(ml1.x, ml2.x));
    float w0 = fexp(ml0.x - M), w1 = fexp(ml1.x - M), w2 = fexp(ml2.x - M);
    float inv = 1.f / (ml0.y * w0 + ml1.y * w1 + ml2.y * w2);
    float2 a0 = *(const float2*)(po + rbh * 64 + cp * 2);
    float2 a1 = *(const float2*)(po + (S + rbh) * 64 + cp * 2);
    float2 a2 = *(const float2*)(po + (2 * S + rbh) * 64 + cp * 2);
    float ox = (a0.x * w0 + a1.x * w1 + a2.x * w2) * inv;
    float oy = (a0.y * w0 + a1.y * w1 + a2.y * w2) * inv;
    int row = (int)(rbh % NQ);
    long bh = rbh / NQ;
    int h = (int)(bh % HEADS), b = (int)(bh / HEADS);
    *(uint32_t*)(ctx + ((long)b * NQ + row) * HDIM + h * 64 + cp * 2) = h2u(ox, oy);
}

// ---------------- launcher ----------------
extern "C" void kernel_launch(void* const* d_in, const int* in_sizes, int n_in,
                              void* d_out, int out_size)
{
    const float* hid = (const float*)d_in[0];
    const float* x   = (const float*)d_in[1];
    const float* Wq  = (const float*)d_in[2];
    const float* bq  = (const float*)d_in[3];
    const float* Wk  = (const float*)d_in[4];
    const float* bk  = (const float*)d_in[5];
    const float* Wv  = (const float*)d_in[6];
    const float* bv  = (const float*)d_in[7];
    const float* Wo  = (const float*)d_in[8];
    const float* bo  = (const float*)d_in[9];
    const float* W1  = (const float*)d_in[10];
    const float* b1  = (const float*)d_in[11];
    const float* W2  = (const float*)d_in[12];
    const float* b2  = (const float*)d_in[13];
    const float* gi  = (const float*)d_in[14];
    const float* bi  = (const float*)d_in[15];
    const float* gh  = (const float*)d_in[16];
    const float* bh  = (const float*)d_in[17];
    const float* gf  = (const float*)d_in[18];
    const float* bf  = (const float*)d_in[19];

    __half *xn, *hn, *q, *kv, *ctx, *hnf, *ff;
    __half *wq, *wkv, *wo, *w1, *w2;
    float *o1, *bkv, *po, *pml;
    cudaGetSymbolAddress((void**)&xn,  g_xn);
    cudaGetSymbolAddress((void**)&hn,  g_hn);
    cudaGetSymbolAddress((void**)&q,   g_q);
    cudaGetSymbolAddress((void**)&kv,  g_kv);
    cudaGetSymbolAddress((void**)&ctx, g_ctx);
    cudaGetSymbolAddress((void**)&o1,  g_o1);
    cudaGetSymbolAddress((void**)&hnf, g_hnf);
    cudaGetSymbolAddress((void**)&ff,  g_ff);
    cudaGetSymbolAddress((void**)&wq,  g_wq);
    cudaGetSymbolAddress((void**)&wkv, g_wkv);
    cudaGetSymbolAddress((void**)&wo,  g_wo);
    cudaGetSymbolAddress((void**)&w1,  g_w1);
    cudaGetSymbolAddress((void**)&w2,  g_w2);
    cudaGetSymbolAddress((void**)&bkv, g_bkv);
    cudaGetSymbolAddress((void**)&po,  g_po);
    cudaGetSymbolAddress((void**)&pml, g_pml);

    cudaFuncSetAttribute(attn_h, cudaFuncAttributeMaxDynamicSharedMemorySize, ASMEM);
    cudaFuncSetAttribute(gemm_h, cudaFuncAttributeMaxDynamicSharedMemorySize, GSM);
    cudaFuncSetAttribute(gemm64, cudaFuncAttributeMaxDynamicSharedMemorySize, W6SM);

    // 0: all weight prep fused
    wprep_all<<<WPBT, 256>>>(Wq, Wk, Wv, Wo, W1, W2, bk, bv,
                             wq, wkv, wo, w1, w2, bkv);
    // 1: xn LN
    ln_kernel<<<BB * NKV / 8, 256>>>(x, gi, bi, xn, IMGD);
    // 2: hn LN
    ln_kernel<<<BB * NQ / 8, 256>>>(hid, gh, bh, hn, HDIM);
    // 3: KV projection
    gemm_h<<<dim3(KVS / 128, BB * NKV / 128), 256, GSM>>>(xn, wkv, bkv, nullptr,
                                                          kv, BB * NKV, KVS, IMGD, 3);
    // 4: Q projection
    gemm64<<<dim3(HDIM / 128, BB * NQ / 64), 128, W6SM>>>(hn, wq, bq, nullptr, q,
                                                          BB * NQ, HDIM, HDIM, 4);
    // 5: attention (profiled slot)
    attn_h<<<dim3(2 * NSPL, HEADS, BB), 256, ASMEM>>>(q, kv, po, pml);
    attn_comb<<<(int)(((long)BB * HEADS * NQ * 32) / 256), 256>>>(po, pml, ctx);

    gemm64<<<dim3(HDIM / 128, BB * NQ / 64), 128, W6SM>>>(ctx, wo, bo, hid, o1,
                                                          BB * NQ, HDIM, HDIM, 1);

    ln_kernel<<<BB * NQ / 8, 256>>>(o1, gf, bf, hnf, HDIM);
    gemm_h<<<dim3(INTER / 128, BB * NQ / 128), 256, GSM>>>(hnf, w1, b1, nullptr, ff,
                                                           BB * NQ, INTER, HDIM, 2);
    gemm64<<<dim3(HDIM / 128,  BB * NQ / 64), 128, W6SM>>>(ff, w2, b2, o1, d_out,
                                                           BB * NQ, HDIM, INTER, 1);
}

// round 17
// speedup vs baseline: 3.3613x; 1.0376x over previous
#include <cuda_runtime.h>
#include <cuda_fp16.h>
#include <cstdint>
#include <math.h>

#define BB    16
#define NQ    256
#define NKV   2304
#define HDIM  768
#define IMGD  1024
#define HEADS 12
#define INTER 3072
#define KVS   1536
#define NSPL  3
#define ATTN_SCALE 0.125f

// ---------------- scratch (static __device__, allocation-free) ----------------
__device__ __half g_xn [BB*NKV*IMGD];
__device__ __half g_hn [BB*NQ*HDIM];
__device__ __half g_q  [BB*NQ*HDIM];
__device__ __half g_kv [BB*NKV*KVS];
__device__ __half g_ctx[BB*NQ*HDIM];
__device__ float  g_o1 [BB*NQ*HDIM];
__device__ __half g_hnf[BB*NQ*HDIM];
__device__ __half g_ff [BB*NQ*INTER];
__device__ float  g_po [(long)NSPL*BB*HEADS*NQ*64];
__device__ float  g_pml[(long)NSPL*BB*HEADS*NQ*2];
__device__ __half g_wq [HDIM*HDIM];
__device__ __half g_wkv[KVS*IMGD];
__device__ __half g_wo [HDIM*HDIM];
__device__ __half g_w1 [INTER*HDIM];
__device__ __half g_w2 [HDIM*INTER];
__device__ float  g_bkv[KVS];

// ---------------- helpers ----------------
__device__ __forceinline__ uint32_t smem_u32(const void* p) {
    uint32_t a;
    asm("{ .reg .u64 t; cvta.to.shared.u64 t, %1; cvt.u32.u64 %0, t; }" : "=r"(a) : "l"(p));
    return a;
}
__device__ __forceinline__ void cpa16(uint32_t dst, const void* src) {
    asm volatile("cp.async.cg.shared.global [%0], [%1], 16;\n" :: "r"(dst), "l"(src));
}
__device__ __forceinline__ void mma_f16(float* c, const uint32_t* a, const uint32_t* b) {
    asm volatile(
        "mma.sync.aligned.m16n8k16.row.col.f32.f16.f16.f32 "
        "{%0,%1,%2,%3}, {%4,%5,%6,%7}, {%8,%9}, {%0,%1,%2,%3};\n"
        : "+f"(c[0]), "+f"(c[1]), "+f"(c[2]), "+f"(c[3])
        : "r"(a[0]), "r"(a[1]), "r"(a[2]), "r"(a[3]), "r"(b[0]), "r"(b[1]));
}
__device__ __forceinline__ void ldm_x4(uint32_t* r, uint32_t addr) {
    asm volatile("ldmatrix.sync.aligned.m8n8.x4.shared.b16 {%0,%1,%2,%3}, [%4];"
        : "=r"(r[0]), "=r"(r[1]), "=r"(r[2]), "=r"(r[3]) : "r"(addr));
}
__device__ __forceinline__ void ldm_x4_t(uint32_t* r, uint32_t addr) {
    asm volatile("ldmatrix.sync.aligned.m8n8.x4.trans.shared.b16 {%0,%1,%2,%3}, [%4];"
        : "=r"(r[0]), "=r"(r[1]), "=r"(r[2]), "=r"(r[3]) : "r"(addr));
}
__device__ __forceinline__ float fexp(float x) {
    float y = fmaxf(x * 1.44269504f, -120.f);
    float r = y + 12582912.f;
    float n = r - 12582912.f;
    float f = y - n;
    float p = 0.00133336f;
    p = fmaf(p, f, 0.00961804f);
    p = fmaf(p, f, 0.05550411f);
    p = fmaf(p, f, 0.24022651f);
    p = fmaf(p, f, 0.69314718f);
    p = fmaf(p, f, 1.0f);
    int ni = __float_as_int(r) - 0x4B400000;
    return p * __int_as_float((ni + 127) << 23);
}
__device__ __forceinline__ uint32_t h2u(float lo, float hi) {
    __half2 h = __floats2half2_rn(lo, hi);
    return *(uint32_t*)&h;
}

__device__ __forceinline__ void epi_store(float v0, float v1, int epi,
                                          const float* res, void* Cout,
                                          long r, long N, int col) {
    if (epi == 1) {
        float2 rv = *(const float2*)(res + r * N + col);
        *(float2*)((float*)Cout + r * N + col) = make_float2(v0 + rv.x, v1 + rv.y);
    } else {
        if (epi == 2) {
            v0 = 0.5f * v0 * (1.f + erff(v0 * 0.70710678118654752f));
            v1 = 0.5f * v1 * (1.f + erff(v1 * 0.70710678118654752f));
        } else if (epi == 4) {
            v0 *= ATTN_SCALE; v1 *= ATTN_SCALE;
        }
        *(uint32_t*)((__half*)Cout + r * N + col) = h2u(v0, v1);
    }
}

// ---------------- fused weight prep ----------------
#define WPB0 576
#define WPB1 (WPB0+768)
#define WPB2 (WPB1+768)
#define WPB3 (WPB2+576)
#define WPB4 (WPB3+2304)
#define WPB5 (WPB4+2304)
#define WPBT (WPB5+6)

__global__ void __launch_bounds__(256) wprep_all(
    const float* __restrict__ Wq, const float* __restrict__ Wk,
    const float* __restrict__ Wv, const float* __restrict__ Wo,
    const float* __restrict__ W1, const float* __restrict__ W2,
    const float* __restrict__ bk, const float* __restrict__ bv,
    __half* __restrict__ wq, __half* __restrict__ wkv,
    __half* __restrict__ wo, __half* __restrict__ w1,
    __half* __restrict__ w2, float* __restrict__ bkv)
{
    int bx = blockIdx.x;
    if (bx >= WPB5) {
        int i = (bx - WPB5) * 256 + threadIdx.x;
        if (i < HDIM)          bkv[i] = bk[i];
        else if (i < 2 * HDIM) bkv[i] = bv[i - HDIM];
        return;
    }
    const float* W; __half* WT; int K, N, lb;
    if (bx < WPB0)      { W = Wq; WT = wq;  K = HDIM;  N = HDIM;  lb = bx; }
    else if (bx < WPB1) { W = Wk; WT = wkv; K = IMGD;  N = HDIM;  lb = bx - WPB0; }
    else if (bx < WPB2) { W = Wv; WT = wkv + (long)HDIM * IMGD;
                          K = IMGD;  N = HDIM;  lb = bx - WPB1; }
    else if (bx < WPB3) { W = Wo; WT = wo;  K = HDIM;  N = HDIM;  lb = bx - WPB2; }
    else if (bx < WPB4) { W = W1; WT = w1;  K = HDIM;  N = INTER; lb = bx - WPB3; }
    else                { W = W2; WT = w2;  K = INTER; N = HDIM;  lb = bx - WPB4; }
    int nbn = N / 32;
    int nb = (lb % nbn) * 32, kb = (lb / nbn) * 32;

    __shared__ float t[32][33];
    int tx = threadIdx.x & 31, ty = threadIdx.x >> 5;
#pragma unroll
    for (int i = 0; i < 32; i += 8)
        t[ty + i][tx] = W[(long)(kb + ty + i) * N + nb + tx];
    __syncthreads();
#pragma unroll
    for (int i = 0; i < 32; i += 8)
        WT[(long)(nb + ty + i) * K + kb + tx] = __float2half(t[tx][ty + i]);
}

// ---------------- LayerNorm: warp-per-row, two-pass streaming ----------------
__global__ void __launch_bounds__(256) ln_kernel(
    const float* __restrict__ in, const float* __restrict__ gam,
    const float* __restrict__ bet, __half* __restrict__ out, int D)
{
    int lane = threadIdx.x & 31, wid = threadIdx.x >> 5;
    long row = (long)blockIdx.x * 8 + wid;
    const float* xr = in + row * (long)D;
    int nv = D >> 7;
    float s = 0.f, s2 = 0.f;
#pragma unroll 8
    for (int i = 0; i < nv; i++) {
        float4 v = __ldg((const float4*)(xr + (i * 32 + lane) * 4));
        s  += v.x + v.y + v.z + v.w;
        s2 += v.x*v.x + v.y*v.y + v.z*v.z + v.w*v.w;
    }
#pragma unroll
    for (int m = 16; m; m >>= 1) {
        s  += __shfl_xor_sync(0xffffffffu, s,  m);
        s2 += __shfl_xor_sync(0xffffffffu, s2, m);
    }
    float mu   = s / (float)D;
    float var  = fmaxf(s2 / (float)D - mu * mu, 0.f);
    float rstd = rsqrtf(var + 1e-5f);
    __half* orow = out + row * (long)D;
#pragma unroll 8
    for (int i = 0; i < nv; i++) {
        int c = (i * 32 + lane) * 4;
        float4 v = __ldg((const float4*)(xr + c));
        float4 g = __ldg((const float4*)(gam + c));
        float4 b = __ldg((const float4*)(bet + c));
        *(uint32_t*)(orow + c)     = h2u((v.x - mu) * rstd * g.x + b.x,
                                         (v.y - mu) * rstd * g.y + b.y);
        *(uint32_t*)(orow + c + 2) = h2u((v.z - mu) * rstd * g.z + b.z,
                                         (v.w - mu) * rstd * g.w + b.w);
    }
}

// ---------------- fp16 GEMM 128x128, 4 warps, 64x64 warp tiles ----------------
// smem-traffic-optimal: A frags read 2x, B frags read 2x (was 4x/2x).
#define GROW  72
#define GA_H  (128*GROW)
#define GST_H (2*GA_H)
#define GSM   (3*GST_H*2)

__global__ void __launch_bounds__(128, 2) gemm_w(
    const __half* __restrict__ A, const __half* __restrict__ Bw,
    const float* __restrict__ bias, const float* __restrict__ res,
    void* __restrict__ Cout, int M, int N, int K, int epi)
{
    extern __shared__ __half smh[];
    uint32_t usm = smem_u32(smh);
    int tid = threadIdx.x, lane = tid & 31, wid = tid >> 5;
    int gid = lane >> 2, tig = lane & 3;
    int wm = wid & 1, wn = wid >> 1;               // 2x2, tiles 64x64
    int m0 = blockIdx.y * 128, n0 = blockIdx.x * 128;

    // cp.async: 8 A + 8 B chunks per thread per stage (rows step 16)
    int r0 = tid >> 3, ch = tid & 7;               // r0 0..15
    long     asrc0 = (long)(m0 + r0) * K + ch * 8;
    long     bsrc0 = (long)(n0 + r0) * K + ch * 8;
    uint32_t adst0 = (r0 * GROW + ch * 8) * 2;
    uint32_t bdst0 = (GA_H + r0 * GROW + ch * 8) * 2;
    long kstep16 = 16L * K;

    int l8    = lane & 7;
    int amrow = wm * 64 + ((lane >> 3) & 1) * 8 + l8;
    int akcol = (lane >> 4) * 8;
    int bnrow = wn * 64 + (lane >> 4) * 8 + l8;
    int bkcol = ((lane >> 3) & 1) * 8;
    uint32_t aB[4], bB[4];
#pragma unroll
    for (int mf = 0; mf < 4; mf++)
        aB[mf] = usm + ((amrow + mf * 16) * GROW + akcol) * 2;
#pragma unroll
    for (int np = 0; np < 4; np++)
        bB[np] = usm + ((GA_H + (bnrow + np * 16) * GROW + bkcol)) * 2;

    float acc[4][8][4];
#pragma unroll
    for (int i = 0; i < 4; i++)
#pragma unroll
        for (int j = 0; j < 8; j++)
#pragma unroll
            for (int r = 0; r < 4; r++) acc[i][j][r] = 0.f;

    const int NC = K / 64;

    auto issue = [&](int c, int s) {
        long kb = (long)c * 64;
        uint32_t so = usm + s * (GST_H * 2);
#pragma unroll
        for (int i = 0; i < 8; i++)
            cpa16(so + adst0 + i * (16 * GROW * 2), A  + asrc0 + i * kstep16 + kb);
#pragma unroll
        for (int i = 0; i < 8; i++)
            cpa16(so + bdst0 + i * (16 * GROW * 2), Bw + bsrc0 + i * kstep16 + kb);
        asm volatile("cp.async.commit_group;\n" ::: "memory");
    };

    issue(0, 0);
    if (NC > 1) issue(1, 1);

    for (int c = 0; c < NC; c++) {
        int s = c % 3;
        if (c + 1 < NC) asm volatile("cp.async.wait_group 1;\n" ::: "memory");
        else            asm volatile("cp.async.wait_group 0;\n" ::: "memory");
        __syncthreads();
        if (c + 2 < NC) issue(c + 2, (c + 2) % 3);

        uint32_t so = s * (GST_H * 2);
#pragma unroll
        for (int ks = 0; ks < 4; ks++) {
            uint32_t a[4][4], b[4][4];
#pragma unroll
            for (int mf = 0; mf < 4; mf++) ldm_x4(a[mf], aB[mf] + so + ks * 32);
#pragma unroll
            for (int np = 0; np < 4; np++) ldm_x4(b[np], bB[np] + so + ks * 32);
#pragma unroll
            for (int mf = 0; mf < 4; mf++)
#pragma unroll
                for (int np = 0; np < 4; np++) {
                    mma_f16(acc[mf][2 * np],     a[mf], &b[np][0]);
                    mma_f16(acc[mf][2 * np + 1], a[mf], &b[np][2]);
                }
        }
    }

    int cbase = n0 + wn * 64 + 2 * tig;
    float2 bl[8];
#pragma unroll
    for (int nf = 0; nf < 8; nf++)
        bl[nf] = *(const float2*)(bias + cbase + nf * 8);

#pragma unroll
    for (int mf = 0; mf < 4; mf++)
#pragma unroll
        for (int hh = 0; hh < 2; hh++) {
            long r = m0 + wm * 64 + mf * 16 + gid + hh * 8;
#pragma unroll
            for (int nf = 0; nf < 8; nf++)
                epi_store(acc[mf][nf][hh * 2] + bl[nf].x,
                          acc[mf][nf][hh * 2 + 1] + bl[nf].y,
                          epi, res, Cout, r, N, cbase + nf * 8);
        }
}

// ---------------- fp16 mma.sync GEMM 64x128 (occ 4) ----------------
#define W6ROW  72
#define W6A_H  (64*W6ROW)
#define W6ST_H (W6A_H + 128*W6ROW)
#define W6SM   (2*W6ST_H*2)

__global__ void __launch_bounds__(128, 4) gemm64(
    const __half* __restrict__ A, const __half* __restrict__ Bw,
    const float* __restrict__ bias, const float* __restrict__ res,
    void* __restrict__ Cout, int M, int N, int K, int epi)
{
    extern __shared__ __half smh[];
    uint32_t usm = smem_u32(smh);
    int tid = threadIdx.x, lane = tid & 31, wn = tid >> 5;
    int gid = lane >> 2, tig = lane & 3;
    int m0 = blockIdx.y * 64, n0 = blockIdx.x * 128;

    int r0 = tid >> 3, ch = tid & 7;
    long     asrc0 = (long)(m0 + r0) * K + ch * 8;
    long     bsrc0 = (long)(n0 + r0) * K + ch * 8;
    uint32_t adst0 = (r0 * W6ROW + ch * 8) * 2;
    uint32_t bdst0 = (W6A_H + r0 * W6ROW + ch * 8) * 2;
    long kstep16 = (long)16 * K;

    int l8    = lane & 7;
    int amrow = ((lane >> 3) & 1) * 8 + l8;
    int akcol = (lane >> 4) * 8;
    int bnrow = wn * 32 + (lane >> 4) * 8 + l8;
    int bkcol = ((lane >> 3) & 1) * 8;
    uint32_t aB[4], bB[2];
#pragma unroll
    for (int mf = 0; mf < 4; mf++)
        aB[mf] = usm + ((amrow + mf * 16) * W6ROW + akcol) * 2;
#pragma unroll
    for (int np = 0; np < 2; np++)
        bB[np] = usm + ((W6A_H + (bnrow + np * 16) * W6ROW + bkcol)) * 2;

    float acc[4][4][4];
#pragma unroll
    for (int i = 0; i < 4; i++)
#pragma unroll
        for (int j = 0; j < 4; j++)
#pragma unroll
            for (int r = 0; r < 4; r++) acc[i][j][r] = 0.f;

    const int NC = K / 64;

    auto issue = [&](int c, int s) {
        long kb = (long)c * 64;
        uint32_t so = usm + s * W6ST_H * 2;
#pragma unroll
        for (int i = 0; i < 4; i++)
            cpa16(so + adst0 + i * (16 * W6ROW * 2), A + asrc0 + i * kstep16 + kb);
#pragma unroll
        for (int i = 0; i < 8; i++)
            cpa16(so + bdst0 + i * (16 * W6ROW * 2), Bw + bsrc0 + i * kstep16 + kb);
        asm volatile("cp.async.commit_group;\n" ::: "memory");
    };

    issue(0, 0);

    for (int c = 0; c < NC; c++) {
        if (c + 1 < NC) {
            issue(c + 1, (c + 1) & 1);
            asm volatile("cp.async.wait_group 1;\n" ::: "memory");
        } else {
            asm volatile("cp.async.wait_group 0;\n" ::: "memory");
        }
        __syncthreads();

        uint32_t so = (c & 1) * (W6ST_H * 2);
#pragma unroll
        for (int ks = 0; ks < 4; ks++) {
            uint32_t a[4][4], b[2][4];
#pragma unroll
            for (int mf = 0; mf < 4; mf++) ldm_x4(a[mf], aB[mf] + so + ks * 32);
#pragma unroll
            for (int np = 0; np < 2; np++) ldm_x4(b[np], bB[np] + so + ks * 32);
#pragma unroll
            for (int mf = 0; mf < 4; mf++)
#pragma unroll
                for (int nf = 0; nf < 4; nf++)
                    mma_f16(acc[mf][nf], a[mf], &b[nf >> 1][(nf & 1) * 2]);
        }
        __syncthreads();
    }

    int cbase = n0 + wn * 32 + 2 * tig;
    float2 bl[4];
#pragma unroll
    for (int nf = 0; nf < 4; nf++)
        bl[nf] = *(const float2*)(bias + cbase + nf * 8);

#pragma unroll
    for (int mf = 0; mf < 4; mf++)
#pragma unroll
        for (int hh = 0; hh < 2; hh++) {
            long r = m0 + mf * 16 + gid + hh * 8;
#pragma unroll
            for (int nf = 0; nf < 4; nf++)
                epi_store(acc[mf][nf][hh * 2] + bl[nf].x,
                          acc[mf][nf][hh * 2 + 1] + bl[nf].y,
                          epi, res, Cout, r, N, cbase + nf * 8);
        }
}

// ---------------- fp16 flash attention, split-KV x3 ----------------
#define AQH   (128*72)
#define AKH   (64*72)
#define ASMEM ((AQH + 4*AKH) * 2)
#define ANCT  (NKV / 64)
#define ANCS  (ANCT / NSPL)

__global__ void __launch_bounds__(256, 2) attn_h(
    const __half* __restrict__ Q, const __half* __restrict__ KV,
    float* __restrict__ po, float* __restrict__ pml)
{
    extern __shared__ __half smh[];
    __half* qs = smh;
    __half* ks = smh + AQH;
    __half* vs = ks + 2 * AKH;
    int tid = threadIdx.x, lane = tid & 31, wid = tid >> 5;
    int gid = lane >> 2, tig = lane & 3;
    int qb = blockIdx.x & 1, sp = blockIdx.x >> 1;
    int h = blockIdx.y, b = blockIdx.z;
    int c0 = sp * ANCS;

    const __half* Qb = Q  + ((long)b * NQ + qb * 128) * HDIM + h * 64;
    const __half* Kb = KV + (long)b * NKV * KVS + h * 64;
    const __half* Vb = Kb + HDIM;

    int l8    = lane & 7;
    int qrow  = wid * 16 + ((lane >> 3) & 1) * 8 + l8;
    int qcol  = (lane >> 4) * 8;
    int krow  = (lane >> 4) * 8 + l8;
    int kcol  = ((lane >> 3) & 1) * 8;
    int vrow  = ((lane >> 3) & 1) * 8 + l8;
    int vcol  = (lane >> 4) * 8;

    auto load_kv = [&](int ct, int buf) {
        __half* kd = ks + buf * AKH;
        __half* vd = vs + buf * AKH;
        long j0 = (long)ct * 64;
#pragma unroll
        for (int i = 0; i < 2; i++) {
            int idx = tid + i * 256;
            int r = idx >> 3, c8 = (idx & 7) * 8;
            cpa16(smem_u32(kd + r * 72 + c8), Kb + (j0 + r) * KVS + c8);
            cpa16(smem_u32(vd + r * 72 + c8), Vb + (j0 + r) * KVS + c8);
        }
        asm volatile("cp.async.commit_group;\n" ::: "memory");
    };

#pragma unroll
    for (int i = 0; i < 4; i++) {
        int idx = tid + i * 256;
        int r = idx >> 3, c8 = (idx & 7) * 8;
        cpa16(smem_u32(qs + r * 72 + c8), Qb + (long)r * HDIM + c8);
    }
    load_kv(c0, 0);

    float o[8][4];
#pragma unroll
    for (int nf = 0; nf < 8; nf++)
#pragma unroll
        for (int e = 0; e < 4; e++) o[nf][e] = 0.f;
    float m0 = -1e30f, m1 = -1e30f, l0 = 0.f, l1 = 0.f;

    uint32_t qa[4][4];

    for (int c = 0; c < ANCS; c++) {
        if (c + 1 < ANCS) {
            load_kv(c0 + c + 1, (c + 1) & 1);
            asm volatile("cp.async.wait_group 1;\n" ::: "memory");
        } else {
            asm volatile("cp.async.wait_group 0;\n" ::: "memory");
        }
        __syncthreads();

        if (c == 0) {
#pragma unroll
            for (int kf = 0; kf < 4; kf++)
                ldm_x4(qa[kf], smem_u32(qs + qrow * 72 + kf * 16 + qcol));
        }

        const __half* kcur = ks + (c & 1) * AKH;
        const __half* vcur = vs + (c & 1) * AKH;

        float sc[8][4];
#pragma unroll
        for (int nf = 0; nf < 8; nf++)
#pragma unroll
            for (int e = 0; e < 4; e++) sc[nf][e] = 0.f;
#pragma unroll
        for (int kf = 0; kf < 4; kf++) {
            uint32_t kb4[4][4];
#pragma unroll
            for (int np = 0; np < 4; np++)
                ldm_x4(kb4[np], smem_u32(kcur + (krow + np * 16) * 72 + kf * 16 + kcol));
#pragma unroll
            for (int np = 0; np < 4; np++) {
                mma_f16(sc[2 * np],     qa[kf], &kb4[np][0]);
                mma_f16(sc[2 * np + 1], qa[kf], &kb4[np][2]);
            }
        }

        float tm0 = -1e30f, tm1 = -1e30f;
#pragma unroll
        for (int nf = 0; nf < 8; nf++) {
            tm0 = fmaxf(tm0, fmaxf(sc[nf][0], sc[nf][1]));
            tm1 = fmaxf(tm1, fmaxf(sc[nf][2], sc[nf][3]));
        }
        tm0 = fmaxf(tm0, __shfl_xor_sync(0xffffffffu, tm0, 1));
        tm0 = fmaxf(tm0, __shfl_xor_sync(0xffffffffu, tm0, 2));
        tm1 = fmaxf(tm1, __shfl_xor_sync(0xffffffffu, tm1, 1));
        tm1 = fmaxf(tm1, __shfl_xor_sync(0xffffffffu, tm1, 2));
        float nm0 = fmaxf(m0, tm0), nm1 = fmaxf(m1, tm1);
        float corr0 = fexp(m0 - nm0), corr1 = fexp(m1 - nm1);
        m0 = nm0; m1 = nm1;

        uint32_t ph[4][4];
        float ps0 = 0.f, ps1 = 0.f;
#pragma unroll
        for (int u = 0; u < 4; u++) {
            float p00 = fexp(sc[2*u][0] - nm0),   p01 = fexp(sc[2*u][1] - nm0);
            float p02 = fexp(sc[2*u][2] - nm1),   p03 = fexp(sc[2*u][3] - nm1);
            float p10 = fexp(sc[2*u+1][0] - nm0), p11 = fexp(sc[2*u+1][1] - nm0);
            float p12 = fexp(sc[2*u+1][2] - nm1), p13 = fexp(sc[2*u+1][3] - nm1);
            __half2 h0 = __floats2half2_rn(p00, p01);
            __half2 h1 = __floats2half2_rn(p02, p03);
            __half2 h2 = __floats2half2_rn(p10, p11);
            __half2 h3 = __floats2half2_rn(p12, p13);
            ph[u][0] = *(uint32_t*)&h0; ph[u][1] = *(uint32_t*)&h1;
            ph[u][2] = *(uint32_t*)&h2; ph[u][3] = *(uint32_t*)&h3;
            float2 f0 = __half22float2(h0), f1 = __half22float2(h1);
            float2 f2 = __half22float2(h2), f3 = __half22float2(h3);
            ps0 += f0.x + f0.y + f2.x + f2.y;
            ps1 += f1.x + f1.y + f3.x + f3.y;
        }
        ps0 += __shfl_xor_sync(0xffffffffu, ps0, 1);
        ps0 += __shfl_xor_sync(0xffffffffu, ps0, 2);
        ps1 += __shfl_xor_sync(0xffffffffu, ps1, 1);
        ps1 += __shfl_xor_sync(0xffffffffu, ps1, 2);
        l0 = l0 * corr0 + ps0;
        l1 = l1 * corr1 + ps1;
#pragma unroll
        for (int nf = 0; nf < 8; nf++) {
            o[nf][0] *= corr0; o[nf][1] *= corr0;
            o[nf][2] *= corr1; o[nf][3] *= corr1;
        }

#pragma unroll
        for (int u = 0; u < 4; u++) {
#pragma unroll
            for (int np = 0; np < 4; np++) {
                uint32_t vb[4];
                ldm_x4_t(vb, smem_u32(vcur + (u * 16 + vrow) * 72 + np * 16 + vcol));
                mma_f16(o[2 * np],     ph[u], &vb[0]);
                mma_f16(o[2 * np + 1], ph[u], &vb[2]);
            }
        }
        __syncthreads();
    }

    long prow = (((long)sp * BB + b) * HEADS + h) * NQ + qb * 128 + wid * 16 + gid;
    float* poB = po + prow * 64;
#pragma unroll
    for (int nf = 0; nf < 8; nf++) {
        int col = nf * 8 + 2 * tig;
        *(float2*)(poB + col)          = make_float2(o[nf][0], o[nf][1]);
        *(float2*)(poB + 8 * 64 + col) = make_float2(o[nf][2], o[nf][3]);
    }
    if (tig == 0) {
        *(float2*)(pml + prow * 2)       = make_float2(m0, l0);
        *(float2*)(pml + (prow + 8) * 2) = make_float2(m1, l1);
    }
}

// ---------------- combine split partials -> ctx fp16 ----------------
__global__ void __launch_bounds__(256) attn_comb(
    const float* __restrict__ po, const float* __restrict__ pml,
    __half* __restrict__ ctx)
{
    const long S = (long)BB * HEADS * NQ;
    long idx = (long)blockIdx.x * 256 + threadIdx.x;
    int cp   = (int)(idx & 31);
    long rbh = idx >> 5;
    float2 ml0 = *(const float2*)(pml + rbh * 2);
    float2 ml1 = *(const float2*)(pml + (S + rbh) * 2);
    float2 ml2 = *(const float2*)(pml + (2 * S + rbh) * 2);
    float M  = fmaxf(ml0.x, fmaxf(ml1.x, ml2.x));
    float w0 = fexp(ml0.x - M), w1 = fexp(ml1.x - M), w2 = fexp(ml2.x - M);
    float inv = 1.f / (ml0.y * w0 + ml1.y * w1 + ml2.y * w2);
    float2 a0 = *(const float2*)(po + rbh * 64 + cp * 2);
    float2 a1 = *(const float2*)(po + (S + rbh) * 64 + cp * 2);
    float2 a2 = *(const float2*)(po + (2 * S + rbh) * 64 + cp * 2);
    float ox = (a0.x * w0 + a1.x * w1 + a2.x * w2) * inv;
    float oy = (a0.y * w0 + a1.y * w1 + a2.y * w2) * inv;
    int row = (int)(rbh % NQ);
    long bh = rbh / NQ;
    int h = (int)(bh % HEADS), b = (int)(bh / HEADS);
    *(uint32_t*)(ctx + ((long)b * NQ + row) * HDIM + h * 64 + cp * 2) = h2u(ox, oy);
}

// ---------------- launcher ----------------
extern "C" void kernel_launch(void* const* d_in, const int* in_sizes, int n_in,
                              void* d_out, int out_size)
{
    const float* hid = (const float*)d_in[0];
    const float* x   = (const float*)d_in[1];
    const float* Wq  = (const float*)d_in[2];
    const float* bq  = (const float*)d_in[3];
    const float* Wk  = (const float*)d_in[4];
    const float* bk  = (const float*)d_in[5];
    const float* Wv  = (const float*)d_in[6];
    const float* bv  = (const float*)d_in[7];
    const float* Wo  = (const float*)d_in[8];
    const float* bo  = (const float*)d_in[9];
    const float* W1  = (const float*)d_in[10];
    const float* b1  = (const float*)d_in[11];
    const float* W2  = (const float*)d_in[12];
    const float* b2  = (const float*)d_in[13];
    const float* gi  = (const float*)d_in[14];
    const float* bi  = (const float*)d_in[15];
    const float* gh  = (const float*)d_in[16];
    const float* bh  = (const float*)d_in[17];
    const float* gf  = (const float*)d_in[18];
    const float* bf  = (const float*)d_in[19];

    __half *xn, *hn, *q, *kv, *ctx, *hnf, *ff;
    __half *wq, *wkv, *wo, *w1, *w2;
    float *o1, *bkv, *po, *pml;
    cudaGetSymbolAddress((void**)&xn,  g_xn);
    cudaGetSymbolAddress((void**)&hn,  g_hn);
    cudaGetSymbolAddress((void**)&q,   g_q);
    cudaGetSymbolAddress((void**)&kv,  g_kv);
    cudaGetSymbolAddress((void**)&ctx, g_ctx);
    cudaGetSymbolAddress((void**)&o1,  g_o1);
    cudaGetSymbolAddress((void**)&hnf, g_hnf);
    cudaGetSymbolAddress((void**)&ff,  g_ff);
    cudaGetSymbolAddress((void**)&wq,  g_wq);
    cudaGetSymbolAddress((void**)&wkv, g_wkv);
    cudaGetSymbolAddress((void**)&wo,  g_wo);
    cudaGetSymbolAddress((void**)&w1,  g_w1);
    cudaGetSymbolAddress((void**)&w2,  g_w2);
    cudaGetSymbolAddress((void**)&bkv, g_bkv);
    cudaGetSymbolAddress((void**)&po,  g_po);
    cudaGetSymbolAddress((void**)&pml, g_pml);

    cudaFuncSetAttribute(attn_h, cudaFuncAttributeMaxDynamicSharedMemorySize, ASMEM);
    cudaFuncSetAttribute(gemm_w, cudaFuncAttributeMaxDynamicSharedMemorySize, GSM);
    cudaFuncSetAttribute(gemm64, cudaFuncAttributeMaxDynamicSharedMemorySize, W6SM);

    wprep_all<<<WPBT, 256>>>(Wq, Wk, Wv, Wo, W1, W2, bk, bv,
                             wq, wkv, wo, w1, w2, bkv);
    ln_kernel<<<BB * NKV / 8, 256>>>(x, gi, bi, xn, IMGD);
    ln_kernel<<<BB * NQ / 8, 256>>>(hid, gh, bh, hn, HDIM);
    // KV projection (wide-warp GEMM)
    gemm_w<<<dim3(KVS / 128, BB * NKV / 128), 128, GSM>>>(xn, wkv, bkv, nullptr,
                                                          kv, BB * NKV, KVS, IMGD, 3);
    gemm64<<<dim3(HDIM / 128, BB * NQ / 64), 128, W6SM>>>(hn, wq, bq, nullptr, q,
                                                          BB * NQ, HDIM, HDIM, 4);
    attn_h<<<dim3(2 * NSPL, HEADS, BB), 256, ASMEM>>>(q, kv, po, pml);
    attn_comb<<<(int)(((long)BB * HEADS * NQ * 32) / 256), 256>>>(po, pml, ctx);

    gemm64<<<dim3(HDIM / 128, BB * NQ / 64), 128, W6SM>>>(ctx, wo, bo, hid, o1,
                                                          BB * NQ, HDIM, HDIM, 1);

    ln_kernel<<<BB * NQ / 8, 256>>>(o1, gf, bf, hnf, HDIM);
    gemm_w<<<dim3(INTER / 128, BB * NQ / 128), 128, GSM>>>(hnf, w1, b1, nullptr, ff,
                                                           BB * NQ, INTER, HDIM, 2);
    gemm64<<<dim3(HDIM / 128,  BB * NQ / 64), 128, W6SM>>>(ff, w2, b2, o1, d_out,
                                                           BB * NQ, HDIM, INTER, 1);
}